// round 2
// baseline (speedup 1.0000x reference)
#include <cuda_runtime.h>
#include <cuda_bf16.h>
#include <cstdint>

#define NN 20000
#define EE 640000
#define DD 128
#define RR 16
#define LL 3

// ---------------- device scratch ----------------
__device__ float g_h   [(size_t)NN * DD];
__device__ float g_hup [(size_t)NN * DD];
__device__ float g_agg [(size_t)NN * DD];
__device__ float g_rbf [(size_t)EE * RR];
__device__ float g_base[DD];

__device__ __forceinline__ float silu_f(float x) {
    return x / (1.0f + __expf(-x));
}

// ---------------- time embedding + time MLP + nodein te-bias precompute ----------------
__global__ void k_time(const int* __restrict__ tptr,
                       const float* __restrict__ tw1, const float* __restrict__ tb1,
                       const float* __restrict__ tw2, const float* __restrict__ tb2,
                       const float* __restrict__ nw1, const float* __restrict__ nb1) {
    __shared__ float sE[DD], sH[DD], sTe[DD];
    const int j = threadIdx.x;  // 128 threads
    // robust scalar t read (int32 / int64-low-word / float32)
    int iv = *tptr;
    float t = (iv >= 0 && iv < 1000000) ? (float)iv : __int_as_float(iv);
    {
        int i = (j < 64) ? j : (j - 64);
        float f = __expf(-logf(10000.0f) * (float)i / 63.0f);
        float a = t * f;
        sE[j] = (j < 64) ? sinf(a) : cosf(a);
    }
    __syncthreads();
    float acc = tb1[j];
    for (int k = 0; k < DD; ++k) acc += sE[k] * tw1[k * DD + j];
    sH[j] = silu_f(acc);
    __syncthreads();
    float acc2 = tb2[j];
    for (int k = 0; k < DD; ++k) acc2 += sH[k] * tw2[k * DD + j];
    sTe[j] = acc2;
    __syncthreads();
    // base[j] = nodein_b1[j] + sum_k te[k] * nodein_w1[3+k][j]
    float accb = nb1[j];
    for (int k = 0; k < DD; ++k) accb += sTe[k] * nw1[(3 + k) * DD + j];
    g_base[j] = accb;
}

// ---------------- RBF per edge ----------------
__global__ void k_rbf(const float* __restrict__ xt, const int* __restrict__ ei) {
    const int e = blockIdx.x * 256 + threadIdx.x;
    if (e >= EE) return;
    const int s = ei[e], d = ei[EE + e];
    const float dx = xt[s * 3 + 0] - xt[d * 3 + 0];
    const float dy = xt[s * 3 + 1] - xt[d * 3 + 1];
    const float r = sqrtf(dx * dx + dy * dy + 1e-8f);
    const float step = 1.41421356237309515f / 15.0f;
    const float gamma = 1.0f / (2.0f * step * step);
#pragma unroll
    for (int c = 0; c < RR; ++c) {
        float u = r - (float)c * step;
        g_rbf[(size_t)e * RR + c] = __expf(-gamma * u * u);
    }
}

// ---------------- node input MLP (te part folded into g_base) ----------------
__global__ void k_nodein(const float* __restrict__ xt,
                         const float* __restrict__ w1,   // [131][128]
                         const float* __restrict__ w2,   // [128][128]
                         const float* __restrict__ b2) {
    extern __shared__ float sm[];
    float* sW2  = sm;                 // 128*128
    float* sW1x = sW2 + DD * DD;      // 3*128
    float* sB   = sW1x + 3 * DD;      // 128 (base)
    float* sHid = sB + DD;            // 128
    const int j = threadIdx.x;        // 128 threads
    for (int i = j; i < DD * DD; i += DD) sW2[i] = w2[i];
    sW1x[j]          = w1[0 * DD + j];
    sW1x[DD + j]     = w1[1 * DD + j];
    sW1x[2 * DD + j] = w1[2 * DD + j];
    sB[j] = g_base[j];
    const float bb = b2[j];
    __syncthreads();
    const int n0 = blockIdx.x * 64;
    for (int m = 0; m < 64; ++m) {
        const int n = n0 + m;
        if (n >= NN) break;
        const float x0 = xt[n * 3 + 0], x1 = xt[n * 3 + 1], x2 = xt[n * 3 + 2];
        sHid[j] = silu_f(sB[j] + x0 * sW1x[j] + x1 * sW1x[DD + j] + x2 * sW1x[2 * DD + j]);
        __syncthreads();
        float o = bb;
#pragma unroll 8
        for (int k = 0; k < DD; ++k) o += sHid[k] * sW2[k * DD + j];
        g_h[(size_t)n * DD + j] = o;
        __syncthreads();
    }
}

// ---------------- zero agg ----------------
__global__ void k_zero() {
    const int i = blockIdx.x * 256 + threadIdx.x;
    if (i < NN * DD) g_agg[i] = 0.0f;
}

// ---------------- fused edge message MLP + scatter-add (dominant kernel) ----------------
// persistent blocks, tile = 64 edges x 128 cols, 256 threads, 4x8 register tiles
__global__ __launch_bounds__(256, 1)
void k_edge(const int* __restrict__ ei,
            const float* __restrict__ w1, const float* __restrict__ b1,
            const float* __restrict__ w2, const float* __restrict__ b2,
            int numTiles) {
    extern __shared__ float sm[];
    float* sW1  = sm;                         // 272*128
    float* sHid = sW1 + 272 * DD;             // 64*128
    float* sA   = sHid + 64 * DD;             // 64*16
    float* sB   = sA + 64 * 16;               // 16*128
    int*   sSrc = (int*)(sB + 16 * DD);       // 64
    int*   sDst = sSrc + 64;                  // 64

    const int tid = threadIdx.x;
    const int tx = tid & 15, ty = tid >> 4;
    const int c0 = tx * 8;
    const int r0 = ty * 4;

    for (int i = tid; i < 272 * DD; i += 256) sW1[i] = w1[i];

    for (int tile = blockIdx.x; tile < numTiles; tile += gridDim.x) {
        const int e0 = tile * 64;
        __syncthreads();
        if (tid < 64) {
            sSrc[tid] = ei[e0 + tid];
            sDst[tid] = ei[EE + e0 + tid];
        }
        float acc[4][8];
#pragma unroll
        for (int i = 0; i < 4; ++i)
#pragma unroll
            for (int j = 0; j < 8; ++j) acc[i][j] = 0.0f;
        __syncthreads();

        // GEMM1: [64 x 272] @ [272 x 128]
        for (int kc = 0; kc < 17; ++kc) {
            const int kbase = kc * 16;
#pragma unroll
            for (int u = 0; u < 4; ++u) {
                const int idx = tid + u * 256;
                const int r = idx >> 4, kk = idx & 15;
                float v;
                if (kbase < 128)      v = g_h[(size_t)sSrc[r] * DD + kbase + kk];
                else if (kbase < 256) v = g_h[(size_t)sDst[r] * DD + (kbase - 128) + kk];
                else                  v = g_rbf[(size_t)(e0 + r) * RR + kk];
                sA[idx] = v;
            }
            __syncthreads();
#pragma unroll
            for (int kk = 0; kk < 16; ++kk) {
                float b[8];
                const float4 b01 = *(const float4*)&sW1[(kbase + kk) * DD + c0];
                const float4 b23 = *(const float4*)&sW1[(kbase + kk) * DD + c0 + 4];
                b[0] = b01.x; b[1] = b01.y; b[2] = b01.z; b[3] = b01.w;
                b[4] = b23.x; b[5] = b23.y; b[6] = b23.z; b[7] = b23.w;
#pragma unroll
                for (int i = 0; i < 4; ++i) {
                    const float a = sA[(r0 + i) * 16 + kk];
#pragma unroll
                    for (int j = 0; j < 8; ++j) acc[i][j] = fmaf(a, b[j], acc[i][j]);
                }
            }
            __syncthreads();
        }
        // epilogue 1: bias + SiLU -> sHid
#pragma unroll
        for (int i = 0; i < 4; ++i)
#pragma unroll
            for (int j = 0; j < 8; ++j) {
                sHid[(r0 + i) * DD + c0 + j] = silu_f(acc[i][j] + b1[c0 + j]);
                acc[i][j] = 0.0f;
            }
        __syncthreads();

        // GEMM2: [64 x 128] @ [128 x 128]
        for (int kc = 0; kc < 8; ++kc) {
            const int kbase = kc * 16;
#pragma unroll
            for (int u = 0; u < 8; ++u) {
                const int idx = tid + u * 256;           // 2048 = 16*128
                sB[idx] = w2[kbase * DD + idx];
            }
            __syncthreads();
#pragma unroll
            for (int kk = 0; kk < 16; ++kk) {
                float b[8];
                const float4 b01 = *(const float4*)&sB[kk * DD + c0];
                const float4 b23 = *(const float4*)&sB[kk * DD + c0 + 4];
                b[0] = b01.x; b[1] = b01.y; b[2] = b01.z; b[3] = b01.w;
                b[4] = b23.x; b[5] = b23.y; b[6] = b23.z; b[7] = b23.w;
#pragma unroll
                for (int i = 0; i < 4; ++i) {
                    const float a = sHid[(r0 + i) * DD + kbase + kk];
#pragma unroll
                    for (int j = 0; j < 8; ++j) acc[i][j] = fmaf(a, b[j], acc[i][j]);
                }
            }
            __syncthreads();
        }
        // epilogue 2: bias + scatter-add
#pragma unroll
        for (int i = 0; i < 4; ++i) {
            const int d = sDst[r0 + i];
#pragma unroll
            for (int j = 0; j < 8; ++j)
                atomicAdd(&g_agg[(size_t)d * DD + c0 + j], acc[i][j] + b2[c0 + j]);
        }
    }
}

// ---------------- node update MLP (concat(h, agg)) + residual -> g_hup ----------------
__global__ __launch_bounds__(256, 1)
void k_node(const float* __restrict__ w1, const float* __restrict__ b1,
            const float* __restrict__ w2, const float* __restrict__ b2,
            int numTiles) {
    extern __shared__ float sm[];
    float* sW1  = sm;                    // 256*128
    float* sHid = sW1 + 256 * DD;        // 64*128
    float* sA   = sHid + 64 * DD;        // 64*16
    float* sB   = sA + 64 * 16;          // 16*128

    const int tid = threadIdx.x;
    const int tx = tid & 15, ty = tid >> 4;
    const int c0 = tx * 8;
    const int r0 = ty * 4;

    for (int i = tid; i < 256 * DD; i += 256) sW1[i] = w1[i];

    for (int tile = blockIdx.x; tile < numTiles; tile += gridDim.x) {
        const int n0 = tile * 64;
        float acc[4][8];
#pragma unroll
        for (int i = 0; i < 4; ++i)
#pragma unroll
            for (int j = 0; j < 8; ++j) acc[i][j] = 0.0f;
        __syncthreads();

        // GEMM1: K = 256 (h | agg)
        for (int kc = 0; kc < 16; ++kc) {
            const int kbase = kc * 16;
#pragma unroll
            for (int u = 0; u < 4; ++u) {
                const int idx = tid + u * 256;
                const int r = idx >> 4, kk = idx & 15;
                int n = n0 + r; if (n >= NN) n = 0;
                float v;
                if (kbase < 128) v = g_h[(size_t)n * DD + kbase + kk];
                else             v = g_agg[(size_t)n * DD + (kbase - 128) + kk];
                sA[idx] = v;
            }
            __syncthreads();
#pragma unroll
            for (int kk = 0; kk < 16; ++kk) {
                float b[8];
                const float4 b01 = *(const float4*)&sW1[(kbase + kk) * DD + c0];
                const float4 b23 = *(const float4*)&sW1[(kbase + kk) * DD + c0 + 4];
                b[0] = b01.x; b[1] = b01.y; b[2] = b01.z; b[3] = b01.w;
                b[4] = b23.x; b[5] = b23.y; b[6] = b23.z; b[7] = b23.w;
#pragma unroll
                for (int i = 0; i < 4; ++i) {
                    const float a = sA[(r0 + i) * 16 + kk];
#pragma unroll
                    for (int j = 0; j < 8; ++j) acc[i][j] = fmaf(a, b[j], acc[i][j]);
                }
            }
            __syncthreads();
        }
#pragma unroll
        for (int i = 0; i < 4; ++i)
#pragma unroll
            for (int j = 0; j < 8; ++j) {
                sHid[(r0 + i) * DD + c0 + j] = silu_f(acc[i][j] + b1[c0 + j]);
                acc[i][j] = 0.0f;
            }
        __syncthreads();

        // GEMM2: K = 128
        for (int kc = 0; kc < 8; ++kc) {
            const int kbase = kc * 16;
#pragma unroll
            for (int u = 0; u < 8; ++u) {
                const int idx = tid + u * 256;
                sB[idx] = w2[kbase * DD + idx];
            }
            __syncthreads();
#pragma unroll
            for (int kk = 0; kk < 16; ++kk) {
                float b[8];
                const float4 b01 = *(const float4*)&sB[kk * DD + c0];
                const float4 b23 = *(const float4*)&sB[kk * DD + c0 + 4];
                b[0] = b01.x; b[1] = b01.y; b[2] = b01.z; b[3] = b01.w;
                b[4] = b23.x; b[5] = b23.y; b[6] = b23.z; b[7] = b23.w;
#pragma unroll
                for (int i = 0; i < 4; ++i) {
                    const float a = sHid[(r0 + i) * DD + kbase + kk];
#pragma unroll
                    for (int j = 0; j < 8; ++j) acc[i][j] = fmaf(a, b[j], acc[i][j]);
                }
            }
            __syncthreads();
        }
        // epilogue: bias + residual -> g_hup
#pragma unroll
        for (int i = 0; i < 4; ++i) {
            const int n = n0 + r0 + i;
            if (n < NN) {
#pragma unroll
                for (int j = 0; j < 8; ++j)
                    g_hup[(size_t)n * DD + c0 + j] =
                        acc[i][j] + b2[c0 + j] + g_h[(size_t)n * DD + c0 + j];
            }
        }
    }
}

// ---------------- LayerNorm: g_h = LN(g_hup) ----------------
__global__ void k_ln(const float* __restrict__ g, const float* __restrict__ b) {
    const int gl = blockIdx.x * blockDim.x + threadIdx.x;
    const int node = gl >> 5;
    const int lane = gl & 31;
    if (node >= NN) return;
    const float4 v = ((const float4*)(g_hup + (size_t)node * DD))[lane];
    float s = v.x + v.y + v.z + v.w;
#pragma unroll
    for (int o = 16; o; o >>= 1) s += __shfl_xor_sync(0xFFFFFFFFu, s, o);
    const float mu = s * (1.0f / 128.0f);
    const float d0 = v.x - mu, d1 = v.y - mu, d2 = v.z - mu, d3 = v.w - mu;
    float q = d0 * d0 + d1 * d1 + d2 * d2 + d3 * d3;
#pragma unroll
    for (int o = 16; o; o >>= 1) q += __shfl_xor_sync(0xFFFFFFFFu, q, o);
    const float inv = rsqrtf(q * (1.0f / 128.0f) + 1e-5f);
    const float4 gg = ((const float4*)g)[lane];
    const float4 bb = ((const float4*)b)[lane];
    float4 o4;
    o4.x = d0 * inv * gg.x + bb.x;
    o4.y = d1 * inv * gg.y + bb.y;
    o4.z = d2 * inv * gg.z + bb.z;
    o4.w = d3 * inv * gg.w + bb.w;
    ((float4*)(g_h + (size_t)node * DD))[lane] = o4;
}

// ---------------- output MLP ----------------
__global__ void k_out(const float* __restrict__ w1, const float* __restrict__ b1,
                      const float* __restrict__ w2, const float* __restrict__ b2,
                      float* __restrict__ out) {
    extern __shared__ float sm[];
    float* sW1  = sm;                 // 128*128
    float* sW2  = sW1 + DD * DD;      // 128*3
    float* sX   = sW2 + DD * 3;       // 128
    float* sHid = sX + DD;            // 128
    const int j = threadIdx.x;        // 128 threads
    for (int i = j; i < DD * DD; i += DD) sW1[i] = w1[i];
    for (int i = j; i < DD * 3; i += DD) sW2[i] = w2[i];
    const float bb1 = b1[j];
    __syncthreads();
    const int n0 = blockIdx.x * 16;
    for (int m = 0; m < 16; ++m) {
        const int n = n0 + m;
        sX[j] = g_h[(size_t)n * DD + j];
        __syncthreads();
        float acc = bb1;
#pragma unroll 8
        for (int k = 0; k < DD; ++k) acc += sX[k] * sW1[k * DD + j];
        sHid[j] = silu_f(acc);
        __syncthreads();
        if (j < 3) {
            float o = b2[j];
            for (int k = 0; k < DD; ++k) o += sHid[k] * sW2[k * 3 + j];
            out[(size_t)n * 3 + j] = o;
        }
        __syncthreads();
    }
}

// ---------------- launch ----------------
extern "C" void kernel_launch(void* const* d_in, const int* in_sizes, int n_in,
                              void* d_out, int out_size) {
    const float* x_t      = (const float*)d_in[0];
    const int*   ei       = (const int*)d_in[1];
    const int*   tp       = (const int*)d_in[2];
    const float* time_w1  = (const float*)d_in[3];
    const float* time_b1  = (const float*)d_in[4];
    const float* time_w2  = (const float*)d_in[5];
    const float* time_b2  = (const float*)d_in[6];
    const float* nodein_w1= (const float*)d_in[7];
    const float* nodein_b1= (const float*)d_in[8];
    const float* nodein_w2= (const float*)d_in[9];
    const float* nodein_b2= (const float*)d_in[10];
    const float* phim_w1  = (const float*)d_in[11];
    const float* phim_b1  = (const float*)d_in[12];
    const float* phim_w2  = (const float*)d_in[13];
    const float* phim_b2  = (const float*)d_in[14];
    const float* phih_w1  = (const float*)d_in[15];
    const float* phih_b1  = (const float*)d_in[16];
    const float* phih_w2  = (const float*)d_in[17];
    const float* phih_b2  = (const float*)d_in[18];
    const float* ln_g     = (const float*)d_in[19];
    const float* ln_b     = (const float*)d_in[20];
    const float* out_w1   = (const float*)d_in[21];
    const float* out_b1   = (const float*)d_in[22];
    const float* out_w2   = (const float*)d_in[23];
    const float* out_b2   = (const float*)d_in[24];
    float* out = (float*)d_out;

    const int SMEM_EDGE   = (272 * 128 + 64 * 128 + 64 * 16 + 16 * 128) * 4 + 128 * 4;
    const int SMEM_NODE   = (256 * 128 + 64 * 128 + 64 * 16 + 16 * 128) * 4;
    const int SMEM_NODEIN = (128 * 128 + 3 * 128 + 128 + 128) * 4;
    const int SMEM_OUT    = (128 * 128 + 128 * 3 + 128 + 128) * 4;

    cudaFuncSetAttribute(k_edge,   cudaFuncAttributeMaxDynamicSharedMemorySize, SMEM_EDGE);
    cudaFuncSetAttribute(k_node,   cudaFuncAttributeMaxDynamicSharedMemorySize, SMEM_NODE);
    cudaFuncSetAttribute(k_nodein, cudaFuncAttributeMaxDynamicSharedMemorySize, SMEM_NODEIN);
    cudaFuncSetAttribute(k_out,    cudaFuncAttributeMaxDynamicSharedMemorySize, SMEM_OUT);

    k_time<<<1, 128>>>(tp, time_w1, time_b1, time_w2, time_b2, nodein_w1, nodein_b1);
    k_rbf<<<(EE + 255) / 256, 256>>>(x_t, ei);
    k_nodein<<<(NN + 63) / 64, 128, SMEM_NODEIN>>>(x_t, nodein_w1, nodein_w2, nodein_b2);

    const int edgeTiles = EE / 64;           // 10000
    const int nodeTiles = (NN + 63) / 64;    // 313

    for (int l = 0; l < LL; ++l) {
        k_zero<<<(NN * DD + 255) / 256, 256>>>();
        k_edge<<<148, 256, SMEM_EDGE>>>(ei,
                                        phim_w1 + (size_t)l * 272 * DD,
                                        phim_b1 + (size_t)l * DD,
                                        phim_w2 + (size_t)l * DD * DD,
                                        phim_b2 + (size_t)l * DD,
                                        edgeTiles);
        k_node<<<148, 256, SMEM_NODE>>>(phih_w1 + (size_t)l * 256 * DD,
                                        phih_b1 + (size_t)l * DD,
                                        phih_w2 + (size_t)l * DD * DD,
                                        phih_b2 + (size_t)l * DD,
                                        nodeTiles);
        k_ln<<<(NN * 32 + 255) / 256, 256>>>(ln_g + (size_t)l * DD, ln_b + (size_t)l * DD);
    }

    k_out<<<NN / 16, 128, SMEM_OUT>>>(out_w1, out_b1, out_w2, out_b2, out);
}

// round 3
// speedup vs baseline: 1.1335x; 1.1335x over previous
#include <cuda_runtime.h>
#include <cuda_bf16.h>
#include <cstdint>

#define NN 20000
#define EE 640000
#define DD 128
#define RR 16
#define LL 3

// ---------------- device scratch ----------------
__device__ float g_h   [(size_t)NN * DD];
__device__ float g_hup [(size_t)NN * DD];
__device__ float g_agg [(size_t)NN * DD];
__device__ float g_rbf [(size_t)EE * RR];
__device__ float g_base[DD];

__device__ __forceinline__ float silu_f(float x) {
    return x / (1.0f + __expf(-x));
}

// sm_103a packed fp32 FMA helpers
__device__ __forceinline__ unsigned long long pk2(float lo, float hi) {
    unsigned long long r;
    asm("mov.b64 %0, {%1, %2};" : "=l"(r) : "f"(lo), "f"(hi));
    return r;
}
__device__ __forceinline__ void up2(unsigned long long v, float& lo, float& hi) {
    asm("mov.b64 {%0, %1}, %2;" : "=f"(lo), "=f"(hi) : "l"(v));
}
__device__ __forceinline__ void ffma2(unsigned long long& d, unsigned long long a, unsigned long long b) {
    asm("fma.rn.f32x2 %0, %1, %2, %0;" : "+l"(d) : "l"(a), "l"(b));
}

// ---------------- time embedding + time MLP + nodein te-bias precompute ----------------
__global__ void k_time(const int* __restrict__ tptr,
                       const float* __restrict__ tw1, const float* __restrict__ tb1,
                       const float* __restrict__ tw2, const float* __restrict__ tb2,
                       const float* __restrict__ nw1, const float* __restrict__ nb1) {
    __shared__ float sE[DD], sH[DD], sTe[DD];
    const int j = threadIdx.x;  // 128 threads
    int iv = *tptr;
    float t = (iv >= 0 && iv < 1000000) ? (float)iv : __int_as_float(iv);
    {
        int i = (j < 64) ? j : (j - 64);
        float f = __expf(-logf(10000.0f) * (float)i / 63.0f);
        float a = t * f;
        sE[j] = (j < 64) ? sinf(a) : cosf(a);
    }
    __syncthreads();
    float acc = tb1[j];
    for (int k = 0; k < DD; ++k) acc += sE[k] * tw1[k * DD + j];
    sH[j] = silu_f(acc);
    __syncthreads();
    float acc2 = tb2[j];
    for (int k = 0; k < DD; ++k) acc2 += sH[k] * tw2[k * DD + j];
    sTe[j] = acc2;
    __syncthreads();
    float accb = nb1[j];
    for (int k = 0; k < DD; ++k) accb += sTe[k] * nw1[(3 + k) * DD + j];
    g_base[j] = accb;
}

// ---------------- RBF per edge ----------------
__global__ void k_rbf(const float* __restrict__ xt, const int* __restrict__ ei) {
    const int e = blockIdx.x * 256 + threadIdx.x;
    if (e >= EE) return;
    const int s = ei[e], d = ei[EE + e];
    const float dx = xt[s * 3 + 0] - xt[d * 3 + 0];
    const float dy = xt[s * 3 + 1] - xt[d * 3 + 1];
    const float r = sqrtf(dx * dx + dy * dy + 1e-8f);
    const float step = 1.41421356237309515f / 15.0f;
    const float gamma = 1.0f / (2.0f * step * step);
#pragma unroll
    for (int c = 0; c < RR; ++c) {
        float u = r - (float)c * step;
        g_rbf[(size_t)e * RR + c] = __expf(-gamma * u * u);
    }
}

// ---------------- node input MLP (te part folded into g_base) ----------------
__global__ void k_nodein(const float* __restrict__ xt,
                         const float* __restrict__ w1,
                         const float* __restrict__ w2,
                         const float* __restrict__ b2) {
    extern __shared__ float sm[];
    float* sW2  = sm;
    float* sW1x = sW2 + DD * DD;
    float* sB   = sW1x + 3 * DD;
    float* sHid = sB + DD;
    const int j = threadIdx.x;  // 128
    for (int i = j; i < DD * DD; i += DD) sW2[i] = w2[i];
    sW1x[j]          = w1[0 * DD + j];
    sW1x[DD + j]     = w1[1 * DD + j];
    sW1x[2 * DD + j] = w1[2 * DD + j];
    sB[j] = g_base[j];
    const float bb = b2[j];
    __syncthreads();
    const int n0 = blockIdx.x * 64;
    for (int m = 0; m < 64; ++m) {
        const int n = n0 + m;
        if (n >= NN) break;
        const float x0 = xt[n * 3 + 0], x1 = xt[n * 3 + 1], x2 = xt[n * 3 + 2];
        sHid[j] = silu_f(sB[j] + x0 * sW1x[j] + x1 * sW1x[DD + j] + x2 * sW1x[2 * DD + j]);
        __syncthreads();
        float o = bb;
#pragma unroll 8
        for (int k = 0; k < DD; ++k) o += sHid[k] * sW2[k * DD + j];
        g_h[(size_t)n * DD + j] = o;
        __syncthreads();
    }
}

// ---------------- zero agg ----------------
__global__ void k_zero() {
    const int i = blockIdx.x * 256 + threadIdx.x;
    if (i < NN * DD) g_agg[i] = 0.0f;
}

// ================= fused edge message MLP + scatter-add =================
// tile = 128 edges x 128 cols, 512 threads, 4x8 thread tile (f32x2 packed),
// double-buffered gather staging, persistent blocks.
#define HSTR 132
__global__ __launch_bounds__(512, 1)
void k_edge(const int* __restrict__ ei,
            const float* __restrict__ w1, const float* __restrict__ b1,
            const float* __restrict__ w2, const float* __restrict__ b2,
            int numTiles) {
    extern __shared__ float sm[];
    float* sW1  = sm;                           // 272*128
    float* sHid = sW1 + 272 * DD;               // 128*HSTR
    float* sA0  = sHid + 128 * HSTR;            // 128*16
    float* sA1  = sA0 + 128 * 16;               // 128*16
    int*   sSrc = (int*)(sA1 + 128 * 16);       // 128
    int*   sDst = sSrc + 128;                   // 128

    const int tid = threadIdx.x;
    const int c0 = (tid & 15) * 8;
    const int r0 = (tid >> 4) * 4;
    const int gr = tid >> 2;                    // gather row 0..127
    const int gq = (tid & 3) * 4;               // gather sub-k 0/4/8/12

    for (int i = tid; i < 272 * DD; i += 512) sW1[i] = w1[i];
    float bias1[8], bias2[8];
#pragma unroll
    for (int j = 0; j < 8; ++j) { bias1[j] = b1[c0 + j]; bias2[j] = b2[c0 + j]; }

    float* bufs[2] = { sA0, sA1 };

    for (int tile = blockIdx.x; tile < numTiles; tile += gridDim.x) {
        const int e0 = tile * 128;
        __syncthreads();  // protect sSrc/sDst + staging buffers from prev tile readers
        if (tid < 128) { sSrc[tid] = ei[e0 + tid]; sDst[tid] = ei[EE + e0 + tid]; }
        unsigned long long acc[4][4];
#pragma unroll
        for (int i = 0; i < 4; ++i)
#pragma unroll
            for (int p = 0; p < 4; ++p) acc[i][p] = 0ull;
        __syncthreads();

        // prologue: stage chunk 0 (h[src] k=0..15)
        {
            float4 v = *(const float4*)&g_h[(size_t)sSrc[gr] * DD + gq];
            *(float4*)&bufs[0][gr * 16 + gq] = v;
        }
        __syncthreads();

        // ---- GEMM1: [128 x 272] @ [272 x 128] ----
        for (int kc = 0; kc < 17; ++kc) {
            float4 nv;
            if (kc < 16) {
                const int k = (kc + 1) * 16 + gq;
                if (k < 128)      nv = *(const float4*)&g_h[(size_t)sSrc[gr] * DD + k];
                else if (k < 256) nv = *(const float4*)&g_h[(size_t)sDst[gr] * DD + (k - 128)];
                else              nv = *(const float4*)&g_rbf[(size_t)(e0 + gr) * RR + gq];
            }
            const float* A = bufs[kc & 1];
            const int kbase = kc * 16;
#pragma unroll
            for (int kk = 0; kk < 16; ++kk) {
                const float* wrow = &sW1[(kbase + kk) * DD + c0];
                const ulonglong2 B0 = *(const ulonglong2*)wrow;
                const ulonglong2 B1 = *(const ulonglong2*)(wrow + 4);
#pragma unroll
                for (int i = 0; i < 4; ++i) {
                    const float a = A[(r0 + i) * 16 + kk];
                    const unsigned long long aa = pk2(a, a);
                    ffma2(acc[i][0], aa, B0.x);
                    ffma2(acc[i][1], aa, B0.y);
                    ffma2(acc[i][2], aa, B1.x);
                    ffma2(acc[i][3], aa, B1.y);
                }
            }
            if (kc < 16) *(float4*)&bufs[(kc + 1) & 1][gr * 16 + gq] = nv;
            __syncthreads();
        }

        // epilogue 1: bias + SiLU -> sHid ; pre-stage W2 chunk 0
        {
            float4 w2v = *(const float4*)&w2[tid * 4];
#pragma unroll
            for (int i = 0; i < 4; ++i) {
                float* hrow = &sHid[(r0 + i) * HSTR + c0];
                float o[8];
#pragma unroll
                for (int p = 0; p < 4; ++p) {
                    float x, y; up2(acc[i][p], x, y);
                    o[2 * p]     = silu_f(x + bias1[2 * p]);
                    o[2 * p + 1] = silu_f(y + bias1[2 * p + 1]);
                    acc[i][p] = 0ull;
                }
                *(float4*)&hrow[0] = make_float4(o[0], o[1], o[2], o[3]);
                *(float4*)&hrow[4] = make_float4(o[4], o[5], o[6], o[7]);
            }
            *(float4*)&bufs[0][tid * 4] = w2v;
        }
        __syncthreads();

        // ---- GEMM2: [128 x 128] @ [128 x 128], W2 streamed double-buffered ----
        for (int kc = 0; kc < 8; ++kc) {
            float4 nv;
            if (kc < 7) nv = *(const float4*)&w2[(size_t)(kc + 1) * 16 * DD + tid * 4];
            const float* Bc = bufs[kc & 1];
            const int kbase = kc * 16;
#pragma unroll
            for (int kk = 0; kk < 16; ++kk) {
                const float* wrow = &Bc[kk * DD + c0];
                const ulonglong2 B0 = *(const ulonglong2*)wrow;
                const ulonglong2 B1 = *(const ulonglong2*)(wrow + 4);
#pragma unroll
                for (int i = 0; i < 4; ++i) {
                    const float a = sHid[(r0 + i) * HSTR + kbase + kk];
                    const unsigned long long aa = pk2(a, a);
                    ffma2(acc[i][0], aa, B0.x);
                    ffma2(acc[i][1], aa, B0.y);
                    ffma2(acc[i][2], aa, B1.x);
                    ffma2(acc[i][3], aa, B1.y);
                }
            }
            if (kc < 7) *(float4*)&bufs[(kc + 1) & 1][tid * 4] = nv;
            __syncthreads();
        }

        // epilogue 2: bias + scatter-add
#pragma unroll
        for (int i = 0; i < 4; ++i) {
            float* dp = &g_agg[(size_t)sDst[r0 + i] * DD + c0];
#pragma unroll
            for (int p = 0; p < 4; ++p) {
                float x, y; up2(acc[i][p], x, y);
                atomicAdd(dp + 2 * p,     x + bias2[2 * p]);
                atomicAdd(dp + 2 * p + 1, y + bias2[2 * p + 1]);
            }
        }
    }
}

// ================= node update MLP (concat(h,agg)) + residual -> g_hup =================
__global__ __launch_bounds__(512, 1)
void k_node(const float* __restrict__ w1, const float* __restrict__ b1,
            const float* __restrict__ w2, const float* __restrict__ b2,
            int numTiles) {
    extern __shared__ float sm[];
    float* sW1  = sm;                           // 256*128
    float* sHid = sW1 + 256 * DD;               // 128*HSTR
    float* sA0  = sHid + 128 * HSTR;            // 128*16
    float* sA1  = sA0 + 128 * 16;               // 128*16

    const int tid = threadIdx.x;
    const int c0 = (tid & 15) * 8;
    const int r0 = (tid >> 4) * 4;
    const int gr = tid >> 2;
    const int gq = (tid & 3) * 4;

    for (int i = tid; i < 256 * DD; i += 512) sW1[i] = w1[i];
    float bias1[8], bias2[8];
#pragma unroll
    for (int j = 0; j < 8; ++j) { bias1[j] = b1[c0 + j]; bias2[j] = b2[c0 + j]; }

    float* bufs[2] = { sA0, sA1 };

    for (int tile = blockIdx.x; tile < numTiles; tile += gridDim.x) {
        const int n0 = tile * 128;
        int gn = n0 + gr; if (gn >= NN) gn = NN - 1;
        unsigned long long acc[4][4];
#pragma unroll
        for (int i = 0; i < 4; ++i)
#pragma unroll
            for (int p = 0; p < 4; ++p) acc[i][p] = 0ull;
        __syncthreads();

        {
            float4 v = *(const float4*)&g_h[(size_t)gn * DD + gq];
            *(float4*)&bufs[0][gr * 16 + gq] = v;
        }
        __syncthreads();

        // ---- GEMM1: K=256 (h | agg) ----
        for (int kc = 0; kc < 16; ++kc) {
            float4 nv;
            if (kc < 15) {
                const int k = (kc + 1) * 16 + gq;
                if (k < 128) nv = *(const float4*)&g_h[(size_t)gn * DD + k];
                else         nv = *(const float4*)&g_agg[(size_t)gn * DD + (k - 128)];
            }
            const float* A = bufs[kc & 1];
            const int kbase = kc * 16;
#pragma unroll
            for (int kk = 0; kk < 16; ++kk) {
                const float* wrow = &sW1[(kbase + kk) * DD + c0];
                const ulonglong2 B0 = *(const ulonglong2*)wrow;
                const ulonglong2 B1 = *(const ulonglong2*)(wrow + 4);
#pragma unroll
                for (int i = 0; i < 4; ++i) {
                    const float a = A[(r0 + i) * 16 + kk];
                    const unsigned long long aa = pk2(a, a);
                    ffma2(acc[i][0], aa, B0.x);
                    ffma2(acc[i][1], aa, B0.y);
                    ffma2(acc[i][2], aa, B1.x);
                    ffma2(acc[i][3], aa, B1.y);
                }
            }
            if (kc < 15) *(float4*)&bufs[(kc + 1) & 1][gr * 16 + gq] = nv;
            __syncthreads();
        }

        // epilogue 1 + pre-stage W2 chunk 0
        {
            float4 w2v = *(const float4*)&w2[tid * 4];
#pragma unroll
            for (int i = 0; i < 4; ++i) {
                float* hrow = &sHid[(r0 + i) * HSTR + c0];
                float o[8];
#pragma unroll
                for (int p = 0; p < 4; ++p) {
                    float x, y; up2(acc[i][p], x, y);
                    o[2 * p]     = silu_f(x + bias1[2 * p]);
                    o[2 * p + 1] = silu_f(y + bias1[2 * p + 1]);
                    acc[i][p] = 0ull;
                }
                *(float4*)&hrow[0] = make_float4(o[0], o[1], o[2], o[3]);
                *(float4*)&hrow[4] = make_float4(o[4], o[5], o[6], o[7]);
            }
            *(float4*)&bufs[0][tid * 4] = w2v;
        }
        __syncthreads();

        // ---- GEMM2: K=128 ----
        for (int kc = 0; kc < 8; ++kc) {
            float4 nv;
            if (kc < 7) nv = *(const float4*)&w2[(size_t)(kc + 1) * 16 * DD + tid * 4];
            const float* Bc = bufs[kc & 1];
            const int kbase = kc * 16;
#pragma unroll
            for (int kk = 0; kk < 16; ++kk) {
                const float* wrow = &Bc[kk * DD + c0];
                const ulonglong2 B0 = *(const ulonglong2*)wrow;
                const ulonglong2 B1 = *(const ulonglong2*)(wrow + 4);
#pragma unroll
                for (int i = 0; i < 4; ++i) {
                    const float a = sHid[(r0 + i) * HSTR + kbase + kk];
                    const unsigned long long aa = pk2(a, a);
                    ffma2(acc[i][0], aa, B0.x);
                    ffma2(acc[i][1], aa, B0.y);
                    ffma2(acc[i][2], aa, B1.x);
                    ffma2(acc[i][3], aa, B1.y);
                }
            }
            if (kc < 7) *(float4*)&bufs[(kc + 1) & 1][tid * 4] = nv;
            __syncthreads();
        }

        // epilogue: bias + residual -> g_hup
#pragma unroll
        for (int i = 0; i < 4; ++i) {
            const int n = n0 + r0 + i;
            if (n < NN) {
                const float4 h0 = *(const float4*)&g_h[(size_t)n * DD + c0];
                const float4 h1 = *(const float4*)&g_h[(size_t)n * DD + c0 + 4];
                float o[8];
#pragma unroll
                for (int p = 0; p < 4; ++p) {
                    float x, y; up2(acc[i][p], x, y);
                    o[2 * p]     = x + bias2[2 * p];
                    o[2 * p + 1] = y + bias2[2 * p + 1];
                }
                *(float4*)&g_hup[(size_t)n * DD + c0] =
                    make_float4(o[0] + h0.x, o[1] + h0.y, o[2] + h0.z, o[3] + h0.w);
                *(float4*)&g_hup[(size_t)n * DD + c0 + 4] =
                    make_float4(o[4] + h1.x, o[5] + h1.y, o[6] + h1.z, o[7] + h1.w);
            }
        }
    }
}

// ---------------- LayerNorm: g_h = LN(g_hup) ----------------
__global__ void k_ln(const float* __restrict__ g, const float* __restrict__ b) {
    const int gl = blockIdx.x * blockDim.x + threadIdx.x;
    const int node = gl >> 5;
    const int lane = gl & 31;
    if (node >= NN) return;
    const float4 v = ((const float4*)(g_hup + (size_t)node * DD))[lane];
    float s = v.x + v.y + v.z + v.w;
#pragma unroll
    for (int o = 16; o; o >>= 1) s += __shfl_xor_sync(0xFFFFFFFFu, s, o);
    const float mu = s * (1.0f / 128.0f);
    const float d0 = v.x - mu, d1 = v.y - mu, d2 = v.z - mu, d3 = v.w - mu;
    float q = d0 * d0 + d1 * d1 + d2 * d2 + d3 * d3;
#pragma unroll
    for (int o = 16; o; o >>= 1) q += __shfl_xor_sync(0xFFFFFFFFu, q, o);
    const float inv = rsqrtf(q * (1.0f / 128.0f) + 1e-5f);
    const float4 gg = ((const float4*)g)[lane];
    const float4 bb = ((const float4*)b)[lane];
    float4 o4;
    o4.x = d0 * inv * gg.x + bb.x;
    o4.y = d1 * inv * gg.y + bb.y;
    o4.z = d2 * inv * gg.z + bb.z;
    o4.w = d3 * inv * gg.w + bb.w;
    ((float4*)(g_h + (size_t)node * DD))[lane] = o4;
}

// ---------------- output MLP ----------------
__global__ void k_out(const float* __restrict__ w1, const float* __restrict__ b1,
                      const float* __restrict__ w2, const float* __restrict__ b2,
                      float* __restrict__ out) {
    extern __shared__ float sm[];
    float* sW1  = sm;
    float* sW2  = sW1 + DD * DD;
    float* sX   = sW2 + DD * 3;
    float* sHid = sX + DD;
    const int j = threadIdx.x;  // 128
    for (int i = j; i < DD * DD; i += DD) sW1[i] = w1[i];
    for (int i = j; i < DD * 3; i += DD) sW2[i] = w2[i];
    const float bb1 = b1[j];
    __syncthreads();
    const int n0 = blockIdx.x * 16;
    for (int m = 0; m < 16; ++m) {
        const int n = n0 + m;
        sX[j] = g_h[(size_t)n * DD + j];
        __syncthreads();
        float acc = bb1;
#pragma unroll 8
        for (int k = 0; k < DD; ++k) acc += sX[k] * sW1[k * DD + j];
        sHid[j] = silu_f(acc);
        __syncthreads();
        if (j < 3) {
            float o = b2[j];
            for (int k = 0; k < DD; ++k) o += sHid[k] * sW2[k * 3 + j];
            out[(size_t)n * 3 + j] = o;
        }
        __syncthreads();
    }
}

// ---------------- launch ----------------
extern "C" void kernel_launch(void* const* d_in, const int* in_sizes, int n_in,
                              void* d_out, int out_size) {
    const float* x_t      = (const float*)d_in[0];
    const int*   ei       = (const int*)d_in[1];
    const int*   tp       = (const int*)d_in[2];
    const float* time_w1  = (const float*)d_in[3];
    const float* time_b1  = (const float*)d_in[4];
    const float* time_w2  = (const float*)d_in[5];
    const float* time_b2  = (const float*)d_in[6];
    const float* nodein_w1= (const float*)d_in[7];
    const float* nodein_b1= (const float*)d_in[8];
    const float* nodein_w2= (const float*)d_in[9];
    const float* nodein_b2= (const float*)d_in[10];
    const float* phim_w1  = (const float*)d_in[11];
    const float* phim_b1  = (const float*)d_in[12];
    const float* phim_w2  = (const float*)d_in[13];
    const float* phim_b2  = (const float*)d_in[14];
    const float* phih_w1  = (const float*)d_in[15];
    const float* phih_b1  = (const float*)d_in[16];
    const float* phih_w2  = (const float*)d_in[17];
    const float* phih_b2  = (const float*)d_in[18];
    const float* ln_g     = (const float*)d_in[19];
    const float* ln_b     = (const float*)d_in[20];
    const float* out_w1   = (const float*)d_in[21];
    const float* out_b1   = (const float*)d_in[22];
    const float* out_w2   = (const float*)d_in[23];
    const float* out_b2   = (const float*)d_in[24];
    float* out = (float*)d_out;

    const int SMEM_EDGE   = (272 * DD + 128 * HSTR + 2 * 128 * 16) * 4 + 256 * 4;
    const int SMEM_NODE   = (256 * DD + 128 * HSTR + 2 * 128 * 16) * 4;
    const int SMEM_NODEIN = (DD * DD + 3 * DD + DD + DD) * 4;
    const int SMEM_OUT    = (DD * DD + DD * 3 + DD + DD) * 4;

    cudaFuncSetAttribute(k_edge,   cudaFuncAttributeMaxDynamicSharedMemorySize, SMEM_EDGE);
    cudaFuncSetAttribute(k_node,   cudaFuncAttributeMaxDynamicSharedMemorySize, SMEM_NODE);
    cudaFuncSetAttribute(k_nodein, cudaFuncAttributeMaxDynamicSharedMemorySize, SMEM_NODEIN);
    cudaFuncSetAttribute(k_out,    cudaFuncAttributeMaxDynamicSharedMemorySize, SMEM_OUT);

    k_time<<<1, 128>>>(tp, time_w1, time_b1, time_w2, time_b2, nodein_w1, nodein_b1);
    k_rbf<<<(EE + 255) / 256, 256>>>(x_t, ei);
    k_nodein<<<(NN + 63) / 64, 128, SMEM_NODEIN>>>(x_t, nodein_w1, nodein_w2, nodein_b2);

    const int edgeTiles = EE / 128;          // 5000
    const int nodeTiles = (NN + 127) / 128;  // 157

    for (int l = 0; l < LL; ++l) {
        k_zero<<<(NN * DD + 255) / 256, 256>>>();
        k_edge<<<148, 512, SMEM_EDGE>>>(ei,
                                        phim_w1 + (size_t)l * 272 * DD,
                                        phim_b1 + (size_t)l * DD,
                                        phim_w2 + (size_t)l * DD * DD,
                                        phim_b2 + (size_t)l * DD,
                                        edgeTiles);
        k_node<<<148, 512, SMEM_NODE>>>(phih_w1 + (size_t)l * 256 * DD,
                                        phih_b1 + (size_t)l * DD,
                                        phih_w2 + (size_t)l * DD * DD,
                                        phih_b2 + (size_t)l * DD,
                                        nodeTiles);
        k_ln<<<(NN * 32 + 255) / 256, 256>>>(ln_g + (size_t)l * DD, ln_b + (size_t)l * DD);
    }

    k_out<<<NN / 16, 128, SMEM_OUT>>>(out_w1, out_b1, out_w2, out_b2, out);
}

// round 5
// speedup vs baseline: 1.1335x; 1.0000x over previous
#include <cuda_runtime.h>
#include <cuda_bf16.h>
#include <cstdint>

#define NN 20000
#define EE 640000
#define DD 128
#define RR 16
#define LL 3

// ---------------- device scratch ----------------
__device__ float g_h   [(size_t)NN * DD];
__device__ float g_hup [(size_t)NN * DD];
__device__ float g_agg [(size_t)NN * DD];
__device__ float g_rbf [(size_t)EE * RR];
__device__ float g_base[DD];

__device__ __forceinline__ float silu_f(float x) {
    return x / (1.0f + __expf(-x));
}

// sm_103a packed fp32 FMA helpers
__device__ __forceinline__ unsigned long long pk2(float lo, float hi) {
    unsigned long long r;
    asm("mov.b64 %0, {%1, %2};" : "=l"(r) : "f"(lo), "f"(hi));
    return r;
}
__device__ __forceinline__ void up2(unsigned long long v, float& lo, float& hi) {
    asm("mov.b64 {%0, %1}, %2;" : "=f"(lo), "=f"(hi) : "l"(v));
}
__device__ __forceinline__ void ffma2(unsigned long long& d, unsigned long long a, unsigned long long b) {
    asm("fma.rn.f32x2 %0, %1, %2, %0;" : "+l"(d) : "l"(a), "l"(b));
}

// ---------------- time embedding + time MLP + nodein te-bias precompute ----------------
__global__ void k_time(const int* __restrict__ tptr,
                       const float* __restrict__ tw1, const float* __restrict__ tb1,
                       const float* __restrict__ tw2, const float* __restrict__ tb2,
                       const float* __restrict__ nw1, const float* __restrict__ nb1) {
    __shared__ float sE[DD], sH[DD], sTe[DD];
    const int j = threadIdx.x;  // 128 threads
    int iv = *tptr;
    float t = (iv >= 0 && iv < 1000000) ? (float)iv : __int_as_float(iv);
    {
        int i = (j < 64) ? j : (j - 64);
        float f = __expf(-logf(10000.0f) * (float)i / 63.0f);
        float a = t * f;
        sE[j] = (j < 64) ? sinf(a) : cosf(a);
    }
    __syncthreads();
    float acc = tb1[j];
    for (int k = 0; k < DD; ++k) acc += sE[k] * tw1[k * DD + j];
    sH[j] = silu_f(acc);
    __syncthreads();
    float acc2 = tb2[j];
    for (int k = 0; k < DD; ++k) acc2 += sH[k] * tw2[k * DD + j];
    sTe[j] = acc2;
    __syncthreads();
    float accb = nb1[j];
    for (int k = 0; k < DD; ++k) accb += sTe[k] * nw1[(3 + k) * DD + j];
    g_base[j] = accb;
}

// ---------------- RBF per edge ----------------
__global__ void k_rbf(const float* __restrict__ xt, const int* __restrict__ ei) {
    const int e = blockIdx.x * 256 + threadIdx.x;
    if (e >= EE) return;
    const int s = ei[e], d = ei[EE + e];
    const float dx = xt[s * 3 + 0] - xt[d * 3 + 0];
    const float dy = xt[s * 3 + 1] - xt[d * 3 + 1];
    const float r = sqrtf(dx * dx + dy * dy + 1e-8f);
    const float step = 1.41421356237309515f / 15.0f;
    const float gamma = 1.0f / (2.0f * step * step);
#pragma unroll
    for (int c = 0; c < RR; ++c) {
        float u = r - (float)c * step;
        g_rbf[(size_t)e * RR + c] = __expf(-gamma * u * u);
    }
}

// ---------------- node input MLP (te part folded into g_base) ----------------
__global__ void k_nodein(const float* __restrict__ xt,
                         const float* __restrict__ w1,
                         const float* __restrict__ w2,
                         const float* __restrict__ b2) {
    extern __shared__ float sm[];
    float* sW2  = sm;
    float* sW1x = sW2 + DD * DD;
    float* sB   = sW1x + 3 * DD;
    float* sHid = sB + DD;
    const int j = threadIdx.x;  // 128
    for (int i = j; i < DD * DD; i += DD) sW2[i] = w2[i];
    sW1x[j]          = w1[0 * DD + j];
    sW1x[DD + j]     = w1[1 * DD + j];
    sW1x[2 * DD + j] = w1[2 * DD + j];
    sB[j] = g_base[j];
    const float bb = b2[j];
    __syncthreads();
    const int n0 = blockIdx.x * 64;
    for (int m = 0; m < 64; ++m) {
        const int n = n0 + m;
        if (n >= NN) break;
        const float x0 = xt[n * 3 + 0], x1 = xt[n * 3 + 1], x2 = xt[n * 3 + 2];
        sHid[j] = silu_f(sB[j] + x0 * sW1x[j] + x1 * sW1x[DD + j] + x2 * sW1x[2 * DD + j]);
        __syncthreads();
        float o = bb;
#pragma unroll 8
        for (int k = 0; k < DD; ++k) o += sHid[k] * sW2[k * DD + j];
        g_h[(size_t)n * DD + j] = o;
        __syncthreads();
    }
}

// ---------------- zero agg ----------------
__global__ void k_zero() {
    const int i = blockIdx.x * 256 + threadIdx.x;
    if (i < NN * DD) g_agg[i] = 0.0f;
}

// ================= fused edge message MLP + scatter-add =================
// tile = 128 edges x 128 cols, 512 threads, 4x8 thread tile (f32x2 packed),
// double-buffered gather staging, persistent blocks.
#define HSTR 132
__global__ __launch_bounds__(512, 1)
void k_edge(const int* __restrict__ ei,
            const float* __restrict__ w1, const float* __restrict__ b1,
            const float* __restrict__ w2, const float* __restrict__ b2,
            int numTiles) {
    extern __shared__ float sm[];
    float* sW1  = sm;                           // 272*128
    float* sHid = sW1 + 272 * DD;               // 128*HSTR
    float* sA0  = sHid + 128 * HSTR;            // 128*16
    float* sA1  = sA0 + 128 * 16;               // 128*16
    int*   sSrc = (int*)(sA1 + 128 * 16);       // 128
    int*   sDst = sSrc + 128;                   // 128

    const int tid = threadIdx.x;
    const int c0 = (tid & 15) * 8;
    const int r0 = (tid >> 4) * 4;
    const int gr = tid >> 2;                    // gather row 0..127
    const int gq = (tid & 3) * 4;               // gather sub-k 0/4/8/12

    for (int i = tid; i < 272 * DD; i += 512) sW1[i] = w1[i];
    float bias1[8], bias2[8];
#pragma unroll
    for (int j = 0; j < 8; ++j) { bias1[j] = b1[c0 + j]; bias2[j] = b2[c0 + j]; }

    float* bufs[2] = { sA0, sA1 };

    for (int tile = blockIdx.x; tile < numTiles; tile += gridDim.x) {
        const int e0 = tile * 128;
        __syncthreads();  // protect sSrc/sDst + staging buffers from prev tile readers
        if (tid < 128) { sSrc[tid] = ei[e0 + tid]; sDst[tid] = ei[EE + e0 + tid]; }
        unsigned long long acc[4][4];
#pragma unroll
        for (int i = 0; i < 4; ++i)
#pragma unroll
            for (int p = 0; p < 4; ++p) acc[i][p] = 0ull;
        __syncthreads();

        // prologue: stage chunk 0 (h[src] k=0..15)
        {
            float4 v = *(const float4*)&g_h[(size_t)sSrc[gr] * DD + gq];
            *(float4*)&bufs[0][gr * 16 + gq] = v;
        }
        __syncthreads();

        // ---- GEMM1: [128 x 272] @ [272 x 128] ----
        for (int kc = 0; kc < 17; ++kc) {
            float4 nv;
            if (kc < 16) {
                const int k = (kc + 1) * 16 + gq;
                if (k < 128)      nv = *(const float4*)&g_h[(size_t)sSrc[gr] * DD + k];
                else if (k < 256) nv = *(const float4*)&g_h[(size_t)sDst[gr] * DD + (k - 128)];
                else              nv = *(const float4*)&g_rbf[(size_t)(e0 + gr) * RR + gq];
            }
            const float* A = bufs[kc & 1];
            const int kbase = kc * 16;
#pragma unroll
            for (int kk = 0; kk < 16; ++kk) {
                const float* wrow = &sW1[(kbase + kk) * DD + c0];
                const ulonglong2 B0 = *(const ulonglong2*)wrow;
                const ulonglong2 B1 = *(const ulonglong2*)(wrow + 4);
#pragma unroll
                for (int i = 0; i < 4; ++i) {
                    const float a = A[(r0 + i) * 16 + kk];
                    const unsigned long long aa = pk2(a, a);
                    ffma2(acc[i][0], aa, B0.x);
                    ffma2(acc[i][1], aa, B0.y);
                    ffma2(acc[i][2], aa, B1.x);
                    ffma2(acc[i][3], aa, B1.y);
                }
            }
            if (kc < 16) *(float4*)&bufs[(kc + 1) & 1][gr * 16 + gq] = nv;
            __syncthreads();
        }

        // epilogue 1: bias + SiLU -> sHid ; pre-stage W2 chunk 0
        {
            float4 w2v = *(const float4*)&w2[tid * 4];
#pragma unroll
            for (int i = 0; i < 4; ++i) {
                float* hrow = &sHid[(r0 + i) * HSTR + c0];
                float o[8];
#pragma unroll
                for (int p = 0; p < 4; ++p) {
                    float x, y; up2(acc[i][p], x, y);
                    o[2 * p]     = silu_f(x + bias1[2 * p]);
                    o[2 * p + 1] = silu_f(y + bias1[2 * p + 1]);
                    acc[i][p] = 0ull;
                }
                *(float4*)&hrow[0] = make_float4(o[0], o[1], o[2], o[3]);
                *(float4*)&hrow[4] = make_float4(o[4], o[5], o[6], o[7]);
            }
            *(float4*)&bufs[0][tid * 4] = w2v;
        }
        __syncthreads();

        // ---- GEMM2: [128 x 128] @ [128 x 128], W2 streamed double-buffered ----
        for (int kc = 0; kc < 8; ++kc) {
            float4 nv;
            if (kc < 7) nv = *(const float4*)&w2[(size_t)(kc + 1) * 16 * DD + tid * 4];
            const float* Bc = bufs[kc & 1];
            const int kbase = kc * 16;
#pragma unroll
            for (int kk = 0; kk < 16; ++kk) {
                const float* wrow = &Bc[kk * DD + c0];
                const ulonglong2 B0 = *(const ulonglong2*)wrow;
                const ulonglong2 B1 = *(const ulonglong2*)(wrow + 4);
#pragma unroll
                for (int i = 0; i < 4; ++i) {
                    const float a = sHid[(r0 + i) * HSTR + kbase + kk];
                    const unsigned long long aa = pk2(a, a);
                    ffma2(acc[i][0], aa, B0.x);
                    ffma2(acc[i][1], aa, B0.y);
                    ffma2(acc[i][2], aa, B1.x);
                    ffma2(acc[i][3], aa, B1.y);
                }
            }
            if (kc < 7) *(float4*)&bufs[(kc + 1) & 1][tid * 4] = nv;
            __syncthreads();
        }

        // epilogue 2: bias + scatter-add
#pragma unroll
        for (int i = 0; i < 4; ++i) {
            float* dp = &g_agg[(size_t)sDst[r0 + i] * DD + c0];
#pragma unroll
            for (int p = 0; p < 4; ++p) {
                float x, y; up2(acc[i][p], x, y);
                atomicAdd(dp + 2 * p,     x + bias2[2 * p]);
                atomicAdd(dp + 2 * p + 1, y + bias2[2 * p + 1]);
            }
        }
    }
}

// ================= node update MLP (concat(h,agg)) + residual -> g_hup =================
__global__ __launch_bounds__(512, 1)
void k_node(const float* __restrict__ w1, const float* __restrict__ b1,
            const float* __restrict__ w2, const float* __restrict__ b2,
            int numTiles) {
    extern __shared__ float sm[];
    float* sW1  = sm;                           // 256*128
    float* sHid = sW1 + 256 * DD;               // 128*HSTR
    float* sA0  = sHid + 128 * HSTR;            // 128*16
    float* sA1  = sA0 + 128 * 16;               // 128*16

    const int tid = threadIdx.x;
    const int c0 = (tid & 15) * 8;
    const int r0 = (tid >> 4) * 4;
    const int gr = tid >> 2;
    const int gq = (tid & 3) * 4;

    for (int i = tid; i < 256 * DD; i += 512) sW1[i] = w1[i];
    float bias1[8], bias2[8];
#pragma unroll
    for (int j = 0; j < 8; ++j) { bias1[j] = b1[c0 + j]; bias2[j] = b2[c0 + j]; }

    float* bufs[2] = { sA0, sA1 };

    for (int tile = blockIdx.x; tile < numTiles; tile += gridDim.x) {
        const int n0 = tile * 128;
        int gn = n0 + gr; if (gn >= NN) gn = NN - 1;
        unsigned long long acc[4][4];
#pragma unroll
        for (int i = 0; i < 4; ++i)
#pragma unroll
            for (int p = 0; p < 4; ++p) acc[i][p] = 0ull;
        __syncthreads();

        {
            float4 v = *(const float4*)&g_h[(size_t)gn * DD + gq];
            *(float4*)&bufs[0][gr * 16 + gq] = v;
        }
        __syncthreads();

        // ---- GEMM1: K=256 (h | agg) ----
        for (int kc = 0; kc < 16; ++kc) {
            float4 nv;
            if (kc < 15) {
                const int k = (kc + 1) * 16 + gq;
                if (k < 128) nv = *(const float4*)&g_h[(size_t)gn * DD + k];
                else         nv = *(const float4*)&g_agg[(size_t)gn * DD + (k - 128)];
            }
            const float* A = bufs[kc & 1];
            const int kbase = kc * 16;
#pragma unroll
            for (int kk = 0; kk < 16; ++kk) {
                const float* wrow = &sW1[(kbase + kk) * DD + c0];
                const ulonglong2 B0 = *(const ulonglong2*)wrow;
                const ulonglong2 B1 = *(const ulonglong2*)(wrow + 4);
#pragma unroll
                for (int i = 0; i < 4; ++i) {
                    const float a = A[(r0 + i) * 16 + kk];
                    const unsigned long long aa = pk2(a, a);
                    ffma2(acc[i][0], aa, B0.x);
                    ffma2(acc[i][1], aa, B0.y);
                    ffma2(acc[i][2], aa, B1.x);
                    ffma2(acc[i][3], aa, B1.y);
                }
            }
            if (kc < 15) *(float4*)&bufs[(kc + 1) & 1][gr * 16 + gq] = nv;
            __syncthreads();
        }

        // epilogue 1 + pre-stage W2 chunk 0
        {
            float4 w2v = *(const float4*)&w2[tid * 4];
#pragma unroll
            for (int i = 0; i < 4; ++i) {
                float* hrow = &sHid[(r0 + i) * HSTR + c0];
                float o[8];
#pragma unroll
                for (int p = 0; p < 4; ++p) {
                    float x, y; up2(acc[i][p], x, y);
                    o[2 * p]     = silu_f(x + bias1[2 * p]);
                    o[2 * p + 1] = silu_f(y + bias1[2 * p + 1]);
                    acc[i][p] = 0ull;
                }
                *(float4*)&hrow[0] = make_float4(o[0], o[1], o[2], o[3]);
                *(float4*)&hrow[4] = make_float4(o[4], o[5], o[6], o[7]);
            }
            *(float4*)&bufs[0][tid * 4] = w2v;
        }
        __syncthreads();

        // ---- GEMM2: K=128 ----
        for (int kc = 0; kc < 8; ++kc) {
            float4 nv;
            if (kc < 7) nv = *(const float4*)&w2[(size_t)(kc + 1) * 16 * DD + tid * 4];
            const float* Bc = bufs[kc & 1];
            const int kbase = kc * 16;
#pragma unroll
            for (int kk = 0; kk < 16; ++kk) {
                const float* wrow = &Bc[kk * DD + c0];
                const ulonglong2 B0 = *(const ulonglong2*)wrow;
                const ulonglong2 B1 = *(const ulonglong2*)(wrow + 4);
#pragma unroll
                for (int i = 0; i < 4; ++i) {
                    const float a = sHid[(r0 + i) * HSTR + kbase + kk];
                    const unsigned long long aa = pk2(a, a);
                    ffma2(acc[i][0], aa, B0.x);
                    ffma2(acc[i][1], aa, B0.y);
                    ffma2(acc[i][2], aa, B1.x);
                    ffma2(acc[i][3], aa, B1.y);
                }
            }
            if (kc < 7) *(float4*)&bufs[(kc + 1) & 1][tid * 4] = nv;
            __syncthreads();
        }

        // epilogue: bias + residual -> g_hup
#pragma unroll
        for (int i = 0; i < 4; ++i) {
            const int n = n0 + r0 + i;
            if (n < NN) {
                const float4 h0 = *(const float4*)&g_h[(size_t)n * DD + c0];
                const float4 h1 = *(const float4*)&g_h[(size_t)n * DD + c0 + 4];
                float o[8];
#pragma unroll
                for (int p = 0; p < 4; ++p) {
                    float x, y; up2(acc[i][p], x, y);
                    o[2 * p]     = x + bias2[2 * p];
                    o[2 * p + 1] = y + bias2[2 * p + 1];
                }
                *(float4*)&g_hup[(size_t)n * DD + c0] =
                    make_float4(o[0] + h0.x, o[1] + h0.y, o[2] + h0.z, o[3] + h0.w);
                *(float4*)&g_hup[(size_t)n * DD + c0 + 4] =
                    make_float4(o[4] + h1.x, o[5] + h1.y, o[6] + h1.z, o[7] + h1.w);
            }
        }
    }
}

// ---------------- LayerNorm: g_h = LN(g_hup) ----------------
__global__ void k_ln(const float* __restrict__ g, const float* __restrict__ b) {
    const int gl = blockIdx.x * blockDim.x + threadIdx.x;
    const int node = gl >> 5;
    const int lane = gl & 31;
    if (node >= NN) return;
    const float4 v = ((const float4*)(g_hup + (size_t)node * DD))[lane];
    float s = v.x + v.y + v.z + v.w;
#pragma unroll
    for (int o = 16; o; o >>= 1) s += __shfl_xor_sync(0xFFFFFFFFu, s, o);
    const float mu = s * (1.0f / 128.0f);
    const float d0 = v.x - mu, d1 = v.y - mu, d2 = v.z - mu, d3 = v.w - mu;
    float q = d0 * d0 + d1 * d1 + d2 * d2 + d3 * d3;
#pragma unroll
    for (int o = 16; o; o >>= 1) q += __shfl_xor_sync(0xFFFFFFFFu, q, o);
    const float inv = rsqrtf(q * (1.0f / 128.0f) + 1e-5f);
    const float4 gg = ((const float4*)g)[lane];
    const float4 bb = ((const float4*)b)[lane];
    float4 o4;
    o4.x = d0 * inv * gg.x + bb.x;
    o4.y = d1 * inv * gg.y + bb.y;
    o4.z = d2 * inv * gg.z + bb.z;
    o4.w = d3 * inv * gg.w + bb.w;
    ((float4*)(g_h + (size_t)node * DD))[lane] = o4;
}

// ---------------- output MLP ----------------
__global__ void k_out(const float* __restrict__ w1, const float* __restrict__ b1,
                      const float* __restrict__ w2, const float* __restrict__ b2,
                      float* __restrict__ out) {
    extern __shared__ float sm[];
    float* sW1  = sm;
    float* sW2  = sW1 + DD * DD;
    float* sX   = sW2 + DD * 3;
    float* sHid = sX + DD;
    const int j = threadIdx.x;  // 128
    for (int i = j; i < DD * DD; i += DD) sW1[i] = w1[i];
    for (int i = j; i < DD * 3; i += DD) sW2[i] = w2[i];
    const float bb1 = b1[j];
    __syncthreads();
    const int n0 = blockIdx.x * 16;
    for (int m = 0; m < 16; ++m) {
        const int n = n0 + m;
        sX[j] = g_h[(size_t)n * DD + j];
        __syncthreads();
        float acc = bb1;
#pragma unroll 8
        for (int k = 0; k < DD; ++k) acc += sX[k] * sW1[k * DD + j];
        sHid[j] = silu_f(acc);
        __syncthreads();
        if (j < 3) {
            float o = b2[j];
            for (int k = 0; k < DD; ++k) o += sHid[k] * sW2[k * 3 + j];
            out[(size_t)n * 3 + j] = o;
        }
        __syncthreads();
    }
}

// ---------------- launch ----------------
extern "C" void kernel_launch(void* const* d_in, const int* in_sizes, int n_in,
                              void* d_out, int out_size) {
    const float* x_t      = (const float*)d_in[0];
    const int*   ei       = (const int*)d_in[1];
    const int*   tp       = (const int*)d_in[2];
    const float* time_w1  = (const float*)d_in[3];
    const float* time_b1  = (const float*)d_in[4];
    const float* time_w2  = (const float*)d_in[5];
    const float* time_b2  = (const float*)d_in[6];
    const float* nodein_w1= (const float*)d_in[7];
    const float* nodein_b1= (const float*)d_in[8];
    const float* nodein_w2= (const float*)d_in[9];
    const float* nodein_b2= (const float*)d_in[10];
    const float* phim_w1  = (const float*)d_in[11];
    const float* phim_b1  = (const float*)d_in[12];
    const float* phim_w2  = (const float*)d_in[13];
    const float* phim_b2  = (const float*)d_in[14];
    const float* phih_w1  = (const float*)d_in[15];
    const float* phih_b1  = (const float*)d_in[16];
    const float* phih_w2  = (const float*)d_in[17];
    const float* phih_b2  = (const float*)d_in[18];
    const float* ln_g     = (const float*)d_in[19];
    const float* ln_b     = (const float*)d_in[20];
    const float* out_w1   = (const float*)d_in[21];
    const float* out_b1   = (const float*)d_in[22];
    const float* out_w2   = (const float*)d_in[23];
    const float* out_b2   = (const float*)d_in[24];
    float* out = (float*)d_out;

    const int SMEM_EDGE   = (272 * DD + 128 * HSTR + 2 * 128 * 16) * 4 + 256 * 4;
    const int SMEM_NODE   = (256 * DD + 128 * HSTR + 2 * 128 * 16) * 4;
    const int SMEM_NODEIN = (DD * DD + 3 * DD + DD + DD) * 4;
    const int SMEM_OUT    = (DD * DD + DD * 3 + DD + DD) * 4;

    cudaFuncSetAttribute(k_edge,   cudaFuncAttributeMaxDynamicSharedMemorySize, SMEM_EDGE);
    cudaFuncSetAttribute(k_node,   cudaFuncAttributeMaxDynamicSharedMemorySize, SMEM_NODE);
    cudaFuncSetAttribute(k_nodein, cudaFuncAttributeMaxDynamicSharedMemorySize, SMEM_NODEIN);
    cudaFuncSetAttribute(k_out,    cudaFuncAttributeMaxDynamicSharedMemorySize, SMEM_OUT);

    k_time<<<1, 128>>>(tp, time_w1, time_b1, time_w2, time_b2, nodein_w1, nodein_b1);
    k_rbf<<<(EE + 255) / 256, 256>>>(x_t, ei);
    k_nodein<<<(NN + 63) / 64, 128, SMEM_NODEIN>>>(x_t, nodein_w1, nodein_w2, nodein_b2);

    const int edgeTiles = EE / 128;          // 5000
    const int nodeTiles = (NN + 127) / 128;  // 157

    for (int l = 0; l < LL; ++l) {
        k_zero<<<(NN * DD + 255) / 256, 256>>>();
        k_edge<<<148, 512, SMEM_EDGE>>>(ei,
                                        phim_w1 + (size_t)l * 272 * DD,
                                        phim_b1 + (size_t)l * DD,
                                        phim_w2 + (size_t)l * DD * DD,
                                        phim_b2 + (size_t)l * DD,
                                        edgeTiles);
        k_node<<<148, 512, SMEM_NODE>>>(phih_w1 + (size_t)l * 256 * DD,
                                        phih_b1 + (size_t)l * DD,
                                        phih_w2 + (size_t)l * DD * DD,
                                        phih_b2 + (size_t)l * DD,
                                        nodeTiles);
        k_ln<<<(NN * 32 + 255) / 256, 256>>>(ln_g + (size_t)l * DD, ln_b + (size_t)l * DD);
    }

    k_out<<<NN / 16, 128, SMEM_OUT>>>(out_w1, out_b1, out_w2, out_b2, out);
}

// round 8
// speedup vs baseline: 3.2575x; 2.8738x over previous
#include <cuda_runtime.h>
#include <cuda_bf16.h>
#include <cstdint>

#define NN 20000
#define EE 640000
#define DD 128
#define RR 16
#define LL 3

// ---------------- device scratch ----------------
__device__ float g_h   [(size_t)NN * DD];
__device__ float g_hup [(size_t)NN * DD];
__device__ float g_agg [(size_t)NN * DD];
__device__ float g_rbf [(size_t)EE * RR];
__device__ float g_xs  [(size_t)NN * DD];   // h @ Wa + b1
__device__ float g_xd  [(size_t)NN * DD];   // h @ Wb
__device__ float g_base[DD];

__device__ __forceinline__ float silu_f(float x) {
    return x / (1.0f + __expf(-x));
}

// sm_103a packed fp32 FMA helpers
__device__ __forceinline__ unsigned long long pk2(float lo, float hi) {
    unsigned long long r;
    asm("mov.b64 %0, {%1, %2};" : "=l"(r) : "f"(lo), "f"(hi));
    return r;
}
__device__ __forceinline__ void up2(unsigned long long v, float& lo, float& hi) {
    asm("mov.b64 {%0, %1}, %2;" : "=f"(lo), "=f"(hi) : "l"(v));
}
__device__ __forceinline__ void ffma2(unsigned long long& d, unsigned long long a, unsigned long long b) {
    asm("fma.rn.f32x2 %0, %1, %2, %0;" : "+l"(d) : "l"(a), "l"(b));
}
__device__ __forceinline__ void red_add_v4(float* p, float a, float b, float c, float d) {
    asm volatile("red.global.add.v4.f32 [%0], {%1, %2, %3, %4};"
                 :: "l"(p), "f"(a), "f"(b), "f"(c), "f"(d) : "memory");
}

// ---------------- time embedding + time MLP + nodein te-bias precompute ----------------
__global__ void k_time(const int* __restrict__ tptr,
                       const float* __restrict__ tw1, const float* __restrict__ tb1,
                       const float* __restrict__ tw2, const float* __restrict__ tb2,
                       const float* __restrict__ nw1, const float* __restrict__ nb1) {
    __shared__ float sE[DD], sH[DD], sTe[DD];
    const int j = threadIdx.x;  // 128 threads
    int iv = *tptr;
    float t = (iv >= 0 && iv < 1000000) ? (float)iv : __int_as_float(iv);
    {
        int i = (j < 64) ? j : (j - 64);
        float f = __expf(-logf(10000.0f) * (float)i / 63.0f);
        float a = t * f;
        sE[j] = (j < 64) ? sinf(a) : cosf(a);
    }
    __syncthreads();
    float acc = tb1[j];
    for (int k = 0; k < DD; ++k) acc += sE[k] * tw1[k * DD + j];
    sH[j] = silu_f(acc);
    __syncthreads();
    float acc2 = tb2[j];
    for (int k = 0; k < DD; ++k) acc2 += sH[k] * tw2[k * DD + j];
    sTe[j] = acc2;
    __syncthreads();
    float accb = nb1[j];
    for (int k = 0; k < DD; ++k) accb += sTe[k] * nw1[(3 + k) * DD + j];
    g_base[j] = accb;
}

// ---------------- RBF per edge ----------------
__global__ void k_rbf(const float* __restrict__ xt, const int* __restrict__ ei) {
    const int e = blockIdx.x * 256 + threadIdx.x;
    if (e >= EE) return;
    const int s = ei[e], d = ei[EE + e];
    const float dx = xt[s * 3 + 0] - xt[d * 3 + 0];
    const float dy = xt[s * 3 + 1] - xt[d * 3 + 1];
    const float r = sqrtf(dx * dx + dy * dy + 1e-8f);
    const float step = 1.41421356237309515f / 15.0f;
    const float gamma = 1.0f / (2.0f * step * step);
#pragma unroll
    for (int c = 0; c < RR; ++c) {
        float u = r - (float)c * step;
        g_rbf[(size_t)e * RR + c] = __expf(-gamma * u * u);
    }
}

// ---------------- node input MLP (te part folded into g_base) ----------------
__global__ void k_nodein(const float* __restrict__ xt,
                         const float* __restrict__ w1,
                         const float* __restrict__ w2,
                         const float* __restrict__ b2) {
    extern __shared__ float sm[];
    float* sW2  = sm;
    float* sW1x = sW2 + DD * DD;
    float* sB   = sW1x + 3 * DD;
    float* sHid = sB + DD;
    const int j = threadIdx.x;  // 128
    for (int i = j; i < DD * DD; i += DD) sW2[i] = w2[i];
    sW1x[j]          = w1[0 * DD + j];
    sW1x[DD + j]     = w1[1 * DD + j];
    sW1x[2 * DD + j] = w1[2 * DD + j];
    sB[j] = g_base[j];
    const float bb = b2[j];
    __syncthreads();
    const int n0 = blockIdx.x * 64;
    for (int m = 0; m < 64; ++m) {
        const int n = n0 + m;
        if (n >= NN) break;
        const float x0 = xt[n * 3 + 0], x1 = xt[n * 3 + 1], x2 = xt[n * 3 + 2];
        sHid[j] = silu_f(sB[j] + x0 * sW1x[j] + x1 * sW1x[DD + j] + x2 * sW1x[2 * DD + j]);
        __syncthreads();
        float o = bb;
#pragma unroll 8
        for (int k = 0; k < DD; ++k) o += sHid[k] * sW2[k * DD + j];
        g_h[(size_t)n * DD + j] = o;
        __syncthreads();
    }
}

// ---------------- zero agg ----------------
__global__ void k_zero() {
    const int i = blockIdx.x * 256 + threadIdx.x;
    if (i < NN * DD) g_agg[i] = 0.0f;
}

// ================= per-layer node precompute: out = h @ W (+ bias) =================
// sel==0 -> g_xs, sel==1 -> g_xd  (device-side symbol resolution; passing the
// __device__ symbol from host was the R6 bug)
#define ATSTR 132
__global__ __launch_bounds__(256, 1)
void k_pre(const float* __restrict__ W, const float* __restrict__ bias, int sel) {
    extern __shared__ float sm[];
    float* sW  = sm;            // 128*128
    float* sAT = sW + DD * DD;  // 128*ATSTR  (transposed h tile, swizzled)
    float* out = sel ? g_xd : g_xs;

    const int tid = threadIdx.x;
    const int tx = tid & 15, ty = tid >> 4;
    const int c0 = tx * 8, r0 = ty * 8;
    const int n0 = blockIdx.x * 128;

    {
        const float4* w4 = (const float4*)W;
#pragma unroll
        for (int i = 0; i < 16; ++i)
            ((float4*)sW)[tid + i * 256] = w4[tid + i * 256];
    }
    // gather h tile transposed into sAT
#pragma unroll
    for (int i = 0; i < 16; ++i) {
        const int idx = tid + i * 256;
        const int nl = idx >> 5;            // local node 0..127
        const int q = (idx & 31) * 4;       // k base
        int n = n0 + nl; if (n >= NN) n = NN - 1;
        const float4 v = *(const float4*)&g_h[(size_t)n * DD + q];
        const float vv[4] = { v.x, v.y, v.z, v.w };
#pragma unroll
        for (int m = 0; m < 4; ++m) {
            const int k = q + m;
            sAT[k * ATSTR + (nl ^ (((k >> 3) & 7) << 3))] = vv[m];
        }
    }
    __syncthreads();

    unsigned long long acc[8][4];
#pragma unroll
    for (int i = 0; i < 8; ++i)
#pragma unroll
        for (int p = 0; p < 4; ++p) acc[i][p] = 0ull;

    for (int kk = 0; kk < 128; ++kk) {
        const int rs = r0 ^ (((kk >> 3) & 7) << 3);
        const float4 a0 = *(const float4*)&sAT[kk * ATSTR + rs];
        const float4 a1 = *(const float4*)&sAT[kk * ATSTR + rs + 4];
        const ulonglong2 B0 = *(const ulonglong2*)&sW[kk * DD + c0];
        const ulonglong2 B1 = *(const ulonglong2*)&sW[kk * DD + c0 + 4];
        const float a[8] = { a0.x, a0.y, a0.z, a0.w, a1.x, a1.y, a1.z, a1.w };
#pragma unroll
        for (int i = 0; i < 8; ++i) {
            const unsigned long long aa = pk2(a[i], a[i]);
            ffma2(acc[i][0], aa, B0.x);
            ffma2(acc[i][1], aa, B0.y);
            ffma2(acc[i][2], aa, B1.x);
            ffma2(acc[i][3], aa, B1.y);
        }
    }

    float bv[8];
#pragma unroll
    for (int j = 0; j < 8; ++j) bv[j] = bias ? bias[c0 + j] : 0.0f;
#pragma unroll
    for (int i = 0; i < 8; ++i) {
        const int n = n0 + r0 + i;
        if (n < NN) {
            float o[8];
#pragma unroll
            for (int p = 0; p < 4; ++p) {
                float x, y; up2(acc[i][p], x, y);
                o[2 * p] = x + bv[2 * p]; o[2 * p + 1] = y + bv[2 * p + 1];
            }
            *(float4*)&out[(size_t)n * DD + c0]     = make_float4(o[0], o[1], o[2], o[3]);
            *(float4*)&out[(size_t)n * DD + c0 + 4] = make_float4(o[4], o[5], o[6], o[7]);
        }
    }
}

// ================= fused edge kernel =================
// pre = Xs[src] + Xd[dst] + rbf @ Wr ; hid = silu(pre); m = hid @ W2 + b2; red agg[dst] += m
// tile = 128 edges x 128 cols, 256 threads, 8x8/thread, W2+Wr resident in smem.
#define SSTR 132
#define HSTR 132
#define RSTR 132
__global__ __launch_bounds__(256, 1)
void k_edge(const int* __restrict__ ei,
            const float* __restrict__ Wr,   // [16][128]
            const float* __restrict__ w2,   // [128][128]
            const float* __restrict__ b2,
            int numTiles) {
    extern __shared__ float sm[];
    float* sW2   = sm;                       // 128*128
    float* sWr   = sW2 + DD * DD;            // 16*128
    float* sSum  = sWr + RR * DD;            // 128*SSTR
    float* sHidT = sSum + 128 * SSTR;        // 128*HSTR (swizzled)
    float* sRbfT = sHidT + 128 * HSTR;       // 16*RSTR
    int*   sSrc  = (int*)(sRbfT + RR * RSTR);// 128
    int*   sDst  = sSrc + 128;               // 128

    const int tid = threadIdx.x;
    const int tx = tid & 15, ty = tid >> 4;
    const int c0 = tx * 8, r0 = ty * 8;

    {
        const float4* w4 = (const float4*)w2;
#pragma unroll
        for (int i = 0; i < 16; ++i)
            ((float4*)sW2)[tid + i * 256] = w4[tid + i * 256];
        const float4* wr4 = (const float4*)Wr;
#pragma unroll
        for (int i = 0; i < 2; ++i)
            ((float4*)sWr)[tid + i * 256] = wr4[tid + i * 256];
    }
    float bias2[8];
#pragma unroll
    for (int j = 0; j < 8; ++j) bias2[j] = b2[c0 + j];

    for (int tile = blockIdx.x; tile < numTiles; tile += gridDim.x) {
        const int e0 = tile * 128;
        __syncthreads();
        if (tid < 128) { sSrc[tid] = ei[e0 + tid]; sDst[tid] = ei[EE + e0 + tid]; }
        __syncthreads();

        // ---- gather: sSum[row][j] = Xs[src][j] + Xd[dst][j] ----
#pragma unroll
        for (int i = 0; i < 16; ++i) {
            const int idx = tid + i * 256;
            const int row = idx >> 5;
            const int q = (idx & 31) * 4;
            const float4 a = *(const float4*)&g_xs[(size_t)sSrc[row] * DD + q];
            const float4 b = *(const float4*)&g_xd[(size_t)sDst[row] * DD + q];
            *(float4*)&sSum[row * SSTR + q] =
                make_float4(a.x + b.x, a.y + b.y, a.z + b.z, a.w + b.w);
        }
        // ---- gather rbf transposed ----
#pragma unroll
        for (int i = 0; i < 2; ++i) {
            const int idx = tid + i * 256;
            const int row = idx >> 2;
            const int c4 = (idx & 3) * 4;
            const float4 v = *(const float4*)&g_rbf[(size_t)(e0 + row) * RR + c4];
            sRbfT[(c4 + 0) * RSTR + row] = v.x;
            sRbfT[(c4 + 1) * RSTR + row] = v.y;
            sRbfT[(c4 + 2) * RSTR + row] = v.z;
            sRbfT[(c4 + 3) * RSTR + row] = v.w;
        }
        __syncthreads();

        // ---- phase 1: K=16 rbf GEMM ----
        unsigned long long acc[8][4];
#pragma unroll
        for (int i = 0; i < 8; ++i)
#pragma unroll
            for (int p = 0; p < 4; ++p) acc[i][p] = 0ull;

#pragma unroll
        for (int kk = 0; kk < 16; ++kk) {
            const float4 a0 = *(const float4*)&sRbfT[kk * RSTR + r0];
            const float4 a1 = *(const float4*)&sRbfT[kk * RSTR + r0 + 4];
            const ulonglong2 B0 = *(const ulonglong2*)&sWr[kk * DD + c0];
            const ulonglong2 B1 = *(const ulonglong2*)&sWr[kk * DD + c0 + 4];
            const float a[8] = { a0.x, a0.y, a0.z, a0.w, a1.x, a1.y, a1.z, a1.w };
#pragma unroll
            for (int i = 0; i < 8; ++i) {
                const unsigned long long aa = pk2(a[i], a[i]);
                ffma2(acc[i][0], aa, B0.x);
                ffma2(acc[i][1], aa, B0.y);
                ffma2(acc[i][2], aa, B1.x);
                ffma2(acc[i][3], aa, B1.y);
            }
        }

        // ---- add gathered sums, silu, write transposed (swizzled) ----
        float o[8][8];
#pragma unroll
        for (int i = 0; i < 8; ++i) {
            const float4 s0 = *(const float4*)&sSum[(r0 + i) * SSTR + c0];
            const float4 s1 = *(const float4*)&sSum[(r0 + i) * SSTR + c0 + 4];
            float x, y;
            up2(acc[i][0], x, y); o[i][0] = silu_f(x + s0.x); o[i][1] = silu_f(y + s0.y);
            up2(acc[i][1], x, y); o[i][2] = silu_f(x + s0.z); o[i][3] = silu_f(y + s0.w);
            up2(acc[i][2], x, y); o[i][4] = silu_f(x + s1.x); o[i][5] = silu_f(y + s1.y);
            up2(acc[i][3], x, y); o[i][6] = silu_f(x + s1.z); o[i][7] = silu_f(y + s1.w);
#pragma unroll
            for (int p = 0; p < 4; ++p) acc[i][p] = 0ull;
        }
        {
            const int rs = r0 ^ ((tx & 7) << 3);   // ((c0+jj)>>3)&7 == tx&7
#pragma unroll
            for (int jj = 0; jj < 8; ++jj) {
                const int j = c0 + jj;
                *(float4*)&sHidT[j * HSTR + rs] =
                    make_float4(o[0][jj], o[1][jj], o[2][jj], o[3][jj]);
                *(float4*)&sHidT[j * HSTR + rs + 4] =
                    make_float4(o[4][jj], o[5][jj], o[6][jj], o[7][jj]);
            }
        }
        __syncthreads();

        // ---- phase 2: K=128 GEMM2 (A = HidT broadcast, B = resident W2) ----
        for (int kk = 0; kk < 128; ++kk) {
            const int rs = r0 ^ (((kk >> 3) & 7) << 3);
            const float4 a0 = *(const float4*)&sHidT[kk * HSTR + rs];
            const float4 a1 = *(const float4*)&sHidT[kk * HSTR + rs + 4];
            const ulonglong2 B0 = *(const ulonglong2*)&sW2[kk * DD + c0];
            const ulonglong2 B1 = *(const ulonglong2*)&sW2[kk * DD + c0 + 4];
            const float a[8] = { a0.x, a0.y, a0.z, a0.w, a1.x, a1.y, a1.z, a1.w };
#pragma unroll
            for (int i = 0; i < 8; ++i) {
                const unsigned long long aa = pk2(a[i], a[i]);
                ffma2(acc[i][0], aa, B0.x);
                ffma2(acc[i][1], aa, B0.y);
                ffma2(acc[i][2], aa, B1.x);
                ffma2(acc[i][3], aa, B1.y);
            }
        }

        // ---- epilogue: bias + vectorized reduction scatter ----
#pragma unroll
        for (int i = 0; i < 8; ++i) {
            float* dp = &g_agg[(size_t)sDst[r0 + i] * DD + c0];
            float x0, y0, x1, y1;
            up2(acc[i][0], x0, y0); up2(acc[i][1], x1, y1);
            red_add_v4(dp, x0 + bias2[0], y0 + bias2[1], x1 + bias2[2], y1 + bias2[3]);
            up2(acc[i][2], x0, y0); up2(acc[i][3], x1, y1);
            red_add_v4(dp + 4, x0 + bias2[4], y0 + bias2[5], x1 + bias2[6], y1 + bias2[7]);
        }
    }
}

// ================= node update MLP (concat(h,agg)) + residual -> g_hup =================
#define NHSTR 132
__global__ __launch_bounds__(512, 1)
void k_node(const float* __restrict__ w1, const float* __restrict__ b1,
            const float* __restrict__ w2, const float* __restrict__ b2,
            int numTiles) {
    extern __shared__ float sm[];
    float* sW1  = sm;                           // 256*128
    float* sHid = sW1 + 256 * DD;               // 128*NHSTR
    float* sA0  = sHid + 128 * NHSTR;           // 128*16
    float* sA1  = sA0 + 128 * 16;               // 128*16

    const int tid = threadIdx.x;
    const int c0 = (tid & 15) * 8;
    const int r0 = (tid >> 4) * 4;
    const int gr = tid >> 2;
    const int gq = (tid & 3) * 4;

    for (int i = tid; i < 256 * DD; i += 512) sW1[i] = w1[i];
    float bias1[8], bias2[8];
#pragma unroll
    for (int j = 0; j < 8; ++j) { bias1[j] = b1[c0 + j]; bias2[j] = b2[c0 + j]; }

    float* bufs[2] = { sA0, sA1 };

    for (int tile = blockIdx.x; tile < numTiles; tile += gridDim.x) {
        const int n0 = tile * 128;
        int gn = n0 + gr; if (gn >= NN) gn = NN - 1;
        unsigned long long acc[4][4];
#pragma unroll
        for (int i = 0; i < 4; ++i)
#pragma unroll
            for (int p = 0; p < 4; ++p) acc[i][p] = 0ull;
        __syncthreads();

        {
            float4 v = *(const float4*)&g_h[(size_t)gn * DD + gq];
            *(float4*)&bufs[0][gr * 16 + gq] = v;
        }
        __syncthreads();

        for (int kc = 0; kc < 16; ++kc) {
            float4 nv;
            if (kc < 15) {
                const int k = (kc + 1) * 16 + gq;
                if (k < 128) nv = *(const float4*)&g_h[(size_t)gn * DD + k];
                else         nv = *(const float4*)&g_agg[(size_t)gn * DD + (k - 128)];
            }
            const float* A = bufs[kc & 1];
            const int kbase = kc * 16;
#pragma unroll
            for (int kk = 0; kk < 16; ++kk) {
                const float* wrow = &sW1[(kbase + kk) * DD + c0];
                const ulonglong2 B0 = *(const ulonglong2*)wrow;
                const ulonglong2 B1 = *(const ulonglong2*)(wrow + 4);
#pragma unroll
                for (int i = 0; i < 4; ++i) {
                    const float a = A[(r0 + i) * 16 + kk];
                    const unsigned long long aa = pk2(a, a);
                    ffma2(acc[i][0], aa, B0.x);
                    ffma2(acc[i][1], aa, B0.y);
                    ffma2(acc[i][2], aa, B1.x);
                    ffma2(acc[i][3], aa, B1.y);
                }
            }
            if (kc < 15) *(float4*)&bufs[(kc + 1) & 1][gr * 16 + gq] = nv;
            __syncthreads();
        }

        {
            float4 w2v = *(const float4*)&w2[tid * 4];
#pragma unroll
            for (int i = 0; i < 4; ++i) {
                float* hrow = &sHid[(r0 + i) * NHSTR + c0];
                float o[8];
#pragma unroll
                for (int p = 0; p < 4; ++p) {
                    float x, y; up2(acc[i][p], x, y);
                    o[2 * p]     = silu_f(x + bias1[2 * p]);
                    o[2 * p + 1] = silu_f(y + bias1[2 * p + 1]);
                    acc[i][p] = 0ull;
                }
                *(float4*)&hrow[0] = make_float4(o[0], o[1], o[2], o[3]);
                *(float4*)&hrow[4] = make_float4(o[4], o[5], o[6], o[7]);
            }
            *(float4*)&bufs[0][tid * 4] = w2v;
        }
        __syncthreads();

        for (int kc = 0; kc < 8; ++kc) {
            float4 nv;
            if (kc < 7) nv = *(const float4*)&w2[(size_t)(kc + 1) * 16 * DD + tid * 4];
            const float* Bc = bufs[kc & 1];
            const int kbase = kc * 16;
#pragma unroll
            for (int kk = 0; kk < 16; ++kk) {
                const float* wrow = &Bc[kk * DD + c0];
                const ulonglong2 B0 = *(const ulonglong2*)wrow;
                const ulonglong2 B1 = *(const ulonglong2*)(wrow + 4);
#pragma unroll
                for (int i = 0; i < 4; ++i) {
                    const float a = sHid[(r0 + i) * NHSTR + kbase + kk];
                    const unsigned long long aa = pk2(a, a);
                    ffma2(acc[i][0], aa, B0.x);
                    ffma2(acc[i][1], aa, B0.y);
                    ffma2(acc[i][2], aa, B1.x);
                    ffma2(acc[i][3], aa, B1.y);
                }
            }
            if (kc < 7) *(float4*)&bufs[(kc + 1) & 1][tid * 4] = nv;
            __syncthreads();
        }

#pragma unroll
        for (int i = 0; i < 4; ++i) {
            const int n = n0 + r0 + i;
            if (n < NN) {
                const float4 h0 = *(const float4*)&g_h[(size_t)n * DD + c0];
                const float4 h1 = *(const float4*)&g_h[(size_t)n * DD + c0 + 4];
                float o[8];
#pragma unroll
                for (int p = 0; p < 4; ++p) {
                    float x, y; up2(acc[i][p], x, y);
                    o[2 * p]     = x + bias2[2 * p];
                    o[2 * p + 1] = y + bias2[2 * p + 1];
                }
                *(float4*)&g_hup[(size_t)n * DD + c0] =
                    make_float4(o[0] + h0.x, o[1] + h0.y, o[2] + h0.z, o[3] + h0.w);
                *(float4*)&g_hup[(size_t)n * DD + c0 + 4] =
                    make_float4(o[4] + h1.x, o[5] + h1.y, o[6] + h1.z, o[7] + h1.w);
            }
        }
    }
}

// ---------------- LayerNorm: g_h = LN(g_hup) ----------------
__global__ void k_ln(const float* __restrict__ g, const float* __restrict__ b) {
    const int gl = blockIdx.x * blockDim.x + threadIdx.x;
    const int node = gl >> 5;
    const int lane = gl & 31;
    if (node >= NN) return;
    const float4 v = ((const float4*)(g_hup + (size_t)node * DD))[lane];
    float s = v.x + v.y + v.z + v.w;
#pragma unroll
    for (int o = 16; o; o >>= 1) s += __shfl_xor_sync(0xFFFFFFFFu, s, o);
    const float mu = s * (1.0f / 128.0f);
    const float d0 = v.x - mu, d1 = v.y - mu, d2 = v.z - mu, d3 = v.w - mu;
    float q = d0 * d0 + d1 * d1 + d2 * d2 + d3 * d3;
#pragma unroll
    for (int o = 16; o; o >>= 1) q += __shfl_xor_sync(0xFFFFFFFFu, q, o);
    const float inv = rsqrtf(q * (1.0f / 128.0f) + 1e-5f);
    const float4 gg = ((const float4*)g)[lane];
    const float4 bb = ((const float4*)b)[lane];
    float4 o4;
    o4.x = d0 * inv * gg.x + bb.x;
    o4.y = d1 * inv * gg.y + bb.y;
    o4.z = d2 * inv * gg.z + bb.z;
    o4.w = d3 * inv * gg.w + bb.w;
    ((float4*)(g_h + (size_t)node * DD))[lane] = o4;
}

// ---------------- output MLP ----------------
__global__ void k_out(const float* __restrict__ w1, const float* __restrict__ b1,
                      const float* __restrict__ w2, const float* __restrict__ b2,
                      float* __restrict__ out) {
    extern __shared__ float sm[];
    float* sW1  = sm;
    float* sW2  = sW1 + DD * DD;
    float* sX   = sW2 + DD * 3;
    float* sHid = sX + DD;
    const int j = threadIdx.x;  // 128
    for (int i = j; i < DD * DD; i += DD) sW1[i] = w1[i];
    for (int i = j; i < DD * 3; i += DD) sW2[i] = w2[i];
    const float bb1 = b1[j];
    __syncthreads();
    const int n0 = blockIdx.x * 16;
    for (int m = 0; m < 16; ++m) {
        const int n = n0 + m;
        sX[j] = g_h[(size_t)n * DD + j];
        __syncthreads();
        float acc = bb1;
#pragma unroll 8
        for (int k = 0; k < DD; ++k) acc += sX[k] * sW1[k * DD + j];
        sHid[j] = silu_f(acc);
        __syncthreads();
        if (j < 3) {
            float o = b2[j];
            for (int k = 0; k < DD; ++k) o += sHid[k] * sW2[k * 3 + j];
            out[(size_t)n * 3 + j] = o;
        }
        __syncthreads();
    }
}

// ---------------- launch ----------------
extern "C" void kernel_launch(void* const* d_in, const int* in_sizes, int n_in,
                              void* d_out, int out_size) {
    const float* x_t      = (const float*)d_in[0];
    const int*   ei       = (const int*)d_in[1];
    const int*   tp       = (const int*)d_in[2];
    const float* time_w1  = (const float*)d_in[3];
    const float* time_b1  = (const float*)d_in[4];
    const float* time_w2  = (const float*)d_in[5];
    const float* time_b2  = (const float*)d_in[6];
    const float* nodein_w1= (const float*)d_in[7];
    const float* nodein_b1= (const float*)d_in[8];
    const float* nodein_w2= (const float*)d_in[9];
    const float* nodein_b2= (const float*)d_in[10];
    const float* phim_w1  = (const float*)d_in[11];
    const float* phim_b1  = (const float*)d_in[12];
    const float* phim_w2  = (const float*)d_in[13];
    const float* phim_b2  = (const float*)d_in[14];
    const float* phih_w1  = (const float*)d_in[15];
    const float* phih_b1  = (const float*)d_in[16];
    const float* phih_w2  = (const float*)d_in[17];
    const float* phih_b2  = (const float*)d_in[18];
    const float* ln_g     = (const float*)d_in[19];
    const float* ln_b     = (const float*)d_in[20];
    const float* out_w1   = (const float*)d_in[21];
    const float* out_b1   = (const float*)d_in[22];
    const float* out_w2   = (const float*)d_in[23];
    const float* out_b2   = (const float*)d_in[24];
    float* out = (float*)d_out;

    const int SMEM_EDGE = (DD * DD + RR * DD + 128 * SSTR + 128 * HSTR + RR * RSTR) * 4 + 256 * 4;
    const int SMEM_PRE  = (DD * DD + 128 * ATSTR) * 4;
    const int SMEM_NODE = (256 * DD + 128 * NHSTR + 2 * 128 * 16) * 4;
    const int SMEM_NODEIN = (DD * DD + 3 * DD + DD + DD) * 4;
    const int SMEM_OUT    = (DD * DD + DD * 3 + DD + DD) * 4;

    cudaFuncSetAttribute(k_edge,   cudaFuncAttributeMaxDynamicSharedMemorySize, SMEM_EDGE);
    cudaFuncSetAttribute(k_pre,    cudaFuncAttributeMaxDynamicSharedMemorySize, SMEM_PRE);
    cudaFuncSetAttribute(k_node,   cudaFuncAttributeMaxDynamicSharedMemorySize, SMEM_NODE);
    cudaFuncSetAttribute(k_nodein, cudaFuncAttributeMaxDynamicSharedMemorySize, SMEM_NODEIN);
    cudaFuncSetAttribute(k_out,    cudaFuncAttributeMaxDynamicSharedMemorySize, SMEM_OUT);

    k_time<<<1, 128>>>(tp, time_w1, time_b1, time_w2, time_b2, nodein_w1, nodein_b1);
    k_rbf<<<(EE + 255) / 256, 256>>>(x_t, ei);
    k_nodein<<<(NN + 63) / 64, 128, SMEM_NODEIN>>>(x_t, nodein_w1, nodein_w2, nodein_b2);

    const int edgeTiles = EE / 128;          // 5000
    const int preTiles  = (NN + 127) / 128;  // 157
    const int nodeTiles = (NN + 127) / 128;  // 157

    for (int l = 0; l < LL; ++l) {
        const float* W1l = phim_w1 + (size_t)l * 272 * DD;
        k_zero<<<(NN * DD + 255) / 256, 256>>>();
        // Xs = h @ Wa + b1 ; Xd = h @ Wb  (selector resolved in device code)
        k_pre<<<preTiles, 256, SMEM_PRE>>>(W1l,            phim_b1 + (size_t)l * DD, 0);
        k_pre<<<preTiles, 256, SMEM_PRE>>>(W1l + 128 * DD, nullptr,                  1);
        k_edge<<<148, 256, SMEM_EDGE>>>(ei,
                                        W1l + 256 * DD,                    // Wr
                                        phim_w2 + (size_t)l * DD * DD,
                                        phim_b2 + (size_t)l * DD,
                                        edgeTiles);
        k_node<<<148, 512, SMEM_NODE>>>(phih_w1 + (size_t)l * 256 * DD,
                                        phih_b1 + (size_t)l * DD,
                                        phih_w2 + (size_t)l * DD * DD,
                                        phih_b2 + (size_t)l * DD,
                                        nodeTiles);
        k_ln<<<(NN * 32 + 255) / 256, 256>>>(ln_g + (size_t)l * DD, ln_b + (size_t)l * DD);
    }

    k_out<<<NN / 16, 128, SMEM_OUT>>>(out_w1, out_b1, out_w2, out_b2, out);
}

// round 9
// speedup vs baseline: 3.2629x; 1.0017x over previous
#include <cuda_runtime.h>
#include <cuda_bf16.h>
#include <cstdint>

#define NN 20000
#define EE 640000
#define DD 128
#define RR 16
#define LL 3

// ---------------- device scratch ----------------
__device__ float g_h   [(size_t)NN * DD];
__device__ float g_hup [(size_t)NN * DD];
__device__ float g_agg [(size_t)NN * DD];
__device__ float g_rbf [(size_t)EE * RR];
__device__ float g_xs  [(size_t)NN * DD];   // h @ Wa + b1
__device__ float g_xd  [(size_t)NN * DD];   // h @ Wb
__device__ float g_base[DD];

__device__ __forceinline__ float silu_f(float x) {
    return x / (1.0f + __expf(-x));
}

// sm_103a packed fp32 FMA helpers
__device__ __forceinline__ unsigned long long pk2(float lo, float hi) {
    unsigned long long r;
    asm("mov.b64 %0, {%1, %2};" : "=l"(r) : "f"(lo), "f"(hi));
    return r;
}
__device__ __forceinline__ void up2(unsigned long long v, float& lo, float& hi) {
    asm("mov.b64 {%0, %1}, %2;" : "=f"(lo), "=f"(hi) : "l"(v));
}
__device__ __forceinline__ void ffma2(unsigned long long& d, unsigned long long a, unsigned long long b) {
    asm("fma.rn.f32x2 %0, %1, %2, %0;" : "+l"(d) : "l"(a), "l"(b));
}
__device__ __forceinline__ void red_add_v4(float* p, float a, float b, float c, float d) {
    asm volatile("red.global.add.v4.f32 [%0], {%1, %2, %3, %4};"
                 :: "l"(p), "f"(a), "f"(b), "f"(c), "f"(d) : "memory");
}

// ---------------- time embedding + time MLP + nodein te-bias precompute ----------------
__global__ void k_time(const int* __restrict__ tptr,
                       const float* __restrict__ tw1, const float* __restrict__ tb1,
                       const float* __restrict__ tw2, const float* __restrict__ tb2,
                       const float* __restrict__ nw1, const float* __restrict__ nb1) {
    __shared__ float sE[DD], sH[DD], sTe[DD];
    const int j = threadIdx.x;  // 128 threads
    int iv = *tptr;
    float t = (iv >= 0 && iv < 1000000) ? (float)iv : __int_as_float(iv);
    {
        int i = (j < 64) ? j : (j - 64);
        float f = __expf(-logf(10000.0f) * (float)i / 63.0f);
        float a = t * f;
        sE[j] = (j < 64) ? sinf(a) : cosf(a);
    }
    __syncthreads();
    float acc = tb1[j];
    for (int k = 0; k < DD; ++k) acc += sE[k] * tw1[k * DD + j];
    sH[j] = silu_f(acc);
    __syncthreads();
    float acc2 = tb2[j];
    for (int k = 0; k < DD; ++k) acc2 += sH[k] * tw2[k * DD + j];
    sTe[j] = acc2;
    __syncthreads();
    float accb = nb1[j];
    for (int k = 0; k < DD; ++k) accb += sTe[k] * nw1[(3 + k) * DD + j];
    g_base[j] = accb;
}

// ================= shared fast-GEMM core pieces =================
#define ATSTR 132

// out = h @ W (+bias), one 128-node tile. Called from k_prep blocks.
__device__ __forceinline__ void do_pre(const float* __restrict__ W,
                                       const float* __restrict__ bias,
                                       float* __restrict__ out, int tileIdx) {
    extern __shared__ float sm[];
    float* sW  = sm;            // 128*128
    float* sAT = sW + DD * DD;  // 128*ATSTR

    const int tid = threadIdx.x;
    const int tx = tid & 15, ty = tid >> 4;
    const int c0 = tx * 8, r0 = ty * 8;
    const int n0 = tileIdx * 128;

    {
        const float4* w4 = (const float4*)W;
#pragma unroll
        for (int i = 0; i < 16; ++i)
            ((float4*)sW)[tid + i * 256] = w4[tid + i * 256];
    }
#pragma unroll
    for (int i = 0; i < 16; ++i) {
        const int idx = tid + i * 256;
        const int nl = idx >> 5;
        const int q = (idx & 31) * 4;
        int n = n0 + nl; if (n >= NN) n = NN - 1;
        const float4 v = *(const float4*)&g_h[(size_t)n * DD + q];
        const float vv[4] = { v.x, v.y, v.z, v.w };
#pragma unroll
        for (int m = 0; m < 4; ++m) {
            const int k = q + m;
            sAT[k * ATSTR + (nl ^ (((k >> 3) & 7) << 3))] = vv[m];
        }
    }
    __syncthreads();

    unsigned long long acc[8][4];
#pragma unroll
    for (int i = 0; i < 8; ++i)
#pragma unroll
        for (int p = 0; p < 4; ++p) acc[i][p] = 0ull;

    for (int kk = 0; kk < 128; ++kk) {
        const int rs = r0 ^ (((kk >> 3) & 7) << 3);
        const float4 a0 = *(const float4*)&sAT[kk * ATSTR + rs];
        const float4 a1 = *(const float4*)&sAT[kk * ATSTR + rs + 4];
        const ulonglong2 B0 = *(const ulonglong2*)&sW[kk * DD + c0];
        const ulonglong2 B1 = *(const ulonglong2*)&sW[kk * DD + c0 + 4];
        const float a[8] = { a0.x, a0.y, a0.z, a0.w, a1.x, a1.y, a1.z, a1.w };
#pragma unroll
        for (int i = 0; i < 8; ++i) {
            const unsigned long long aa = pk2(a[i], a[i]);
            ffma2(acc[i][0], aa, B0.x);
            ffma2(acc[i][1], aa, B0.y);
            ffma2(acc[i][2], aa, B1.x);
            ffma2(acc[i][3], aa, B1.y);
        }
    }

    float bv[8];
#pragma unroll
    for (int j = 0; j < 8; ++j) bv[j] = bias ? bias[c0 + j] : 0.0f;
#pragma unroll
    for (int i = 0; i < 8; ++i) {
        const int n = n0 + r0 + i;
        if (n < NN) {
            float o[8];
#pragma unroll
            for (int p = 0; p < 4; ++p) {
                float x, y; up2(acc[i][p], x, y);
                o[2 * p] = x + bv[2 * p]; o[2 * p + 1] = y + bv[2 * p + 1];
            }
            *(float4*)&out[(size_t)n * DD + c0]     = make_float4(o[0], o[1], o[2], o[3]);
            *(float4*)&out[(size_t)n * DD + c0 + 4] = make_float4(o[4], o[5], o[6], o[7]);
        }
    }
}

// ================= fused per-layer prologue =================
// blocks [0,157)   : Xs = h@Wa + b1
// blocks [157,314) : Xd = h@Wb
// blocks [314,471) : zero g_agg
// blocks [471,...) : rbf (only when withRbf)
#define PRE_TILES 157
__global__ __launch_bounds__(256, 1)
void k_prep(const float* __restrict__ Wa, const float* __restrict__ Wb,
            const float* __restrict__ b1,
            const int* __restrict__ ei, const float* __restrict__ xt,
            int withRbf) {
    int bx = blockIdx.x;
    if (bx < 2 * PRE_TILES) {
        const int sel = (bx >= PRE_TILES);
        do_pre(sel ? Wb : Wa, sel ? nullptr : b1, sel ? g_xd : g_xs,
               sel ? bx - PRE_TILES : bx);
        return;
    }
    bx -= 2 * PRE_TILES;
    if (bx < 157) {
        // zero g_agg: 157 blocks x 16384 floats
        const int base = bx * 16384 + threadIdx.x * 4;
#pragma unroll
        for (int k = 0; k < 16; ++k) {
            const int i = base + k * 1024;
            if (i < NN * DD) *(float4*)&g_agg[i] = make_float4(0.f, 0.f, 0.f, 0.f);
        }
        return;
    }
    bx -= 157;
    // rbf: 625 blocks x 1024 edges
#pragma unroll
    for (int k = 0; k < 4; ++k) {
        const int e = bx * 1024 + k * 256 + threadIdx.x;
        if (e < EE) {
            const int s = ei[e], d = ei[EE + e];
            const float dx = xt[s * 3 + 0] - xt[d * 3 + 0];
            const float dy = xt[s * 3 + 1] - xt[d * 3 + 1];
            const float r = sqrtf(dx * dx + dy * dy + 1e-8f);
            const float step = 1.41421356237309515f / 15.0f;
            const float gamma = 1.0f / (2.0f * step * step);
#pragma unroll
            for (int c = 0; c < RR; ++c) {
                float u = r - (float)c * step;
                g_rbf[(size_t)e * RR + c] = __expf(-gamma * u * u);
            }
        }
    }
}

// ================= node input MLP (fast GEMM form) =================
__global__ __launch_bounds__(256, 1)
void k_nin(const float* __restrict__ xt,
           const float* __restrict__ w1,   // [131][128]
           const float* __restrict__ w2,   // [128][128]
           const float* __restrict__ b2) {
    extern __shared__ float sm[];
    float* sW    = sm;                      // 128*128
    float* sAT   = sW + DD * DD;            // 128*ATSTR
    float* sW1x  = sAT + 128 * ATSTR;       // 3*128
    float* sBase = sW1x + 3 * DD;           // 128

    const int tid = threadIdx.x;
    const int tx = tid & 15, ty = tid >> 4;
    const int c0 = tx * 8, r0 = ty * 8;
    const int n0 = blockIdx.x * 128;

    {
        const float4* w4 = (const float4*)w2;
#pragma unroll
        for (int i = 0; i < 16; ++i)
            ((float4*)sW)[tid + i * 256] = w4[tid + i * 256];
    }
    if (tid < 128) {
        sW1x[tid]            = w1[tid];
        sW1x[128 + tid]      = w1[128 + tid];
        sW1x[256 + tid]      = w1[256 + tid];
        sBase[tid]           = g_base[tid];
    }
    __syncthreads();

    // hidden = silu(base + x @ W1x), stored transposed+swizzled
#pragma unroll
    for (int i = 0; i < 16; ++i) {
        const int idx = tid + i * 256;
        const int nl = idx >> 5;
        const int q = (idx & 31) * 4;
        int n = n0 + nl; if (n >= NN) n = NN - 1;
        const float x0 = xt[n * 3 + 0], x1 = xt[n * 3 + 1], x2 = xt[n * 3 + 2];
#pragma unroll
        for (int m = 0; m < 4; ++m) {
            const int k = q + m;
            const float v = silu_f(sBase[k] + x0 * sW1x[k] + x1 * sW1x[128 + k] + x2 * sW1x[256 + k]);
            sAT[k * ATSTR + (nl ^ (((k >> 3) & 7) << 3))] = v;
        }
    }
    __syncthreads();

    unsigned long long acc[8][4];
#pragma unroll
    for (int i = 0; i < 8; ++i)
#pragma unroll
        for (int p = 0; p < 4; ++p) acc[i][p] = 0ull;

    for (int kk = 0; kk < 128; ++kk) {
        const int rs = r0 ^ (((kk >> 3) & 7) << 3);
        const float4 a0 = *(const float4*)&sAT[kk * ATSTR + rs];
        const float4 a1 = *(const float4*)&sAT[kk * ATSTR + rs + 4];
        const ulonglong2 B0 = *(const ulonglong2*)&sW[kk * DD + c0];
        const ulonglong2 B1 = *(const ulonglong2*)&sW[kk * DD + c0 + 4];
        const float a[8] = { a0.x, a0.y, a0.z, a0.w, a1.x, a1.y, a1.z, a1.w };
#pragma unroll
        for (int i = 0; i < 8; ++i) {
            const unsigned long long aa = pk2(a[i], a[i]);
            ffma2(acc[i][0], aa, B0.x);
            ffma2(acc[i][1], aa, B0.y);
            ffma2(acc[i][2], aa, B1.x);
            ffma2(acc[i][3], aa, B1.y);
        }
    }

    float bv[8];
#pragma unroll
    for (int j = 0; j < 8; ++j) bv[j] = b2[c0 + j];
#pragma unroll
    for (int i = 0; i < 8; ++i) {
        const int n = n0 + r0 + i;
        if (n < NN) {
            float o[8];
#pragma unroll
            for (int p = 0; p < 4; ++p) {
                float x, y; up2(acc[i][p], x, y);
                o[2 * p] = x + bv[2 * p]; o[2 * p + 1] = y + bv[2 * p + 1];
            }
            *(float4*)&g_h[(size_t)n * DD + c0]     = make_float4(o[0], o[1], o[2], o[3]);
            *(float4*)&g_h[(size_t)n * DD + c0 + 4] = make_float4(o[4], o[5], o[6], o[7]);
        }
    }
}

// ================= fused edge kernel v2: 64-edge tiles, 2 CTAs/SM =================
#define ESTR 68
__global__ __launch_bounds__(256, 2)
void k_edge(const int* __restrict__ ei,
            const float* __restrict__ Wr,   // [16][128]
            const float* __restrict__ w2,   // [128][128]
            const float* __restrict__ b2,
            int numTiles) {
    extern __shared__ float sm[];
    float* sW2   = sm;                        // 128*128
    float* sWr   = sW2 + DD * DD;             // 16*128
    float* sHidT = sWr + RR * DD;             // 128*ESTR (transposed, swizzled)
    float* sRbfT = sHidT + 128 * ESTR;        // 16*ESTR
    int*   sSrc  = (int*)(sRbfT + RR * ESTR); // 64
    int*   sDst  = sSrc + 64;                 // 64

    const int tid = threadIdx.x;
    const int tx = tid & 15, ty = tid >> 4;
    const int c0 = tx * 8, r0 = ty * 4;

    {
        const float4* w4 = (const float4*)w2;
#pragma unroll
        for (int i = 0; i < 16; ++i)
            ((float4*)sW2)[tid + i * 256] = w4[tid + i * 256];
        const float4* wr4 = (const float4*)Wr;
#pragma unroll
        for (int i = 0; i < 2; ++i)
            ((float4*)sWr)[tid + i * 256] = wr4[tid + i * 256];
    }
    float bias2[8];
#pragma unroll
    for (int j = 0; j < 8; ++j) bias2[j] = b2[c0 + j];

    for (int tile = blockIdx.x; tile < numTiles; tile += gridDim.x) {
        const int e0 = tile * 64;
        __syncthreads();  // protect smem from previous tile's readers
        if (tid < 64)       sSrc[tid]      = ei[e0 + tid];
        else if (tid < 128) sDst[tid - 64] = ei[EE + e0 + tid - 64];
        {
            const int row = tid & 63, c4 = (tid >> 6) * 4;
            const float4 v = *(const float4*)&g_rbf[(size_t)(e0 + row) * RR + c4];
            sRbfT[(c4 + 0) * ESTR + row] = v.x;
            sRbfT[(c4 + 1) * ESTR + row] = v.y;
            sRbfT[(c4 + 2) * ESTR + row] = v.z;
            sRbfT[(c4 + 3) * ESTR + row] = v.w;
        }
        __syncthreads();

        // gather Xs[src]+Xd[dst] for this thread's 4 rows x 8 cols into regs
        float xsv[4][8];
#pragma unroll
        for (int i = 0; i < 4; ++i) {
            const int s = sSrc[r0 + i], d = sDst[r0 + i];
            const float4 a0 = *(const float4*)&g_xs[(size_t)s * DD + c0];
            const float4 a1 = *(const float4*)&g_xs[(size_t)s * DD + c0 + 4];
            const float4 b0 = *(const float4*)&g_xd[(size_t)d * DD + c0];
            const float4 b1 = *(const float4*)&g_xd[(size_t)d * DD + c0 + 4];
            xsv[i][0] = a0.x + b0.x; xsv[i][1] = a0.y + b0.y;
            xsv[i][2] = a0.z + b0.z; xsv[i][3] = a0.w + b0.w;
            xsv[i][4] = a1.x + b1.x; xsv[i][5] = a1.y + b1.y;
            xsv[i][6] = a1.z + b1.z; xsv[i][7] = a1.w + b1.w;
        }

        // phase 1: K=16 rbf GEMM
        unsigned long long acc[4][4];
#pragma unroll
        for (int i = 0; i < 4; ++i)
#pragma unroll
            for (int p = 0; p < 4; ++p) acc[i][p] = 0ull;
#pragma unroll
        for (int kk = 0; kk < 16; ++kk) {
            const float4 av = *(const float4*)&sRbfT[kk * ESTR + r0];  // rows r0..r0+3
            const ulonglong2 B0 = *(const ulonglong2*)&sWr[kk * DD + c0];
            const ulonglong2 B1 = *(const ulonglong2*)&sWr[kk * DD + c0 + 4];
            const float a[4] = { av.x, av.y, av.z, av.w };
#pragma unroll
            for (int i = 0; i < 4; ++i) {
                const unsigned long long aa = pk2(a[i], a[i]);
                ffma2(acc[i][0], aa, B0.x);
                ffma2(acc[i][1], aa, B0.y);
                ffma2(acc[i][2], aa, B1.x);
                ffma2(acc[i][3], aa, B1.y);
            }
        }

        // epilogue 1: silu(acc + xsv) -> sHidT (transposed, XOR-swizzled rows)
        {
            float o[4][8];
#pragma unroll
            for (int i = 0; i < 4; ++i) {
                float x, y;
                up2(acc[i][0], x, y); o[i][0] = silu_f(x + xsv[i][0]); o[i][1] = silu_f(y + xsv[i][1]);
                up2(acc[i][1], x, y); o[i][2] = silu_f(x + xsv[i][2]); o[i][3] = silu_f(y + xsv[i][3]);
                up2(acc[i][2], x, y); o[i][4] = silu_f(x + xsv[i][4]); o[i][5] = silu_f(y + xsv[i][5]);
                up2(acc[i][3], x, y); o[i][6] = silu_f(x + xsv[i][6]); o[i][7] = silu_f(y + xsv[i][7]);
#pragma unroll
                for (int p = 0; p < 4; ++p) acc[i][p] = 0ull;
            }
            const int rs0 = r0 ^ ((tx & 7) << 3);  // ((c0+jj)>>3)&7 == tx&7 for jj<8
#pragma unroll
            for (int jj = 0; jj < 8; ++jj) {
                *(float4*)&sHidT[(c0 + jj) * ESTR + rs0] =
                    make_float4(o[0][jj], o[1][jj], o[2][jj], o[3][jj]);
            }
        }
        __syncthreads();

        // phase 2: K=128 GEMM2 (A broadcast from HidT, B resident W2)
        for (int kk = 0; kk < 128; ++kk) {
            const int rs = r0 ^ (((kk >> 3) & 7) << 3);
            const float4 av = *(const float4*)&sHidT[kk * ESTR + rs];
            const ulonglong2 B0 = *(const ulonglong2*)&sW2[kk * DD + c0];
            const ulonglong2 B1 = *(const ulonglong2*)&sW2[kk * DD + c0 + 4];
            const float a[4] = { av.x, av.y, av.z, av.w };
#pragma unroll
            for (int i = 0; i < 4; ++i) {
                const unsigned long long aa = pk2(a[i], a[i]);
                ffma2(acc[i][0], aa, B0.x);
                ffma2(acc[i][1], aa, B0.y);
                ffma2(acc[i][2], aa, B1.x);
                ffma2(acc[i][3], aa, B1.y);
            }
        }

        // epilogue 2: bias + vectorized reduction scatter
#pragma unroll
        for (int i = 0; i < 4; ++i) {
            float* dp = &g_agg[(size_t)sDst[r0 + i] * DD + c0];
            float x0, y0, x1, y1;
            up2(acc[i][0], x0, y0); up2(acc[i][1], x1, y1);
            red_add_v4(dp, x0 + bias2[0], y0 + bias2[1], x1 + bias2[2], y1 + bias2[3]);
            up2(acc[i][2], x0, y0); up2(acc[i][3], x1, y1);
            red_add_v4(dp + 4, x0 + bias2[4], y0 + bias2[5], x1 + bias2[6], y1 + bias2[7]);
        }
    }
}

// ================= node update MLP (concat(h,agg)) + residual -> g_hup =================
#define NHSTR 132
__global__ __launch_bounds__(512, 1)
void k_node(const float* __restrict__ w1, const float* __restrict__ b1,
            const float* __restrict__ w2, const float* __restrict__ b2,
            int numTiles) {
    extern __shared__ float sm[];
    float* sW1  = sm;                           // 256*128
    float* sHid = sW1 + 256 * DD;               // 128*NHSTR
    float* sA0  = sHid + 128 * NHSTR;           // 128*16
    float* sA1  = sA0 + 128 * 16;               // 128*16

    const int tid = threadIdx.x;
    const int c0 = (tid & 15) * 8;
    const int r0 = (tid >> 4) * 4;
    const int gr = tid >> 2;
    const int gq = (tid & 3) * 4;

    for (int i = tid; i < 256 * DD; i += 512) sW1[i] = w1[i];
    float bias1[8], bias2[8];
#pragma unroll
    for (int j = 0; j < 8; ++j) { bias1[j] = b1[c0 + j]; bias2[j] = b2[c0 + j]; }

    float* bufs[2] = { sA0, sA1 };

    for (int tile = blockIdx.x; tile < numTiles; tile += gridDim.x) {
        const int n0 = tile * 128;
        int gn = n0 + gr; if (gn >= NN) gn = NN - 1;
        unsigned long long acc[4][4];
#pragma unroll
        for (int i = 0; i < 4; ++i)
#pragma unroll
            for (int p = 0; p < 4; ++p) acc[i][p] = 0ull;
        __syncthreads();

        {
            float4 v = *(const float4*)&g_h[(size_t)gn * DD + gq];
            *(float4*)&bufs[0][gr * 16 + gq] = v;
        }
        __syncthreads();

        for (int kc = 0; kc < 16; ++kc) {
            float4 nv;
            if (kc < 15) {
                const int k = (kc + 1) * 16 + gq;
                if (k < 128) nv = *(const float4*)&g_h[(size_t)gn * DD + k];
                else         nv = *(const float4*)&g_agg[(size_t)gn * DD + (k - 128)];
            }
            const float* A = bufs[kc & 1];
            const int kbase = kc * 16;
#pragma unroll
            for (int kk = 0; kk < 16; ++kk) {
                const float* wrow = &sW1[(kbase + kk) * DD + c0];
                const ulonglong2 B0 = *(const ulonglong2*)wrow;
                const ulonglong2 B1 = *(const ulonglong2*)(wrow + 4);
#pragma unroll
                for (int i = 0; i < 4; ++i) {
                    const float a = A[(r0 + i) * 16 + kk];
                    const unsigned long long aa = pk2(a, a);
                    ffma2(acc[i][0], aa, B0.x);
                    ffma2(acc[i][1], aa, B0.y);
                    ffma2(acc[i][2], aa, B1.x);
                    ffma2(acc[i][3], aa, B1.y);
                }
            }
            if (kc < 15) *(float4*)&bufs[(kc + 1) & 1][gr * 16 + gq] = nv;
            __syncthreads();
        }

        {
            float4 w2v = *(const float4*)&w2[tid * 4];
#pragma unroll
            for (int i = 0; i < 4; ++i) {
                float* hrow = &sHid[(r0 + i) * NHSTR + c0];
                float o[8];
#pragma unroll
                for (int p = 0; p < 4; ++p) {
                    float x, y; up2(acc[i][p], x, y);
                    o[2 * p]     = silu_f(x + bias1[2 * p]);
                    o[2 * p + 1] = silu_f(y + bias1[2 * p + 1]);
                    acc[i][p] = 0ull;
                }
                *(float4*)&hrow[0] = make_float4(o[0], o[1], o[2], o[3]);
                *(float4*)&hrow[4] = make_float4(o[4], o[5], o[6], o[7]);
            }
            *(float4*)&bufs[0][tid * 4] = w2v;
        }
        __syncthreads();

        for (int kc = 0; kc < 8; ++kc) {
            float4 nv;
            if (kc < 7) nv = *(const float4*)&w2[(size_t)(kc + 1) * 16 * DD + tid * 4];
            const float* Bc = bufs[kc & 1];
            const int kbase = kc * 16;
#pragma unroll
            for (int kk = 0; kk < 16; ++kk) {
                const float* wrow = &Bc[kk * DD + c0];
                const ulonglong2 B0 = *(const ulonglong2*)wrow;
                const ulonglong2 B1 = *(const ulonglong2*)(wrow + 4);
#pragma unroll
                for (int i = 0; i < 4; ++i) {
                    const float a = sHid[(r0 + i) * NHSTR + kbase + kk];
                    const unsigned long long aa = pk2(a, a);
                    ffma2(acc[i][0], aa, B0.x);
                    ffma2(acc[i][1], aa, B0.y);
                    ffma2(acc[i][2], aa, B1.x);
                    ffma2(acc[i][3], aa, B1.y);
                }
            }
            if (kc < 7) *(float4*)&bufs[(kc + 1) & 1][tid * 4] = nv;
            __syncthreads();
        }

#pragma unroll
        for (int i = 0; i < 4; ++i) {
            const int n = n0 + r0 + i;
            if (n < NN) {
                const float4 h0 = *(const float4*)&g_h[(size_t)n * DD + c0];
                const float4 h1 = *(const float4*)&g_h[(size_t)n * DD + c0 + 4];
                float o[8];
#pragma unroll
                for (int p = 0; p < 4; ++p) {
                    float x, y; up2(acc[i][p], x, y);
                    o[2 * p]     = x + bias2[2 * p];
                    o[2 * p + 1] = y + bias2[2 * p + 1];
                }
                *(float4*)&g_hup[(size_t)n * DD + c0] =
                    make_float4(o[0] + h0.x, o[1] + h0.y, o[2] + h0.z, o[3] + h0.w);
                *(float4*)&g_hup[(size_t)n * DD + c0 + 4] =
                    make_float4(o[4] + h1.x, o[5] + h1.y, o[6] + h1.z, o[7] + h1.w);
            }
        }
    }
}

// ---------------- LayerNorm: g_h = LN(g_hup) ----------------
__global__ void k_ln(const float* __restrict__ g, const float* __restrict__ b) {
    const int gl = blockIdx.x * blockDim.x + threadIdx.x;
    const int node = gl >> 5;
    const int lane = gl & 31;
    if (node >= NN) return;
    const float4 v = ((const float4*)(g_hup + (size_t)node * DD))[lane];
    float s = v.x + v.y + v.z + v.w;
#pragma unroll
    for (int o = 16; o; o >>= 1) s += __shfl_xor_sync(0xFFFFFFFFu, s, o);
    const float mu = s * (1.0f / 128.0f);
    const float d0 = v.x - mu, d1 = v.y - mu, d2 = v.z - mu, d3 = v.w - mu;
    float q = d0 * d0 + d1 * d1 + d2 * d2 + d3 * d3;
#pragma unroll
    for (int o = 16; o; o >>= 1) q += __shfl_xor_sync(0xFFFFFFFFu, q, o);
    const float inv = rsqrtf(q * (1.0f / 128.0f) + 1e-5f);
    const float4 gg = ((const float4*)g)[lane];
    const float4 bb = ((const float4*)b)[lane];
    float4 o4;
    o4.x = d0 * inv * gg.x + bb.x;
    o4.y = d1 * inv * gg.y + bb.y;
    o4.z = d2 * inv * gg.z + bb.z;
    o4.w = d3 * inv * gg.w + bb.w;
    ((float4*)(g_h + (size_t)node * DD))[lane] = o4;
}

// ---------------- output MLP ----------------
__global__ void k_out(const float* __restrict__ w1, const float* __restrict__ b1,
                      const float* __restrict__ w2, const float* __restrict__ b2,
                      float* __restrict__ out) {
    extern __shared__ float sm[];
    float* sW1  = sm;
    float* sW2  = sW1 + DD * DD;
    float* sX   = sW2 + DD * 3;
    float* sHid = sX + DD;
    const int j = threadIdx.x;  // 128
    for (int i = j; i < DD * DD; i += DD) sW1[i] = w1[i];
    for (int i = j; i < DD * 3; i += DD) sW2[i] = w2[i];
    const float bb1 = b1[j];
    __syncthreads();
    const int n0 = blockIdx.x * 16;
    for (int m = 0; m < 16; ++m) {
        const int n = n0 + m;
        sX[j] = g_h[(size_t)n * DD + j];
        __syncthreads();
        float acc = bb1;
#pragma unroll 8
        for (int k = 0; k < DD; ++k) acc += sX[k] * sW1[k * DD + j];
        sHid[j] = silu_f(acc);
        __syncthreads();
        if (j < 3) {
            float o = b2[j];
            for (int k = 0; k < DD; ++k) o += sHid[k] * sW2[k * 3 + j];
            out[(size_t)n * 3 + j] = o;
        }
        __syncthreads();
    }
}

// ---------------- launch ----------------
extern "C" void kernel_launch(void* const* d_in, const int* in_sizes, int n_in,
                              void* d_out, int out_size) {
    const float* x_t      = (const float*)d_in[0];
    const int*   ei       = (const int*)d_in[1];
    const int*   tp       = (const int*)d_in[2];
    const float* time_w1  = (const float*)d_in[3];
    const float* time_b1  = (const float*)d_in[4];
    const float* time_w2  = (const float*)d_in[5];
    const float* time_b2  = (const float*)d_in[6];
    const float* nodein_w1= (const float*)d_in[7];
    const float* nodein_b1= (const float*)d_in[8];
    const float* nodein_w2= (const float*)d_in[9];
    const float* nodein_b2= (const float*)d_in[10];
    const float* phim_w1  = (const float*)d_in[11];
    const float* phim_b1  = (const float*)d_in[12];
    const float* phim_w2  = (const float*)d_in[13];
    const float* phim_b2  = (const float*)d_in[14];
    const float* phih_w1  = (const float*)d_in[15];
    const float* phih_b1  = (const float*)d_in[16];
    const float* phih_w2  = (const float*)d_in[17];
    const float* phih_b2  = (const float*)d_in[18];
    const float* ln_g     = (const float*)d_in[19];
    const float* ln_b     = (const float*)d_in[20];
    const float* out_w1   = (const float*)d_in[21];
    const float* out_b1   = (const float*)d_in[22];
    const float* out_w2   = (const float*)d_in[23];
    const float* out_b2   = (const float*)d_in[24];
    float* out = (float*)d_out;

    const int SMEM_EDGE = (DD * DD + RR * DD + 128 * ESTR + RR * ESTR) * 4 + 128 * 4;
    const int SMEM_PRE  = (DD * DD + 128 * ATSTR) * 4;
    const int SMEM_NIN  = (DD * DD + 128 * ATSTR + 3 * DD + DD) * 4;
    const int SMEM_NODE = (256 * DD + 128 * NHSTR + 2 * 128 * 16) * 4;
    const int SMEM_OUT  = (DD * DD + DD * 3 + DD + DD) * 4;

    cudaFuncSetAttribute(k_edge, cudaFuncAttributeMaxDynamicSharedMemorySize, SMEM_EDGE);
    cudaFuncSetAttribute(k_prep, cudaFuncAttributeMaxDynamicSharedMemorySize, SMEM_PRE);
    cudaFuncSetAttribute(k_nin,  cudaFuncAttributeMaxDynamicSharedMemorySize, SMEM_NIN);
    cudaFuncSetAttribute(k_node, cudaFuncAttributeMaxDynamicSharedMemorySize, SMEM_NODE);
    cudaFuncSetAttribute(k_out,  cudaFuncAttributeMaxDynamicSharedMemorySize, SMEM_OUT);

    const int edgeTiles = EE / 64;           // 10000
    const int nodeTiles = (NN + 127) / 128;  // 157

    // launch 0
    k_time<<<1, 128>>>(tp, time_w1, time_b1, time_w2, time_b2, nodein_w1, nodein_b1);
    // launch 1
    k_nin<<<PRE_TILES, 256, SMEM_NIN>>>(x_t, nodein_w1, nodein_w2, nodein_b2);

    for (int l = 0; l < LL; ++l) {
        const float* W1l = phim_w1 + (size_t)l * 272 * DD;
        const int withRbf = (l == 0);
        const int prepGrid = 2 * PRE_TILES + 157 + (withRbf ? 625 : 0);
        // launch 2 (l==0)
        k_prep<<<prepGrid, 256, SMEM_PRE>>>(W1l, W1l + 128 * DD,
                                            phim_b1 + (size_t)l * DD, ei, x_t, withRbf);
        // launch 3 (l==0) -> ncu capture target
        k_edge<<<296, 256, SMEM_EDGE>>>(ei,
                                        W1l + 256 * DD,
                                        phim_w2 + (size_t)l * DD * DD,
                                        phim_b2 + (size_t)l * DD,
                                        edgeTiles);
        k_node<<<148, 512, SMEM_NODE>>>(phih_w1 + (size_t)l * 256 * DD,
                                        phih_b1 + (size_t)l * DD,
                                        phih_w2 + (size_t)l * DD * DD,
                                        phih_b2 + (size_t)l * DD,
                                        nodeTiles);
        k_ln<<<(NN * 32 + 255) / 256, 256>>>(ln_g + (size_t)l * DD, ln_b + (size_t)l * DD);
    }

    k_out<<<NN / 16, 128, SMEM_OUT>>>(out_w1, out_b1, out_w2, out_b2, out);
}

// round 10
// speedup vs baseline: 4.0722x; 1.2480x over previous
#include <cuda_runtime.h>
#include <cuda_bf16.h>
#include <cstdint>

#define NN 20000
#define EE 640000
#define DD 128
#define RR 16
#define LL 3

// ---------------- device scratch ----------------
__device__ float g_h   [(size_t)NN * DD];
__device__ float g_hup [(size_t)NN * DD];
__device__ float g_agg [(size_t)NN * DD];
__device__ float g_rbf [(size_t)EE * RR];
__device__ float g_xs  [(size_t)NN * DD];   // h @ Wa + b1
__device__ float g_xd  [(size_t)NN * DD];   // h @ Wb
__device__ float g_base[DD];

__device__ __forceinline__ float silu_f(float x) {
    return x / (1.0f + __expf(-x));
}

// sm_103a packed fp32 FMA helpers
__device__ __forceinline__ unsigned long long pk2(float lo, float hi) {
    unsigned long long r;
    asm("mov.b64 %0, {%1, %2};" : "=l"(r) : "f"(lo), "f"(hi));
    return r;
}
__device__ __forceinline__ void up2(unsigned long long v, float& lo, float& hi) {
    asm("mov.b64 {%0, %1}, %2;" : "=f"(lo), "=f"(hi) : "l"(v));
}
__device__ __forceinline__ void ffma2(unsigned long long& d, unsigned long long a, unsigned long long b) {
    asm("fma.rn.f32x2 %0, %1, %2, %0;" : "+l"(d) : "l"(a), "l"(b));
}
__device__ __forceinline__ void red_add_v4(float* p, float a, float b, float c, float d) {
    asm volatile("red.global.add.v4.f32 [%0], {%1, %2, %3, %4};"
                 :: "l"(p), "f"(a), "f"(b), "f"(c), "f"(d) : "memory");
}

// ---------------- time embedding + time MLP + nodein te-bias precompute ----------------
__global__ void k_time(const int* __restrict__ tptr,
                       const float* __restrict__ tw1, const float* __restrict__ tb1,
                       const float* __restrict__ tw2, const float* __restrict__ tb2,
                       const float* __restrict__ nw1, const float* __restrict__ nb1) {
    __shared__ float sE[DD], sH[DD], sTe[DD];
    const int j = threadIdx.x;  // 128 threads
    int iv = *tptr;
    float t = (iv >= 0 && iv < 1000000) ? (float)iv : __int_as_float(iv);
    {
        int i = (j < 64) ? j : (j - 64);
        float f = __expf(-logf(10000.0f) * (float)i / 63.0f);
        float a = t * f;
        sE[j] = (j < 64) ? sinf(a) : cosf(a);
    }
    __syncthreads();
    float acc = tb1[j];
    for (int k = 0; k < DD; ++k) acc += sE[k] * tw1[k * DD + j];
    sH[j] = silu_f(acc);
    __syncthreads();
    float acc2 = tb2[j];
    for (int k = 0; k < DD; ++k) acc2 += sH[k] * tw2[k * DD + j];
    sTe[j] = acc2;
    __syncthreads();
    float accb = nb1[j];
    for (int k = 0; k < DD; ++k) accb += sTe[k] * nw1[(3 + k) * DD + j];
    g_base[j] = accb;
}

// ================= shared fast-GEMM core pieces =================
#define ATSTR 132

// out = h @ W (+bias), one 128-node tile. Called from k_prep blocks.
__device__ __forceinline__ void do_pre(const float* __restrict__ W,
                                       const float* __restrict__ bias,
                                       float* __restrict__ out, int tileIdx) {
    extern __shared__ float sm[];
    float* sW  = sm;            // 128*128
    float* sAT = sW + DD * DD;  // 128*ATSTR

    const int tid = threadIdx.x;
    const int tx = tid & 15, ty = tid >> 4;
    const int c0 = tx * 8, r0 = ty * 8;
    const int n0 = tileIdx * 128;

    {
        const float4* w4 = (const float4*)W;
#pragma unroll
        for (int i = 0; i < 16; ++i)
            ((float4*)sW)[tid + i * 256] = w4[tid + i * 256];
    }
#pragma unroll
    for (int i = 0; i < 16; ++i) {
        const int idx = tid + i * 256;
        const int nl = idx >> 5;
        const int q = (idx & 31) * 4;
        int n = n0 + nl; if (n >= NN) n = NN - 1;
        const float4 v = *(const float4*)&g_h[(size_t)n * DD + q];
        const float vv[4] = { v.x, v.y, v.z, v.w };
#pragma unroll
        for (int m = 0; m < 4; ++m) {
            const int k = q + m;
            sAT[k * ATSTR + (nl ^ (((k >> 3) & 7) << 3))] = vv[m];
        }
    }
    __syncthreads();

    unsigned long long acc[8][4];
#pragma unroll
    for (int i = 0; i < 8; ++i)
#pragma unroll
        for (int p = 0; p < 4; ++p) acc[i][p] = 0ull;

    for (int kk = 0; kk < 128; ++kk) {
        const int rs = r0 ^ (((kk >> 3) & 7) << 3);
        const float4 a0 = *(const float4*)&sAT[kk * ATSTR + rs];
        const float4 a1 = *(const float4*)&sAT[kk * ATSTR + rs + 4];
        const ulonglong2 B0 = *(const ulonglong2*)&sW[kk * DD + c0];
        const ulonglong2 B1 = *(const ulonglong2*)&sW[kk * DD + c0 + 4];
        const float a[8] = { a0.x, a0.y, a0.z, a0.w, a1.x, a1.y, a1.z, a1.w };
#pragma unroll
        for (int i = 0; i < 8; ++i) {
            const unsigned long long aa = pk2(a[i], a[i]);
            ffma2(acc[i][0], aa, B0.x);
            ffma2(acc[i][1], aa, B0.y);
            ffma2(acc[i][2], aa, B1.x);
            ffma2(acc[i][3], aa, B1.y);
        }
    }

    float bv[8];
#pragma unroll
    for (int j = 0; j < 8; ++j) bv[j] = bias ? bias[c0 + j] : 0.0f;
#pragma unroll
    for (int i = 0; i < 8; ++i) {
        const int n = n0 + r0 + i;
        if (n < NN) {
            float o[8];
#pragma unroll
            for (int p = 0; p < 4; ++p) {
                float x, y; up2(acc[i][p], x, y);
                o[2 * p] = x + bv[2 * p]; o[2 * p + 1] = y + bv[2 * p + 1];
            }
            *(float4*)&out[(size_t)n * DD + c0]     = make_float4(o[0], o[1], o[2], o[3]);
            *(float4*)&out[(size_t)n * DD + c0 + 4] = make_float4(o[4], o[5], o[6], o[7]);
        }
    }
}

// ================= fused per-layer prologue =================
#define PRE_TILES 157
__global__ __launch_bounds__(256, 1)
void k_prep(const float* __restrict__ Wa, const float* __restrict__ Wb,
            const float* __restrict__ b1,
            const int* __restrict__ ei, const float* __restrict__ xt,
            int withRbf) {
    int bx = blockIdx.x;
    if (bx < 2 * PRE_TILES) {
        const int sel = (bx >= PRE_TILES);
        do_pre(sel ? Wb : Wa, sel ? nullptr : b1, sel ? g_xd : g_xs,
               sel ? bx - PRE_TILES : bx);
        return;
    }
    bx -= 2 * PRE_TILES;
    if (bx < 157) {
        const int base = bx * 16384 + threadIdx.x * 4;
#pragma unroll
        for (int k = 0; k < 16; ++k) {
            const int i = base + k * 1024;
            if (i < NN * DD) *(float4*)&g_agg[i] = make_float4(0.f, 0.f, 0.f, 0.f);
        }
        return;
    }
    bx -= 157;
#pragma unroll
    for (int k = 0; k < 4; ++k) {
        const int e = bx * 1024 + k * 256 + threadIdx.x;
        if (e < EE) {
            const int s = ei[e], d = ei[EE + e];
            const float dx = xt[s * 3 + 0] - xt[d * 3 + 0];
            const float dy = xt[s * 3 + 1] - xt[d * 3 + 1];
            const float r = sqrtf(dx * dx + dy * dy + 1e-8f);
            const float step = 1.41421356237309515f / 15.0f;
            const float gamma = 1.0f / (2.0f * step * step);
#pragma unroll
            for (int c = 0; c < RR; ++c) {
                float u = r - (float)c * step;
                g_rbf[(size_t)e * RR + c] = __expf(-gamma * u * u);
            }
        }
    }
}

// ================= node input MLP (fast GEMM form) =================
__global__ __launch_bounds__(256, 1)
void k_nin(const float* __restrict__ xt,
           const float* __restrict__ w1,   // [131][128]
           const float* __restrict__ w2,   // [128][128]
           const float* __restrict__ b2) {
    extern __shared__ float sm[];
    float* sW    = sm;                      // 128*128
    float* sAT   = sW + DD * DD;            // 128*ATSTR
    float* sW1x  = sAT + 128 * ATSTR;       // 3*128
    float* sBase = sW1x + 3 * DD;           // 128

    const int tid = threadIdx.x;
    const int tx = tid & 15, ty = tid >> 4;
    const int c0 = tx * 8, r0 = ty * 8;
    const int n0 = blockIdx.x * 128;

    {
        const float4* w4 = (const float4*)w2;
#pragma unroll
        for (int i = 0; i < 16; ++i)
            ((float4*)sW)[tid + i * 256] = w4[tid + i * 256];
    }
    if (tid < 128) {
        sW1x[tid]            = w1[tid];
        sW1x[128 + tid]      = w1[128 + tid];
        sW1x[256 + tid]      = w1[256 + tid];
        sBase[tid]           = g_base[tid];
    }
    __syncthreads();

#pragma unroll
    for (int i = 0; i < 16; ++i) {
        const int idx = tid + i * 256;
        const int nl = idx >> 5;
        const int q = (idx & 31) * 4;
        int n = n0 + nl; if (n >= NN) n = NN - 1;
        const float x0 = xt[n * 3 + 0], x1 = xt[n * 3 + 1], x2 = xt[n * 3 + 2];
#pragma unroll
        for (int m = 0; m < 4; ++m) {
            const int k = q + m;
            const float v = silu_f(sBase[k] + x0 * sW1x[k] + x1 * sW1x[128 + k] + x2 * sW1x[256 + k]);
            sAT[k * ATSTR + (nl ^ (((k >> 3) & 7) << 3))] = v;
        }
    }
    __syncthreads();

    unsigned long long acc[8][4];
#pragma unroll
    for (int i = 0; i < 8; ++i)
#pragma unroll
        for (int p = 0; p < 4; ++p) acc[i][p] = 0ull;

    for (int kk = 0; kk < 128; ++kk) {
        const int rs = r0 ^ (((kk >> 3) & 7) << 3);
        const float4 a0 = *(const float4*)&sAT[kk * ATSTR + rs];
        const float4 a1 = *(const float4*)&sAT[kk * ATSTR + rs + 4];
        const ulonglong2 B0 = *(const ulonglong2*)&sW[kk * DD + c0];
        const ulonglong2 B1 = *(const ulonglong2*)&sW[kk * DD + c0 + 4];
        const float a[8] = { a0.x, a0.y, a0.z, a0.w, a1.x, a1.y, a1.z, a1.w };
#pragma unroll
        for (int i = 0; i < 8; ++i) {
            const unsigned long long aa = pk2(a[i], a[i]);
            ffma2(acc[i][0], aa, B0.x);
            ffma2(acc[i][1], aa, B0.y);
            ffma2(acc[i][2], aa, B1.x);
            ffma2(acc[i][3], aa, B1.y);
        }
    }

    float bv[8];
#pragma unroll
    for (int j = 0; j < 8; ++j) bv[j] = b2[c0 + j];
#pragma unroll
    for (int i = 0; i < 8; ++i) {
        const int n = n0 + r0 + i;
        if (n < NN) {
            float o[8];
#pragma unroll
            for (int p = 0; p < 4; ++p) {
                float x, y; up2(acc[i][p], x, y);
                o[2 * p] = x + bv[2 * p]; o[2 * p + 1] = y + bv[2 * p + 1];
            }
            *(float4*)&g_h[(size_t)n * DD + c0]     = make_float4(o[0], o[1], o[2], o[3]);
            *(float4*)&g_h[(size_t)n * DD + c0 + 4] = make_float4(o[4], o[5], o[6], o[7]);
        }
    }
}

// ================= fused edge kernel v3: 64-edge tiles, 2 CTAs/SM,
// square (32x32) warp tiles to minimize smem wavefronts =================
#define ESTR 68
__global__ __launch_bounds__(256, 2)
void k_edge(const int* __restrict__ ei,
            const float* __restrict__ Wr,   // [16][128]
            const float* __restrict__ w2,   // [128][128]
            const float* __restrict__ b2,
            int numTiles) {
    extern __shared__ float sm[];
    float* sW2   = sm;                        // 128*128
    float* sWr   = sW2 + DD * DD;             // 16*128
    float* sHidT = sWr + RR * DD;             // 128*ESTR (transposed, swizzled)
    float* sRbfT = sHidT + 128 * ESTR;        // 16*ESTR
    int*   sSrc  = (int*)(sRbfT + RR * ESTR); // 64
    int*   sDst  = sSrc + 64;                 // 64

    const int tid = threadIdx.x;
    // square warp tiling: warp w covers rows (w&1)*32..+32, cols (w>>1)*32..+32
    const int w    = tid >> 5;
    const int lane = tid & 31;
    const int ly   = lane >> 2;     // 0..7  -> 4-row group
    const int lx   = lane & 3;      // 0..3  -> 8-col group
    const int r0 = (w & 1) * 32 + ly * 4;
    const int c0 = (w >> 1) * 32 + lx * 8;
    const int sw0 = (c0 >> 3) & 7;

    {
        const float4* w4 = (const float4*)w2;
#pragma unroll
        for (int i = 0; i < 16; ++i)
            ((float4*)sW2)[tid + i * 256] = w4[tid + i * 256];
        const float4* wr4 = (const float4*)Wr;
#pragma unroll
        for (int i = 0; i < 2; ++i)
            ((float4*)sWr)[tid + i * 256] = wr4[tid + i * 256];
    }
    float bias2[8];
#pragma unroll
    for (int j = 0; j < 8; ++j) bias2[j] = b2[c0 + j];

    for (int tile = blockIdx.x; tile < numTiles; tile += gridDim.x) {
        const int e0 = tile * 64;
        __syncthreads();  // protect smem from previous tile's readers
        if (tid < 64)       sSrc[tid]      = ei[e0 + tid];
        else if (tid < 128) sDst[tid - 64] = ei[EE + e0 + tid - 64];
        {
            const int row = tid & 63, c4 = (tid >> 6) * 4;
            const float4 v = *(const float4*)&g_rbf[(size_t)(e0 + row) * RR + c4];
            sRbfT[(c4 + 0) * ESTR + row] = v.x;
            sRbfT[(c4 + 1) * ESTR + row] = v.y;
            sRbfT[(c4 + 2) * ESTR + row] = v.z;
            sRbfT[(c4 + 3) * ESTR + row] = v.w;
        }
        __syncthreads();

        // gather Xs[src]+Xd[dst] for this thread's 4 rows x 8 cols into regs;
        // cache dst indices for the scatter epilogue.
        float xsv[4][8];
        int dreg[4];
#pragma unroll
        for (int i = 0; i < 4; ++i) {
            const int s = sSrc[r0 + i], d = sDst[r0 + i];
            dreg[i] = d;
            const float4 a0 = *(const float4*)&g_xs[(size_t)s * DD + c0];
            const float4 a1 = *(const float4*)&g_xs[(size_t)s * DD + c0 + 4];
            const float4 b0 = *(const float4*)&g_xd[(size_t)d * DD + c0];
            const float4 b1 = *(const float4*)&g_xd[(size_t)d * DD + c0 + 4];
            xsv[i][0] = a0.x + b0.x; xsv[i][1] = a0.y + b0.y;
            xsv[i][2] = a0.z + b0.z; xsv[i][3] = a0.w + b0.w;
            xsv[i][4] = a1.x + b1.x; xsv[i][5] = a1.y + b1.y;
            xsv[i][6] = a1.z + b1.z; xsv[i][7] = a1.w + b1.w;
        }

        // phase 1: K=16 rbf GEMM (overlaps the gather LDG latency)
        unsigned long long acc[4][4];
#pragma unroll
        for (int i = 0; i < 4; ++i)
#pragma unroll
            for (int p = 0; p < 4; ++p) acc[i][p] = 0ull;
#pragma unroll
        for (int kk = 0; kk < 16; ++kk) {
            const float4 av = *(const float4*)&sRbfT[kk * ESTR + r0];
            const ulonglong2 B0 = *(const ulonglong2*)&sWr[kk * DD + c0];
            const ulonglong2 B1 = *(const ulonglong2*)&sWr[kk * DD + c0 + 4];
            const float a[4] = { av.x, av.y, av.z, av.w };
#pragma unroll
            for (int i = 0; i < 4; ++i) {
                const unsigned long long aa = pk2(a[i], a[i]);
                ffma2(acc[i][0], aa, B0.x);
                ffma2(acc[i][1], aa, B0.y);
                ffma2(acc[i][2], aa, B1.x);
                ffma2(acc[i][3], aa, B1.y);
            }
        }

        // epilogue 1: silu(acc + xsv) -> sHidT (transposed, XOR-swizzled rows)
        {
            float o[4][8];
#pragma unroll
            for (int i = 0; i < 4; ++i) {
                float x, y;
                up2(acc[i][0], x, y); o[i][0] = silu_f(x + xsv[i][0]); o[i][1] = silu_f(y + xsv[i][1]);
                up2(acc[i][1], x, y); o[i][2] = silu_f(x + xsv[i][2]); o[i][3] = silu_f(y + xsv[i][3]);
                up2(acc[i][2], x, y); o[i][4] = silu_f(x + xsv[i][4]); o[i][5] = silu_f(y + xsv[i][5]);
                up2(acc[i][3], x, y); o[i][6] = silu_f(x + xsv[i][6]); o[i][7] = silu_f(y + xsv[i][7]);
#pragma unroll
                for (int p = 0; p < 4; ++p) acc[i][p] = 0ull;
            }
            const int rs0 = r0 ^ (sw0 << 3);
#pragma unroll
            for (int jj = 0; jj < 8; ++jj) {
                *(float4*)&sHidT[(c0 + jj) * ESTR + rs0] =
                    make_float4(o[0][jj], o[1][jj], o[2][jj], o[3][jj]);
            }
        }
        __syncthreads();

        // phase 2: K=128 GEMM2.
        // A: warp reads 32 contiguous (swizzle-permuted) rows = 128B -> 1 wavefront.
        // B: warp reads 32 cols = 128B -> 2 wavefronts. FMA-pipe bound.
        for (int kk = 0; kk < 128; ++kk) {
            const int rs = r0 ^ (((kk >> 3) & 7) << 3);
            const float4 av = *(const float4*)&sHidT[kk * ESTR + rs];
            const ulonglong2 B0 = *(const ulonglong2*)&sW2[kk * DD + c0];
            const ulonglong2 B1 = *(const ulonglong2*)&sW2[kk * DD + c0 + 4];
            const float a[4] = { av.x, av.y, av.z, av.w };
#pragma unroll
            for (int i = 0; i < 4; ++i) {
                const unsigned long long aa = pk2(a[i], a[i]);
                ffma2(acc[i][0], aa, B0.x);
                ffma2(acc[i][1], aa, B0.y);
                ffma2(acc[i][2], aa, B1.x);
                ffma2(acc[i][3], aa, B1.y);
            }
        }

        // epilogue 2: bias + vectorized reduction scatter
#pragma unroll
        for (int i = 0; i < 4; ++i) {
            float* dp = &g_agg[(size_t)dreg[i] * DD + c0];
            float x0, y0, x1, y1;
            up2(acc[i][0], x0, y0); up2(acc[i][1], x1, y1);
            red_add_v4(dp, x0 + bias2[0], y0 + bias2[1], x1 + bias2[2], y1 + bias2[3]);
            up2(acc[i][2], x0, y0); up2(acc[i][3], x1, y1);
            red_add_v4(dp + 4, x0 + bias2[4], y0 + bias2[5], x1 + bias2[6], y1 + bias2[7]);
        }
    }
}

// ================= node update MLP (concat(h,agg)) + residual -> g_hup =================
#define NHSTR 132
__global__ __launch_bounds__(512, 1)
void k_node(const float* __restrict__ w1, const float* __restrict__ b1,
            const float* __restrict__ w2, const float* __restrict__ b2,
            int numTiles) {
    extern __shared__ float sm[];
    float* sW1  = sm;                           // 256*128
    float* sHid = sW1 + 256 * DD;               // 128*NHSTR
    float* sA0  = sHid + 128 * NHSTR;           // 128*16
    float* sA1  = sA0 + 128 * 16;               // 128*16

    const int tid = threadIdx.x;
    const int c0 = (tid & 15) * 8;
    const int r0 = (tid >> 4) * 4;
    const int gr = tid >> 2;
    const int gq = (tid & 3) * 4;

    for (int i = tid; i < 256 * DD; i += 512) sW1[i] = w1[i];
    float bias1[8], bias2[8];
#pragma unroll
    for (int j = 0; j < 8; ++j) { bias1[j] = b1[c0 + j]; bias2[j] = b2[c0 + j]; }

    float* bufs[2] = { sA0, sA1 };

    for (int tile = blockIdx.x; tile < numTiles; tile += gridDim.x) {
        const int n0 = tile * 128;
        int gn = n0 + gr; if (gn >= NN) gn = NN - 1;
        unsigned long long acc[4][4];
#pragma unroll
        for (int i = 0; i < 4; ++i)
#pragma unroll
            for (int p = 0; p < 4; ++p) acc[i][p] = 0ull;
        __syncthreads();

        {
            float4 v = *(const float4*)&g_h[(size_t)gn * DD + gq];
            *(float4*)&bufs[0][gr * 16 + gq] = v;
        }
        __syncthreads();

        for (int kc = 0; kc < 16; ++kc) {
            float4 nv;
            if (kc < 15) {
                const int k = (kc + 1) * 16 + gq;
                if (k < 128) nv = *(const float4*)&g_h[(size_t)gn * DD + k];
                else         nv = *(const float4*)&g_agg[(size_t)gn * DD + (k - 128)];
            }
            const float* A = bufs[kc & 1];
            const int kbase = kc * 16;
#pragma unroll
            for (int kk = 0; kk < 16; ++kk) {
                const float* wrow = &sW1[(kbase + kk) * DD + c0];
                const ulonglong2 B0 = *(const ulonglong2*)wrow;
                const ulonglong2 B1 = *(const ulonglong2*)(wrow + 4);
#pragma unroll
                for (int i = 0; i < 4; ++i) {
                    const float a = A[(r0 + i) * 16 + kk];
                    const unsigned long long aa = pk2(a, a);
                    ffma2(acc[i][0], aa, B0.x);
                    ffma2(acc[i][1], aa, B0.y);
                    ffma2(acc[i][2], aa, B1.x);
                    ffma2(acc[i][3], aa, B1.y);
                }
            }
            if (kc < 15) *(float4*)&bufs[(kc + 1) & 1][gr * 16 + gq] = nv;
            __syncthreads();
        }

        {
            float4 w2v = *(const float4*)&w2[tid * 4];
#pragma unroll
            for (int i = 0; i < 4; ++i) {
                float* hrow = &sHid[(r0 + i) * NHSTR + c0];
                float o[8];
#pragma unroll
                for (int p = 0; p < 4; ++p) {
                    float x, y; up2(acc[i][p], x, y);
                    o[2 * p]     = silu_f(x + bias1[2 * p]);
                    o[2 * p + 1] = silu_f(y + bias1[2 * p + 1]);
                    acc[i][p] = 0ull;
                }
                *(float4*)&hrow[0] = make_float4(o[0], o[1], o[2], o[3]);
                *(float4*)&hrow[4] = make_float4(o[4], o[5], o[6], o[7]);
            }
            *(float4*)&bufs[0][tid * 4] = w2v;
        }
        __syncthreads();

        for (int kc = 0; kc < 8; ++kc) {
            float4 nv;
            if (kc < 7) nv = *(const float4*)&w2[(size_t)(kc + 1) * 16 * DD + tid * 4];
            const float* Bc = bufs[kc & 1];
            const int kbase = kc * 16;
#pragma unroll
            for (int kk = 0; kk < 16; ++kk) {
                const float* wrow = &Bc[kk * DD + c0];
                const ulonglong2 B0 = *(const ulonglong2*)wrow;
                const ulonglong2 B1 = *(const ulonglong2*)(wrow + 4);
#pragma unroll
                for (int i = 0; i < 4; ++i) {
                    const float a = sHid[(r0 + i) * NHSTR + kbase + kk];
                    const unsigned long long aa = pk2(a, a);
                    ffma2(acc[i][0], aa, B0.x);
                    ffma2(acc[i][1], aa, B0.y);
                    ffma2(acc[i][2], aa, B1.x);
                    ffma2(acc[i][3], aa, B1.y);
                }
            }
            if (kc < 7) *(float4*)&bufs[(kc + 1) & 1][tid * 4] = nv;
            __syncthreads();
        }

#pragma unroll
        for (int i = 0; i < 4; ++i) {
            const int n = n0 + r0 + i;
            if (n < NN) {
                const float4 h0 = *(const float4*)&g_h[(size_t)n * DD + c0];
                const float4 h1 = *(const float4*)&g_h[(size_t)n * DD + c0 + 4];
                float o[8];
#pragma unroll
                for (int p = 0; p < 4; ++p) {
                    float x, y; up2(acc[i][p], x, y);
                    o[2 * p]     = x + bias2[2 * p];
                    o[2 * p + 1] = y + bias2[2 * p + 1];
                }
                *(float4*)&g_hup[(size_t)n * DD + c0] =
                    make_float4(o[0] + h0.x, o[1] + h0.y, o[2] + h0.z, o[3] + h0.w);
                *(float4*)&g_hup[(size_t)n * DD + c0 + 4] =
                    make_float4(o[4] + h1.x, o[5] + h1.y, o[6] + h1.z, o[7] + h1.w);
            }
        }
    }
}

// ---------------- LayerNorm: g_h = LN(g_hup) ----------------
__global__ void k_ln(const float* __restrict__ g, const float* __restrict__ b) {
    const int gl = blockIdx.x * blockDim.x + threadIdx.x;
    const int node = gl >> 5;
    const int lane = gl & 31;
    if (node >= NN) return;
    const float4 v = ((const float4*)(g_hup + (size_t)node * DD))[lane];
    float s = v.x + v.y + v.z + v.w;
#pragma unroll
    for (int o = 16; o; o >>= 1) s += __shfl_xor_sync(0xFFFFFFFFu, s, o);
    const float mu = s * (1.0f / 128.0f);
    const float d0 = v.x - mu, d1 = v.y - mu, d2 = v.z - mu, d3 = v.w - mu;
    float q = d0 * d0 + d1 * d1 + d2 * d2 + d3 * d3;
#pragma unroll
    for (int o = 16; o; o >>= 1) q += __shfl_xor_sync(0xFFFFFFFFu, q, o);
    const float inv = rsqrtf(q * (1.0f / 128.0f) + 1e-5f);
    const float4 gg = ((const float4*)g)[lane];
    const float4 bb = ((const float4*)b)[lane];
    float4 o4;
    o4.x = d0 * inv * gg.x + bb.x;
    o4.y = d1 * inv * gg.y + bb.y;
    o4.z = d2 * inv * gg.z + bb.z;
    o4.w = d3 * inv * gg.w + bb.w;
    ((float4*)(g_h + (size_t)node * DD))[lane] = o4;
}

// ---------------- output MLP ----------------
__global__ void k_out(const float* __restrict__ w1, const float* __restrict__ b1,
                      const float* __restrict__ w2, const float* __restrict__ b2,
                      float* __restrict__ out) {
    extern __shared__ float sm[];
    float* sW1  = sm;
    float* sW2  = sW1 + DD * DD;
    float* sX   = sW2 + DD * 3;
    float* sHid = sX + DD;
    const int j = threadIdx.x;  // 128
    for (int i = j; i < DD * DD; i += DD) sW1[i] = w1[i];
    for (int i = j; i < DD * 3; i += DD) sW2[i] = w2[i];
    const float bb1 = b1[j];
    __syncthreads();
    const int n0 = blockIdx.x * 16;
    for (int m = 0; m < 16; ++m) {
        const int n = n0 + m;
        sX[j] = g_h[(size_t)n * DD + j];
        __syncthreads();
        float acc = bb1;
#pragma unroll 8
        for (int k = 0; k < DD; ++k) acc += sX[k] * sW1[k * DD + j];
        sHid[j] = silu_f(acc);
        __syncthreads();
        if (j < 3) {
            float o = b2[j];
            for (int k = 0; k < DD; ++k) o += sHid[k] * sW2[k * 3 + j];
            out[(size_t)n * 3 + j] = o;
        }
        __syncthreads();
    }
}

// ---------------- launch ----------------
extern "C" void kernel_launch(void* const* d_in, const int* in_sizes, int n_in,
                              void* d_out, int out_size) {
    const float* x_t      = (const float*)d_in[0];
    const int*   ei       = (const int*)d_in[1];
    const int*   tp       = (const int*)d_in[2];
    const float* time_w1  = (const float*)d_in[3];
    const float* time_b1  = (const float*)d_in[4];
    const float* time_w2  = (const float*)d_in[5];
    const float* time_b2  = (const float*)d_in[6];
    const float* nodein_w1= (const float*)d_in[7];
    const float* nodein_b1= (const float*)d_in[8];
    const float* nodein_w2= (const float*)d_in[9];
    const float* nodein_b2= (const float*)d_in[10];
    const float* phim_w1  = (const float*)d_in[11];
    const float* phim_b1  = (const float*)d_in[12];
    const float* phim_w2  = (const float*)d_in[13];
    const float* phim_b2  = (const float*)d_in[14];
    const float* phih_w1  = (const float*)d_in[15];
    const float* phih_b1  = (const float*)d_in[16];
    const float* phih_w2  = (const float*)d_in[17];
    const float* phih_b2  = (const float*)d_in[18];
    const float* ln_g     = (const float*)d_in[19];
    const float* ln_b     = (const float*)d_in[20];
    const float* out_w1   = (const float*)d_in[21];
    const float* out_b1   = (const float*)d_in[22];
    const float* out_w2   = (const float*)d_in[23];
    const float* out_b2   = (const float*)d_in[24];
    float* out = (float*)d_out;

    const int SMEM_EDGE = (DD * DD + RR * DD + 128 * ESTR + RR * ESTR) * 4 + 128 * 4;
    const int SMEM_PRE  = (DD * DD + 128 * ATSTR) * 4;
    const int SMEM_NIN  = (DD * DD + 128 * ATSTR + 3 * DD + DD) * 4;
    const int SMEM_NODE = (256 * DD + 128 * NHSTR + 2 * 128 * 16) * 4;
    const int SMEM_OUT  = (DD * DD + DD * 3 + DD + DD) * 4;

    cudaFuncSetAttribute(k_edge, cudaFuncAttributeMaxDynamicSharedMemorySize, SMEM_EDGE);
    cudaFuncSetAttribute(k_prep, cudaFuncAttributeMaxDynamicSharedMemorySize, SMEM_PRE);
    cudaFuncSetAttribute(k_nin,  cudaFuncAttributeMaxDynamicSharedMemorySize, SMEM_NIN);
    cudaFuncSetAttribute(k_node, cudaFuncAttributeMaxDynamicSharedMemorySize, SMEM_NODE);
    cudaFuncSetAttribute(k_out,  cudaFuncAttributeMaxDynamicSharedMemorySize, SMEM_OUT);

    const int edgeTiles = EE / 64;           // 10000
    const int nodeTiles = (NN + 127) / 128;  // 157

    // launch 0
    k_time<<<1, 128>>>(tp, time_w1, time_b1, time_w2, time_b2, nodein_w1, nodein_b1);
    // launch 1
    k_nin<<<PRE_TILES, 256, SMEM_NIN>>>(x_t, nodein_w1, nodein_w2, nodein_b2);

    for (int l = 0; l < LL; ++l) {
        const float* W1l = phim_w1 + (size_t)l * 272 * DD;
        const int withRbf = (l == 0);
        const int prepGrid = 2 * PRE_TILES + 157 + (withRbf ? 625 : 0);
        k_prep<<<prepGrid, 256, SMEM_PRE>>>(W1l, W1l + 128 * DD,
                                            phim_b1 + (size_t)l * DD, ei, x_t, withRbf);
        // launch 3 (l==0) -> ncu capture target
        k_edge<<<296, 256, SMEM_EDGE>>>(ei,
                                        W1l + 256 * DD,
                                        phim_w2 + (size_t)l * DD * DD,
                                        phim_b2 + (size_t)l * DD,
                                        edgeTiles);
        k_node<<<148, 512, SMEM_NODE>>>(phih_w1 + (size_t)l * 256 * DD,
                                        phih_b1 + (size_t)l * DD,
                                        phih_w2 + (size_t)l * DD * DD,
                                        phih_b2 + (size_t)l * DD,
                                        nodeTiles);
        k_ln<<<(NN * 32 + 255) / 256, 256>>>(ln_g + (size_t)l * DD, ln_b + (size_t)l * DD);
    }

    k_out<<<NN / 16, 128, SMEM_OUT>>>(out_w1, out_b1, out_w2, out_b2, out);
}

// round 11
// speedup vs baseline: 4.0858x; 1.0033x over previous
#include <cuda_runtime.h>
#include <cuda_bf16.h>
#include <cstdint>

#define NN 20000
#define EE 640000
#define DD 128
#define RR 16
#define LL 3

// ---------------- device scratch ----------------
__device__ float g_h   [(size_t)NN * DD];
__device__ float g_hup [(size_t)NN * DD];
__device__ float g_agg [(size_t)NN * DD];
__device__ float g_rbf [(size_t)EE * RR];   // in SORTED edge order
__device__ float g_xs  [(size_t)NN * DD];   // h @ Wa + b1
__device__ float g_xd  [(size_t)NN * DD];   // h @ Wb
__device__ float g_base[DD];
// dst-sorted edge structure (rebuilt every call; g_hist re-zeroed by scatter)
__device__ int   g_hist[NN + 1];            // zero-initialized at load
__device__ int   g_woff[NN];
__device__ int   g_ssrc[EE];
__device__ int   g_sdst[EE];

__device__ __forceinline__ float silu_f(float x) {
    return x / (1.0f + __expf(-x));
}

// sm_103a packed fp32 FMA helpers
__device__ __forceinline__ unsigned long long pk2(float lo, float hi) {
    unsigned long long r;
    asm("mov.b64 %0, {%1, %2};" : "=l"(r) : "f"(lo), "f"(hi));
    return r;
}
__device__ __forceinline__ void up2(unsigned long long v, float& lo, float& hi) {
    asm("mov.b64 {%0, %1}, %2;" : "=f"(lo), "=f"(hi) : "l"(v));
}
__device__ __forceinline__ void ffma2(unsigned long long& d, unsigned long long a, unsigned long long b) {
    asm("fma.rn.f32x2 %0, %1, %2, %0;" : "+l"(d) : "l"(a), "l"(b));
}
__device__ __forceinline__ void red_add_f(float* p, float v) {
    asm volatile("red.global.add.f32 [%0], %1;" :: "l"(p), "f"(v) : "memory");
}

// ---------------- launch 0: time MLP (block 0) + dst histogram (blocks 1..2500) ----------------
__global__ void k_time_hist(const int* __restrict__ ei, const int* __restrict__ tptr,
                            const float* __restrict__ tw1, const float* __restrict__ tb1,
                            const float* __restrict__ tw2, const float* __restrict__ tb2,
                            const float* __restrict__ nw1, const float* __restrict__ nb1) {
    if (blockIdx.x > 0) {
        const int e = (blockIdx.x - 1) * 256 + threadIdx.x;   // exactly EE threads
        atomicAdd(&g_hist[ei[EE + e]], 1);
        return;
    }
    __shared__ float sE[DD], sH[DD], sTe[DD];
    const int j = threadIdx.x;
    const bool act = (j < DD);
    int iv = *tptr;
    float t = (iv >= 0 && iv < 1000000) ? (float)iv : __int_as_float(iv);
    if (act) {
        int i = (j < 64) ? j : (j - 64);
        float f = __expf(-logf(10000.0f) * (float)i / 63.0f);
        float a = t * f;
        sE[j] = (j < 64) ? sinf(a) : cosf(a);
    }
    __syncthreads();
    if (act) {
        float acc = tb1[j];
        for (int k = 0; k < DD; ++k) acc += sE[k] * tw1[k * DD + j];
        sH[j] = silu_f(acc);
    }
    __syncthreads();
    if (act) {
        float acc2 = tb2[j];
        for (int k = 0; k < DD; ++k) acc2 += sH[k] * tw2[k * DD + j];
        sTe[j] = acc2;
    }
    __syncthreads();
    if (act) {
        float accb = nb1[j];
        for (int k = 0; k < DD; ++k) accb += sTe[k] * nw1[(3 + k) * DD + j];
        g_base[j] = accb;
    }
}

// ================= shared fast-GEMM core pieces =================
#define ATSTR 132

// out = h @ W (+bias), one 128-node tile.
__device__ __forceinline__ void do_pre(const float* __restrict__ W,
                                       const float* __restrict__ bias,
                                       float* __restrict__ out, int tileIdx) {
    extern __shared__ float sm[];
    float* sW  = sm;            // 128*128
    float* sAT = sW + DD * DD;  // 128*ATSTR

    const int tid = threadIdx.x;
    const int tx = tid & 15, ty = tid >> 4;
    const int c0 = tx * 8, r0 = ty * 8;
    const int n0 = tileIdx * 128;

    {
        const float4* w4 = (const float4*)W;
#pragma unroll
        for (int i = 0; i < 16; ++i)
            ((float4*)sW)[tid + i * 256] = w4[tid + i * 256];
    }
#pragma unroll
    for (int i = 0; i < 16; ++i) {
        const int idx = tid + i * 256;
        const int nl = idx >> 5;
        const int q = (idx & 31) * 4;
        int n = n0 + nl; if (n >= NN) n = NN - 1;
        const float4 v = *(const float4*)&g_h[(size_t)n * DD + q];
        const float vv[4] = { v.x, v.y, v.z, v.w };
#pragma unroll
        for (int m = 0; m < 4; ++m) {
            const int k = q + m;
            sAT[k * ATSTR + (nl ^ (((k >> 3) & 7) << 3))] = vv[m];
        }
    }
    __syncthreads();

    unsigned long long acc[8][4];
#pragma unroll
    for (int i = 0; i < 8; ++i)
#pragma unroll
        for (int p = 0; p < 4; ++p) acc[i][p] = 0ull;

    for (int kk = 0; kk < 128; ++kk) {
        const int rs = r0 ^ (((kk >> 3) & 7) << 3);
        const float4 a0 = *(const float4*)&sAT[kk * ATSTR + rs];
        const float4 a1 = *(const float4*)&sAT[kk * ATSTR + rs + 4];
        const ulonglong2 B0 = *(const ulonglong2*)&sW[kk * DD + c0];
        const ulonglong2 B1 = *(const ulonglong2*)&sW[kk * DD + c0 + 4];
        const float a[8] = { a0.x, a0.y, a0.z, a0.w, a1.x, a1.y, a1.z, a1.w };
#pragma unroll
        for (int i = 0; i < 8; ++i) {
            const unsigned long long aa = pk2(a[i], a[i]);
            ffma2(acc[i][0], aa, B0.x);
            ffma2(acc[i][1], aa, B0.y);
            ffma2(acc[i][2], aa, B1.x);
            ffma2(acc[i][3], aa, B1.y);
        }
    }

    float bv[8];
#pragma unroll
    for (int j = 0; j < 8; ++j) bv[j] = bias ? bias[c0 + j] : 0.0f;
#pragma unroll
    for (int i = 0; i < 8; ++i) {
        const int n = n0 + r0 + i;
        if (n < NN) {
            float o[8];
#pragma unroll
            for (int p = 0; p < 4; ++p) {
                float x, y; up2(acc[i][p], x, y);
                o[2 * p] = x + bv[2 * p]; o[2 * p + 1] = y + bv[2 * p + 1];
            }
            *(float4*)&out[(size_t)n * DD + c0]     = make_float4(o[0], o[1], o[2], o[3]);
            *(float4*)&out[(size_t)n * DD + c0 + 4] = make_float4(o[4], o[5], o[6], o[7]);
        }
    }
}

// ---------------- launch 1: scan (block 0) + node-input MLP (blocks 1..157) ----------------
__global__ __launch_bounds__(256, 1)
void k_scan_nin(const float* __restrict__ xt,
                const float* __restrict__ w1,   // [131][128]
                const float* __restrict__ w2,   // [128][128]
                const float* __restrict__ b2) {
    extern __shared__ float sm[];
    if (blockIdx.x == 0) {
        // exclusive scan of g_hist counts -> g_woff segment starts
        int* ip = (int*)sm;  // 256 partials
        const int t = threadIdx.x;
        const int per = 79;  // 256*79 >= NN+1
        const int start = t * per;
        int sum = 0;
        for (int i = 0; i < per; ++i) {
            const int idx = start + i;
            if (idx < NN) sum += g_hist[idx];
        }
        ip[t] = sum;
        __syncthreads();
        if (t == 0) {
            int run = 0;
            for (int i = 0; i < 256; ++i) { int v = ip[i]; ip[i] = run; run += v; }
        }
        __syncthreads();
        int run = ip[t];
        for (int i = 0; i < per; ++i) {
            const int idx = start + i;
            if (idx < NN) { int v = g_hist[idx]; g_woff[idx] = run; run += v; }
        }
        return;
    }
    // ---- node input MLP tile ----
    float* sW    = sm;                      // 128*128
    float* sAT   = sW + DD * DD;            // 128*ATSTR
    float* sW1x  = sAT + 128 * ATSTR;       // 3*128
    float* sBase = sW1x + 3 * DD;           // 128

    const int tid = threadIdx.x;
    const int tx = tid & 15, ty = tid >> 4;
    const int c0 = tx * 8, r0 = ty * 8;
    const int n0 = (blockIdx.x - 1) * 128;

    {
        const float4* w4 = (const float4*)w2;
#pragma unroll
        for (int i = 0; i < 16; ++i)
            ((float4*)sW)[tid + i * 256] = w4[tid + i * 256];
    }
    if (tid < 128) {
        sW1x[tid]       = w1[tid];
        sW1x[128 + tid] = w1[128 + tid];
        sW1x[256 + tid] = w1[256 + tid];
        sBase[tid]      = g_base[tid];
    }
    __syncthreads();

#pragma unroll
    for (int i = 0; i < 16; ++i) {
        const int idx = tid + i * 256;
        const int nl = idx >> 5;
        const int q = (idx & 31) * 4;
        int n = n0 + nl; if (n >= NN) n = NN - 1;
        const float x0 = xt[n * 3 + 0], x1 = xt[n * 3 + 1], x2 = xt[n * 3 + 2];
#pragma unroll
        for (int m = 0; m < 4; ++m) {
            const int k = q + m;
            const float v = silu_f(sBase[k] + x0 * sW1x[k] + x1 * sW1x[128 + k] + x2 * sW1x[256 + k]);
            sAT[k * ATSTR + (nl ^ (((k >> 3) & 7) << 3))] = v;
        }
    }
    __syncthreads();

    unsigned long long acc[8][4];
#pragma unroll
    for (int i = 0; i < 8; ++i)
#pragma unroll
        for (int p = 0; p < 4; ++p) acc[i][p] = 0ull;

    for (int kk = 0; kk < 128; ++kk) {
        const int rs = r0 ^ (((kk >> 3) & 7) << 3);
        const float4 a0 = *(const float4*)&sAT[kk * ATSTR + rs];
        const float4 a1 = *(const float4*)&sAT[kk * ATSTR + rs + 4];
        const ulonglong2 B0 = *(const ulonglong2*)&sW[kk * DD + c0];
        const ulonglong2 B1 = *(const ulonglong2*)&sW[kk * DD + c0 + 4];
        const float a[8] = { a0.x, a0.y, a0.z, a0.w, a1.x, a1.y, a1.z, a1.w };
#pragma unroll
        for (int i = 0; i < 8; ++i) {
            const unsigned long long aa = pk2(a[i], a[i]);
            ffma2(acc[i][0], aa, B0.x);
            ffma2(acc[i][1], aa, B0.y);
            ffma2(acc[i][2], aa, B1.x);
            ffma2(acc[i][3], aa, B1.y);
        }
    }

    float bv[8];
#pragma unroll
    for (int j = 0; j < 8; ++j) bv[j] = b2[c0 + j];
#pragma unroll
    for (int i = 0; i < 8; ++i) {
        const int n = n0 + r0 + i;
        if (n < NN) {
            float o[8];
#pragma unroll
            for (int p = 0; p < 4; ++p) {
                float x, y; up2(acc[i][p], x, y);
                o[2 * p] = x + bv[2 * p]; o[2 * p + 1] = y + bv[2 * p + 1];
            }
            *(float4*)&g_h[(size_t)n * DD + c0]     = make_float4(o[0], o[1], o[2], o[3]);
            *(float4*)&g_h[(size_t)n * DD + c0 + 4] = make_float4(o[4], o[5], o[6], o[7]);
        }
    }
}

// ================= per-layer prologue =================
// blocks [0, scatBlocks)              : edge scatter (sort) + RBF @ sorted pos + hist rezero
// blocks [scatBlocks, +314)           : Xs = h@Wa + b1 ; Xd = h@Wb
// blocks [scatBlocks+314, +471)       : zero g_agg
#define PRE_TILES 157
__global__ __launch_bounds__(256, 1)
void k_prep(const float* __restrict__ Wa, const float* __restrict__ Wb,
            const float* __restrict__ b1,
            const int* __restrict__ ei, const float* __restrict__ xt,
            int scatBlocks) {
    int bx = blockIdx.x;
    if (bx < scatBlocks) {
        const int e = bx * 256 + threadIdx.x;        // exactly EE threads
        if (e <= NN) g_hist[e] = 0;                  // re-zero for next call
        const int s = ei[e], d = ei[EE + e];
        const int pos = atomicAdd(&g_woff[d], 1);
        g_ssrc[pos] = s;
        g_sdst[pos] = d;
        const float dx = xt[s * 3 + 0] - xt[d * 3 + 0];
        const float dy = xt[s * 3 + 1] - xt[d * 3 + 1];
        const float r = sqrtf(dx * dx + dy * dy + 1e-8f);
        const float step = 1.41421356237309515f / 15.0f;
        const float gamma = 1.0f / (2.0f * step * step);
#pragma unroll
        for (int c = 0; c < RR; ++c) {
            float u = r - (float)c * step;
            g_rbf[(size_t)pos * RR + c] = __expf(-gamma * u * u);
        }
        return;
    }
    bx -= scatBlocks;
    if (bx < 2 * PRE_TILES) {
        const int sel = (bx >= PRE_TILES);
        do_pre(sel ? Wb : Wa, sel ? nullptr : b1, sel ? g_xd : g_xs,
               sel ? bx - PRE_TILES : bx);
        return;
    }
    bx -= 2 * PRE_TILES;
    // zero g_agg: 157 blocks x 16384 floats
    const int base = bx * 16384 + threadIdx.x * 4;
#pragma unroll
    for (int k = 0; k < 16; ++k) {
        const int i = base + k * 1024;
        if (i < NN * DD) *(float4*)&g_agg[i] = make_float4(0.f, 0.f, 0.f, 0.f);
    }
}

// ================= fused edge kernel v4: dst-sorted 64-edge tiles, 2 CTAs/SM,
// square warp tiles, segment-reduced scatter =================
#define ESTR 68
#define OSTR 132
__global__ __launch_bounds__(256, 2)
void k_edge(const float* __restrict__ Wr,   // [16][128]
            const float* __restrict__ w2,   // [128][128]
            const float* __restrict__ b2,
            int numTiles) {
    extern __shared__ float sm[];
    float* sW2   = sm;                        // 128*128
    float* sWr   = sW2 + DD * DD;             // 16*128
    float* sHidT = sWr + RR * DD;             // 128*ESTR (transposed, swizzled); reused as sOut
    float* sRbfT = sHidT + 128 * ESTR;        // 16*ESTR
    int*   sSrc  = (int*)(sRbfT + RR * ESTR); // 64
    int*   sDst  = sSrc + 64;                 // 64

    const int tid = threadIdx.x;
    const int w    = tid >> 5;
    const int lane = tid & 31;
    const int ly   = lane >> 2;
    const int lx   = lane & 3;
    const int r0 = (w & 1) * 32 + ly * 4;
    const int c0 = (w >> 1) * 32 + lx * 8;
    const int sw0 = (c0 >> 3) & 7;

    {
        const float4* w4 = (const float4*)w2;
#pragma unroll
        for (int i = 0; i < 16; ++i)
            ((float4*)sW2)[tid + i * 256] = w4[tid + i * 256];
        const float4* wr4 = (const float4*)Wr;
#pragma unroll
        for (int i = 0; i < 2; ++i)
            ((float4*)sWr)[tid + i * 256] = wr4[tid + i * 256];
    }
    float bias2[8];
#pragma unroll
    for (int j = 0; j < 8; ++j) bias2[j] = b2[c0 + j];

    for (int tile = blockIdx.x; tile < numTiles; tile += gridDim.x) {
        const int e0 = tile * 64;
        __syncthreads();  // protect smem from previous tile's readers
        if (tid < 64)       sSrc[tid]      = g_ssrc[e0 + tid];
        else if (tid < 128) sDst[tid - 64] = g_sdst[e0 + tid - 64];
        {
            const int row = tid & 63, c4 = (tid >> 6) * 4;
            const float4 v = *(const float4*)&g_rbf[(size_t)(e0 + row) * RR + c4];
            sRbfT[(c4 + 0) * ESTR + row] = v.x;
            sRbfT[(c4 + 1) * ESTR + row] = v.y;
            sRbfT[(c4 + 2) * ESTR + row] = v.z;
            sRbfT[(c4 + 3) * ESTR + row] = v.w;
        }
        __syncthreads();

        // gather Xs[src]+Xd[dst] (dst sorted -> Xd hits L1)
        float xsv[4][8];
#pragma unroll
        for (int i = 0; i < 4; ++i) {
            const int s = sSrc[r0 + i], d = sDst[r0 + i];
            const float4 a0 = *(const float4*)&g_xs[(size_t)s * DD + c0];
            const float4 a1 = *(const float4*)&g_xs[(size_t)s * DD + c0 + 4];
            const float4 b0 = *(const float4*)&g_xd[(size_t)d * DD + c0];
            const float4 b1 = *(const float4*)&g_xd[(size_t)d * DD + c0 + 4];
            xsv[i][0] = a0.x + b0.x; xsv[i][1] = a0.y + b0.y;
            xsv[i][2] = a0.z + b0.z; xsv[i][3] = a0.w + b0.w;
            xsv[i][4] = a1.x + b1.x; xsv[i][5] = a1.y + b1.y;
            xsv[i][6] = a1.z + b1.z; xsv[i][7] = a1.w + b1.w;
        }

        // phase 1: K=16 rbf GEMM (overlaps the gather LDG latency)
        unsigned long long acc[4][4];
#pragma unroll
        for (int i = 0; i < 4; ++i)
#pragma unroll
            for (int p = 0; p < 4; ++p) acc[i][p] = 0ull;
#pragma unroll
        for (int kk = 0; kk < 16; ++kk) {
            const float4 av = *(const float4*)&sRbfT[kk * ESTR + r0];
            const ulonglong2 B0 = *(const ulonglong2*)&sWr[kk * DD + c0];
            const ulonglong2 B1 = *(const ulonglong2*)&sWr[kk * DD + c0 + 4];
            const float a[4] = { av.x, av.y, av.z, av.w };
#pragma unroll
            for (int i = 0; i < 4; ++i) {
                const unsigned long long aa = pk2(a[i], a[i]);
                ffma2(acc[i][0], aa, B0.x);
                ffma2(acc[i][1], aa, B0.y);
                ffma2(acc[i][2], aa, B1.x);
                ffma2(acc[i][3], aa, B1.y);
            }
        }

        // epilogue 1: silu(acc + xsv) -> sHidT (transposed, XOR-swizzled rows)
        {
            float o[4][8];
#pragma unroll
            for (int i = 0; i < 4; ++i) {
                float x, y;
                up2(acc[i][0], x, y); o[i][0] = silu_f(x + xsv[i][0]); o[i][1] = silu_f(y + xsv[i][1]);
                up2(acc[i][1], x, y); o[i][2] = silu_f(x + xsv[i][2]); o[i][3] = silu_f(y + xsv[i][3]);
                up2(acc[i][2], x, y); o[i][4] = silu_f(x + xsv[i][4]); o[i][5] = silu_f(y + xsv[i][5]);
                up2(acc[i][3], x, y); o[i][6] = silu_f(x + xsv[i][6]); o[i][7] = silu_f(y + xsv[i][7]);
#pragma unroll
                for (int p = 0; p < 4; ++p) acc[i][p] = 0ull;
            }
            const int rs0 = r0 ^ (sw0 << 3);
#pragma unroll
            for (int jj = 0; jj < 8; ++jj) {
                *(float4*)&sHidT[(c0 + jj) * ESTR + rs0] =
                    make_float4(o[0][jj], o[1][jj], o[2][jj], o[3][jj]);
            }
        }
        __syncthreads();

        // phase 2: K=128 GEMM2
        for (int kk = 0; kk < 128; ++kk) {
            const int rs = r0 ^ (((kk >> 3) & 7) << 3);
            const float4 av = *(const float4*)&sHidT[kk * ESTR + rs];
            const ulonglong2 B0 = *(const ulonglong2*)&sW2[kk * DD + c0];
            const ulonglong2 B1 = *(const ulonglong2*)&sW2[kk * DD + c0 + 4];
            const float a[4] = { av.x, av.y, av.z, av.w };
#pragma unroll
            for (int i = 0; i < 4; ++i) {
                const unsigned long long aa = pk2(a[i], a[i]);
                ffma2(acc[i][0], aa, B0.x);
                ffma2(acc[i][1], aa, B0.y);
                ffma2(acc[i][2], aa, B1.x);
                ffma2(acc[i][3], aa, B1.y);
            }
        }
        __syncthreads();  // all GEMM2 reads of sHidT complete before overwrite

        // epilogue 2a: write messages (+bias) to smem tile (reuse sHidT region)
        float* sOut = sHidT;  // 64 rows x OSTR
#pragma unroll
        for (int i = 0; i < 4; ++i) {
            float x0, y0, x1, y1;
            up2(acc[i][0], x0, y0); up2(acc[i][1], x1, y1);
            *(float4*)&sOut[(r0 + i) * OSTR + c0] =
                make_float4(x0 + bias2[0], y0 + bias2[1], x1 + bias2[2], y1 + bias2[3]);
            up2(acc[i][2], x0, y0); up2(acc[i][3], x1, y1);
            *(float4*)&sOut[(r0 + i) * OSTR + c0 + 4] =
                make_float4(x0 + bias2[4], y0 + bias2[5], x1 + bias2[6], y1 + bias2[7]);
        }
        __syncthreads();

        // epilogue 2b: segment-sum over sorted dst, one red per (segment, col)
        {
            const int col  = tid & 127;
            const int rbeg = (tid >> 7) * 32;
            float a2 = 0.0f;
            int prev = sDst[rbeg];
            for (int r = rbeg; r < rbeg + 32; ++r) {
                const int d = sDst[r];
                if (d != prev) {
                    red_add_f(&g_agg[(size_t)prev * DD + col], a2);
                    a2 = 0.0f; prev = d;
                }
                a2 += sOut[r * OSTR + col];
            }
            red_add_f(&g_agg[(size_t)prev * DD + col], a2);
        }
    }
}

// ================= node update MLP (concat(h,agg)) + residual -> g_hup =================
#define NHSTR 132
__global__ __launch_bounds__(512, 1)
void k_node(const float* __restrict__ w1, const float* __restrict__ b1,
            const float* __restrict__ w2, const float* __restrict__ b2,
            int numTiles) {
    extern __shared__ float sm[];
    float* sW1  = sm;                           // 256*128
    float* sHid = sW1 + 256 * DD;               // 128*NHSTR
    float* sA0  = sHid + 128 * NHSTR;           // 128*16
    float* sA1  = sA0 + 128 * 16;               // 128*16

    const int tid = threadIdx.x;
    const int c0 = (tid & 15) * 8;
    const int r0 = (tid >> 4) * 4;
    const int gr = tid >> 2;
    const int gq = (tid & 3) * 4;

    for (int i = tid; i < 256 * DD; i += 512) sW1[i] = w1[i];
    float bias1[8], bias2[8];
#pragma unroll
    for (int j = 0; j < 8; ++j) { bias1[j] = b1[c0 + j]; bias2[j] = b2[c0 + j]; }

    float* bufs[2] = { sA0, sA1 };

    for (int tile = blockIdx.x; tile < numTiles; tile += gridDim.x) {
        const int n0 = tile * 128;
        int gn = n0 + gr; if (gn >= NN) gn = NN - 1;
        unsigned long long acc[4][4];
#pragma unroll
        for (int i = 0; i < 4; ++i)
#pragma unroll
            for (int p = 0; p < 4; ++p) acc[i][p] = 0ull;
        __syncthreads();

        {
            float4 v = *(const float4*)&g_h[(size_t)gn * DD + gq];
            *(float4*)&bufs[0][gr * 16 + gq] = v;
        }
        __syncthreads();

        for (int kc = 0; kc < 16; ++kc) {
            float4 nv;
            if (kc < 15) {
                const int k = (kc + 1) * 16 + gq;
                if (k < 128) nv = *(const float4*)&g_h[(size_t)gn * DD + k];
                else         nv = *(const float4*)&g_agg[(size_t)gn * DD + (k - 128)];
            }
            const float* A = bufs[kc & 1];
            const int kbase = kc * 16;
#pragma unroll
            for (int kk = 0; kk < 16; ++kk) {
                const float* wrow = &sW1[(kbase + kk) * DD + c0];
                const ulonglong2 B0 = *(const ulonglong2*)wrow;
                const ulonglong2 B1 = *(const ulonglong2*)(wrow + 4);
#pragma unroll
                for (int i = 0; i < 4; ++i) {
                    const float a = A[(r0 + i) * 16 + kk];
                    const unsigned long long aa = pk2(a, a);
                    ffma2(acc[i][0], aa, B0.x);
                    ffma2(acc[i][1], aa, B0.y);
                    ffma2(acc[i][2], aa, B1.x);
                    ffma2(acc[i][3], aa, B1.y);
                }
            }
            if (kc < 15) *(float4*)&bufs[(kc + 1) & 1][gr * 16 + gq] = nv;
            __syncthreads();
        }

        {
            float4 w2v = *(const float4*)&w2[tid * 4];
#pragma unroll
            for (int i = 0; i < 4; ++i) {
                float* hrow = &sHid[(r0 + i) * NHSTR + c0];
                float o[8];
#pragma unroll
                for (int p = 0; p < 4; ++p) {
                    float x, y; up2(acc[i][p], x, y);
                    o[2 * p]     = silu_f(x + bias1[2 * p]);
                    o[2 * p + 1] = silu_f(y + bias1[2 * p + 1]);
                    acc[i][p] = 0ull;
                }
                *(float4*)&hrow[0] = make_float4(o[0], o[1], o[2], o[3]);
                *(float4*)&hrow[4] = make_float4(o[4], o[5], o[6], o[7]);
            }
            *(float4*)&bufs[0][tid * 4] = w2v;
        }
        __syncthreads();

        for (int kc = 0; kc < 8; ++kc) {
            float4 nv;
            if (kc < 7) nv = *(const float4*)&w2[(size_t)(kc + 1) * 16 * DD + tid * 4];
            const float* Bc = bufs[kc & 1];
            const int kbase = kc * 16;
#pragma unroll
            for (int kk = 0; kk < 16; ++kk) {
                const float* wrow = &Bc[kk * DD + c0];
                const ulonglong2 B0 = *(const ulonglong2*)wrow;
                const ulonglong2 B1 = *(const ulonglong2*)(wrow + 4);
#pragma unroll
                for (int i = 0; i < 4; ++i) {
                    const float a = sHid[(r0 + i) * NHSTR + kbase + kk];
                    const unsigned long long aa = pk2(a, a);
                    ffma2(acc[i][0], aa, B0.x);
                    ffma2(acc[i][1], aa, B0.y);
                    ffma2(acc[i][2], aa, B1.x);
                    ffma2(acc[i][3], aa, B1.y);
                }
            }
            if (kc < 7) *(float4*)&bufs[(kc + 1) & 1][tid * 4] = nv;
            __syncthreads();
        }

#pragma unroll
        for (int i = 0; i < 4; ++i) {
            const int n = n0 + r0 + i;
            if (n < NN) {
                const float4 h0 = *(const float4*)&g_h[(size_t)n * DD + c0];
                const float4 h1 = *(const float4*)&g_h[(size_t)n * DD + c0 + 4];
                float o[8];
#pragma unroll
                for (int p = 0; p < 4; ++p) {
                    float x, y; up2(acc[i][p], x, y);
                    o[2 * p]     = x + bias2[2 * p];
                    o[2 * p + 1] = y + bias2[2 * p + 1];
                }
                *(float4*)&g_hup[(size_t)n * DD + c0] =
                    make_float4(o[0] + h0.x, o[1] + h0.y, o[2] + h0.z, o[3] + h0.w);
                *(float4*)&g_hup[(size_t)n * DD + c0 + 4] =
                    make_float4(o[4] + h1.x, o[5] + h1.y, o[6] + h1.z, o[7] + h1.w);
            }
        }
    }
}

// ---------------- LayerNorm: g_h = LN(g_hup) ----------------
__global__ void k_ln(const float* __restrict__ g, const float* __restrict__ b) {
    const int gl = blockIdx.x * blockDim.x + threadIdx.x;
    const int node = gl >> 5;
    const int lane = gl & 31;
    if (node >= NN) return;
    const float4 v = ((const float4*)(g_hup + (size_t)node * DD))[lane];
    float s = v.x + v.y + v.z + v.w;
#pragma unroll
    for (int o = 16; o; o >>= 1) s += __shfl_xor_sync(0xFFFFFFFFu, s, o);
    const float mu = s * (1.0f / 128.0f);
    const float d0 = v.x - mu, d1 = v.y - mu, d2 = v.z - mu, d3 = v.w - mu;
    float q = d0 * d0 + d1 * d1 + d2 * d2 + d3 * d3;
#pragma unroll
    for (int o = 16; o; o >>= 1) q += __shfl_xor_sync(0xFFFFFFFFu, q, o);
    const float inv = rsqrtf(q * (1.0f / 128.0f) + 1e-5f);
    const float4 gg = ((const float4*)g)[lane];
    const float4 bb = ((const float4*)b)[lane];
    float4 o4;
    o4.x = d0 * inv * gg.x + bb.x;
    o4.y = d1 * inv * gg.y + bb.y;
    o4.z = d2 * inv * gg.z + bb.z;
    o4.w = d3 * inv * gg.w + bb.w;
    ((float4*)(g_h + (size_t)node * DD))[lane] = o4;
}

// ---------------- output MLP ----------------
__global__ void k_out(const float* __restrict__ w1, const float* __restrict__ b1,
                      const float* __restrict__ w2, const float* __restrict__ b2,
                      float* __restrict__ out) {
    extern __shared__ float sm[];
    float* sW1  = sm;
    float* sW2  = sW1 + DD * DD;
    float* sX   = sW2 + DD * 3;
    float* sHid = sX + DD;
    const int j = threadIdx.x;  // 128
    for (int i = j; i < DD * DD; i += DD) sW1[i] = w1[i];
    for (int i = j; i < DD * 3; i += DD) sW2[i] = w2[i];
    const float bb1 = b1[j];
    __syncthreads();
    const int n0 = blockIdx.x * 16;
    for (int m = 0; m < 16; ++m) {
        const int n = n0 + m;
        sX[j] = g_h[(size_t)n * DD + j];
        __syncthreads();
        float acc = bb1;
#pragma unroll 8
        for (int k = 0; k < DD; ++k) acc += sX[k] * sW1[k * DD + j];
        sHid[j] = silu_f(acc);
        __syncthreads();
        if (j < 3) {
            float o = b2[j];
            for (int k = 0; k < DD; ++k) o += sHid[k] * sW2[k * 3 + j];
            out[(size_t)n * 3 + j] = o;
        }
        __syncthreads();
    }
}

// ---------------- launch ----------------
extern "C" void kernel_launch(void* const* d_in, const int* in_sizes, int n_in,
                              void* d_out, int out_size) {
    const float* x_t      = (const float*)d_in[0];
    const int*   ei       = (const int*)d_in[1];
    const int*   tp       = (const int*)d_in[2];
    const float* time_w1  = (const float*)d_in[3];
    const float* time_b1  = (const float*)d_in[4];
    const float* time_w2  = (const float*)d_in[5];
    const float* time_b2  = (const float*)d_in[6];
    const float* nodein_w1= (const float*)d_in[7];
    const float* nodein_b1= (const float*)d_in[8];
    const float* nodein_w2= (const float*)d_in[9];
    const float* nodein_b2= (const float*)d_in[10];
    const float* phim_w1  = (const float*)d_in[11];
    const float* phim_b1  = (const float*)d_in[12];
    const float* phim_w2  = (const float*)d_in[13];
    const float* phim_b2  = (const float*)d_in[14];
    const float* phih_w1  = (const float*)d_in[15];
    const float* phih_b1  = (const float*)d_in[16];
    const float* phih_w2  = (const float*)d_in[17];
    const float* phih_b2  = (const float*)d_in[18];
    const float* ln_g     = (const float*)d_in[19];
    const float* ln_b     = (const float*)d_in[20];
    const float* out_w1   = (const float*)d_in[21];
    const float* out_b1   = (const float*)d_in[22];
    const float* out_w2   = (const float*)d_in[23];
    const float* out_b2   = (const float*)d_in[24];
    float* out = (float*)d_out;

    const int SMEM_EDGE = (DD * DD + RR * DD + 128 * ESTR + RR * ESTR) * 4 + 128 * 4;
    const int SMEM_PRE  = (DD * DD + 128 * ATSTR) * 4;
    const int SMEM_NIN  = (DD * DD + 128 * ATSTR + 3 * DD + DD) * 4;
    const int SMEM_NODE = (256 * DD + 128 * NHSTR + 2 * 128 * 16) * 4;
    const int SMEM_OUT  = (DD * DD + DD * 3 + DD + DD) * 4;

    cudaFuncSetAttribute(k_edge,     cudaFuncAttributeMaxDynamicSharedMemorySize, SMEM_EDGE);
    cudaFuncSetAttribute(k_prep,     cudaFuncAttributeMaxDynamicSharedMemorySize, SMEM_PRE);
    cudaFuncSetAttribute(k_scan_nin, cudaFuncAttributeMaxDynamicSharedMemorySize, SMEM_NIN);
    cudaFuncSetAttribute(k_node,     cudaFuncAttributeMaxDynamicSharedMemorySize, SMEM_NODE);
    cudaFuncSetAttribute(k_out,      cudaFuncAttributeMaxDynamicSharedMemorySize, SMEM_OUT);

    const int edgeTiles = EE / 64;           // 10000
    const int nodeTiles = (NN + 127) / 128;  // 157
    const int SCAT = EE / 256;               // 2500

    // launch 0: time MLP + dst histogram
    k_time_hist<<<1 + SCAT, 256>>>(ei, tp, time_w1, time_b1, time_w2, time_b2,
                                   nodein_w1, nodein_b1);
    // launch 1: exclusive scan + node-input MLP
    k_scan_nin<<<1 + PRE_TILES, 256, SMEM_NIN>>>(x_t, nodein_w1, nodein_w2, nodein_b2);

    for (int l = 0; l < LL; ++l) {
        const float* W1l = phim_w1 + (size_t)l * 272 * DD;
        const int scat = (l == 0) ? SCAT : 0;   // sort + rbf once; xs/xd/agg-zero per layer
        // launch 2 (l==0): scatter-sort + rbf + hist-rezero + Xs/Xd + agg-zero
        k_prep<<<scat + 2 * PRE_TILES + 157, 256, SMEM_PRE>>>(
            W1l, W1l + 128 * DD, phim_b1 + (size_t)l * DD, ei, x_t, scat);
        // launch 3 (l==0) -> ncu capture target
        k_edge<<<296, 256, SMEM_EDGE>>>(W1l + 256 * DD,
                                        phim_w2 + (size_t)l * DD * DD,
                                        phim_b2 + (size_t)l * DD,
                                        edgeTiles);
        k_node<<<148, 512, SMEM_NODE>>>(phih_w1 + (size_t)l * 256 * DD,
                                        phih_b1 + (size_t)l * DD,
                                        phih_w2 + (size_t)l * DD * DD,
                                        phih_b2 + (size_t)l * DD,
                                        nodeTiles);
        k_ln<<<(NN * 32 + 255) / 256, 256>>>(ln_g + (size_t)l * DD, ln_b + (size_t)l * DD);
    }

    k_out<<<NN / 16, 128, SMEM_OUT>>>(out_w1, out_b1, out_w2, out_b2, out);
}

// round 13
// speedup vs baseline: 4.2072x; 1.0297x over previous
#include <cuda_runtime.h>
#include <cuda_bf16.h>
#include <cstdint>

#define NN 20000
#define EE 640000
#define DD 128
#define RR 16
#define LL 3

// ---------------- device scratch ----------------
__device__ float g_h   [(size_t)NN * DD];
__device__ float g_agg [(size_t)NN * DD];
__device__ float g_rbf [(size_t)EE * RR];   // in SORTED edge order
__device__ float g_xs  [(size_t)NN * DD];   // h @ Wa + b1
__device__ float g_xd  [(size_t)NN * DD];   // h @ Wb
__device__ float g_base[DD];
// dst-sorted edge structure (rebuilt every call; g_hist re-zeroed by scatter)
__device__ int   g_hist[NN + 1];            // zero-initialized at load
__device__ int   g_woff[NN];
__device__ int   g_ssrc[EE];
__device__ int   g_sdst[EE];

__device__ __forceinline__ float silu_f(float x) {
    return x / (1.0f + __expf(-x));
}

// sm_103a packed fp32 FMA helpers
__device__ __forceinline__ unsigned long long pk2(float lo, float hi) {
    unsigned long long r;
    asm("mov.b64 %0, {%1, %2};" : "=l"(r) : "f"(lo), "f"(hi));
    return r;
}
__device__ __forceinline__ void up2(unsigned long long v, float& lo, float& hi) {
    asm("mov.b64 {%0, %1}, %2;" : "=f"(lo), "=f"(hi) : "l"(v));
}
__device__ __forceinline__ void ffma2(unsigned long long& d, unsigned long long a, unsigned long long b) {
    asm("fma.rn.f32x2 %0, %1, %2, %0;" : "+l"(d) : "l"(a), "l"(b));
}
__device__ __forceinline__ void red_add_f(float* p, float v) {
    asm volatile("red.global.add.f32 [%0], %1;" :: "l"(p), "f"(v) : "memory");
}

// ---------------- launch 0: time MLP (block 0) + dst histogram ----------------
__global__ void k_time_hist(const int* __restrict__ ei, const int* __restrict__ tptr,
                            const float* __restrict__ tw1, const float* __restrict__ tb1,
                            const float* __restrict__ tw2, const float* __restrict__ tb2,
                            const float* __restrict__ nw1, const float* __restrict__ nb1) {
    if (blockIdx.x > 0) {
        const int e = (blockIdx.x - 1) * 256 + threadIdx.x;   // exactly EE threads
        atomicAdd(&g_hist[ei[EE + e]], 1);
        return;
    }
    __shared__ float sE[DD], sH[DD], sTe[DD];
    const int j = threadIdx.x;
    const bool act = (j < DD);
    int iv = *tptr;
    float t = (iv >= 0 && iv < 1000000) ? (float)iv : __int_as_float(iv);
    if (act) {
        int i = (j < 64) ? j : (j - 64);
        float f = __expf(-logf(10000.0f) * (float)i / 63.0f);
        float a = t * f;
        sE[j] = (j < 64) ? sinf(a) : cosf(a);
    }
    __syncthreads();
    if (act) {
        float acc = tb1[j];
        for (int k = 0; k < DD; ++k) acc += sE[k] * tw1[k * DD + j];
        sH[j] = silu_f(acc);
    }
    __syncthreads();
    if (act) {
        float acc2 = tb2[j];
        for (int k = 0; k < DD; ++k) acc2 += sH[k] * tw2[k * DD + j];
        sTe[j] = acc2;
    }
    __syncthreads();
    if (act) {
        float accb = nb1[j];
        for (int k = 0; k < DD; ++k) accb += sTe[k] * nw1[(3 + k) * DD + j];
        g_base[j] = accb;
    }
}

// ================= shared fast-GEMM core pieces =================
#define ATSTR 132

// out = h @ W (+bias), one 128-node tile.
__device__ __forceinline__ void do_pre(const float* __restrict__ W,
                                       const float* __restrict__ bias,
                                       float* __restrict__ out, int tileIdx) {
    extern __shared__ float sm[];
    float* sW  = sm;            // 128*128
    float* sAT = sW + DD * DD;  // 128*ATSTR

    const int tid = threadIdx.x;
    const int tx = tid & 15, ty = tid >> 4;
    const int c0 = tx * 8, r0 = ty * 8;
    const int n0 = tileIdx * 128;

    {
        const float4* w4 = (const float4*)W;
#pragma unroll
        for (int i = 0; i < 16; ++i)
            ((float4*)sW)[tid + i * 256] = w4[tid + i * 256];
    }
#pragma unroll
    for (int i = 0; i < 16; ++i) {
        const int idx = tid + i * 256;
        const int nl = idx >> 5;
        const int q = (idx & 31) * 4;
        int n = n0 + nl; if (n >= NN) n = NN - 1;
        const float4 v = *(const float4*)&g_h[(size_t)n * DD + q];
        const float vv[4] = { v.x, v.y, v.z, v.w };
#pragma unroll
        for (int m = 0; m < 4; ++m) {
            const int k = q + m;
            sAT[k * ATSTR + (nl ^ (((k >> 3) & 7) << 3))] = vv[m];
        }
    }
    __syncthreads();

    unsigned long long acc[8][4];
#pragma unroll
    for (int i = 0; i < 8; ++i)
#pragma unroll
        for (int p = 0; p < 4; ++p) acc[i][p] = 0ull;

    for (int kk = 0; kk < 128; ++kk) {
        const int rs = r0 ^ (((kk >> 3) & 7) << 3);
        const float4 a0 = *(const float4*)&sAT[kk * ATSTR + rs];
        const float4 a1 = *(const float4*)&sAT[kk * ATSTR + rs + 4];
        const ulonglong2 B0 = *(const ulonglong2*)&sW[kk * DD + c0];
        const ulonglong2 B1 = *(const ulonglong2*)&sW[kk * DD + c0 + 4];
        const float a[8] = { a0.x, a0.y, a0.z, a0.w, a1.x, a1.y, a1.z, a1.w };
#pragma unroll
        for (int i = 0; i < 8; ++i) {
            const unsigned long long aa = pk2(a[i], a[i]);
            ffma2(acc[i][0], aa, B0.x);
            ffma2(acc[i][1], aa, B0.y);
            ffma2(acc[i][2], aa, B1.x);
            ffma2(acc[i][3], aa, B1.y);
        }
    }

    float bv[8];
#pragma unroll
    for (int j = 0; j < 8; ++j) bv[j] = bias ? bias[c0 + j] : 0.0f;
#pragma unroll
    for (int i = 0; i < 8; ++i) {
        const int n = n0 + r0 + i;
        if (n < NN) {
            float o[8];
#pragma unroll
            for (int p = 0; p < 4; ++p) {
                float x, y; up2(acc[i][p], x, y);
                o[2 * p] = x + bv[2 * p]; o[2 * p + 1] = y + bv[2 * p + 1];
            }
            *(float4*)&out[(size_t)n * DD + c0]     = make_float4(o[0], o[1], o[2], o[3]);
            *(float4*)&out[(size_t)n * DD + c0 + 4] = make_float4(o[4], o[5], o[6], o[7]);
        }
    }
}

// ---------------- launch 1: scan (block 0) + node-input MLP (blocks 1..157) ----------------
__global__ __launch_bounds__(256, 1)
void k_scan_nin(const float* __restrict__ xt,
                const float* __restrict__ w1,   // [131][128]
                const float* __restrict__ w2,   // [128][128]
                const float* __restrict__ b2) {
    extern __shared__ float sm[];
    if (blockIdx.x == 0) {
        int* ip = (int*)sm;  // 256 partials
        const int t = threadIdx.x;
        const int per = 79;
        const int start = t * per;
        int sum = 0;
        for (int i = 0; i < per; ++i) {
            const int idx = start + i;
            if (idx < NN) sum += g_hist[idx];
        }
        ip[t] = sum;
        __syncthreads();
        if (t == 0) {
            int run = 0;
            for (int i = 0; i < 256; ++i) { int v = ip[i]; ip[i] = run; run += v; }
        }
        __syncthreads();
        int run = ip[t];
        for (int i = 0; i < per; ++i) {
            const int idx = start + i;
            if (idx < NN) { int v = g_hist[idx]; g_woff[idx] = run; run += v; }
        }
        return;
    }
    // ---- node input MLP tile ----
    float* sW    = sm;                      // 128*128
    float* sAT   = sW + DD * DD;            // 128*ATSTR
    float* sW1x  = sAT + 128 * ATSTR;       // 3*128
    float* sBase = sW1x + 3 * DD;           // 128

    const int tid = threadIdx.x;
    const int tx = tid & 15, ty = tid >> 4;
    const int c0 = tx * 8, r0 = ty * 8;
    const int n0 = (blockIdx.x - 1) * 128;

    {
        const float4* w4 = (const float4*)w2;
#pragma unroll
        for (int i = 0; i < 16; ++i)
            ((float4*)sW)[tid + i * 256] = w4[tid + i * 256];
    }
    if (tid < 128) {
        sW1x[tid]       = w1[tid];
        sW1x[128 + tid] = w1[128 + tid];
        sW1x[256 + tid] = w1[256 + tid];
        sBase[tid]      = g_base[tid];
    }
    __syncthreads();

#pragma unroll
    for (int i = 0; i < 16; ++i) {
        const int idx = tid + i * 256;
        const int nl = idx >> 5;
        const int q = (idx & 31) * 4;
        int n = n0 + nl; if (n >= NN) n = NN - 1;
        const float x0 = xt[n * 3 + 0], x1 = xt[n * 3 + 1], x2 = xt[n * 3 + 2];
#pragma unroll
        for (int m = 0; m < 4; ++m) {
            const int k = q + m;
            const float v = silu_f(sBase[k] + x0 * sW1x[k] + x1 * sW1x[128 + k] + x2 * sW1x[256 + k]);
            sAT[k * ATSTR + (nl ^ (((k >> 3) & 7) << 3))] = v;
        }
    }
    __syncthreads();

    unsigned long long acc[8][4];
#pragma unroll
    for (int i = 0; i < 8; ++i)
#pragma unroll
        for (int p = 0; p < 4; ++p) acc[i][p] = 0ull;

    for (int kk = 0; kk < 128; ++kk) {
        const int rs = r0 ^ (((kk >> 3) & 7) << 3);
        const float4 a0 = *(const float4*)&sAT[kk * ATSTR + rs];
        const float4 a1 = *(const float4*)&sAT[kk * ATSTR + rs + 4];
        const ulonglong2 B0 = *(const ulonglong2*)&sW[kk * DD + c0];
        const ulonglong2 B1 = *(const ulonglong2*)&sW[kk * DD + c0 + 4];
        const float a[8] = { a0.x, a0.y, a0.z, a0.w, a1.x, a1.y, a1.z, a1.w };
#pragma unroll
        for (int i = 0; i < 8; ++i) {
            const unsigned long long aa = pk2(a[i], a[i]);
            ffma2(acc[i][0], aa, B0.x);
            ffma2(acc[i][1], aa, B0.y);
            ffma2(acc[i][2], aa, B1.x);
            ffma2(acc[i][3], aa, B1.y);
        }
    }

    float bv[8];
#pragma unroll
    for (int j = 0; j < 8; ++j) bv[j] = b2[c0 + j];
#pragma unroll
    for (int i = 0; i < 8; ++i) {
        const int n = n0 + r0 + i;
        if (n < NN) {
            float o[8];
#pragma unroll
            for (int p = 0; p < 4; ++p) {
                float x, y; up2(acc[i][p], x, y);
                o[2 * p] = x + bv[2 * p]; o[2 * p + 1] = y + bv[2 * p + 1];
            }
            *(float4*)&g_h[(size_t)n * DD + c0]     = make_float4(o[0], o[1], o[2], o[3]);
            *(float4*)&g_h[(size_t)n * DD + c0 + 4] = make_float4(o[4], o[5], o[6], o[7]);
        }
    }
}

// ================= per-layer prologue =================
#define PRE_TILES 157
__global__ __launch_bounds__(256, 1)
void k_prep(const float* __restrict__ Wa, const float* __restrict__ Wb,
            const float* __restrict__ b1,
            const int* __restrict__ ei, const float* __restrict__ xt,
            int scatBlocks) {
    int bx = blockIdx.x;
    if (bx < scatBlocks) {
        const int e = bx * 256 + threadIdx.x;        // exactly EE threads
        if (e <= NN) g_hist[e] = 0;                  // re-zero for next call
        const int s = ei[e], d = ei[EE + e];
        const int pos = atomicAdd(&g_woff[d], 1);
        g_ssrc[pos] = s;
        g_sdst[pos] = d;
        const float dx = xt[s * 3 + 0] - xt[d * 3 + 0];
        const float dy = xt[s * 3 + 1] - xt[d * 3 + 1];
        const float r = sqrtf(dx * dx + dy * dy + 1e-8f);
        const float step = 1.41421356237309515f / 15.0f;
        const float gamma = 1.0f / (2.0f * step * step);
#pragma unroll
        for (int c = 0; c < RR; ++c) {
            float u = r - (float)c * step;
            g_rbf[(size_t)pos * RR + c] = __expf(-gamma * u * u);
        }
        return;
    }
    bx -= scatBlocks;
    if (bx < 2 * PRE_TILES) {
        const int sel = (bx >= PRE_TILES);
        do_pre(sel ? Wb : Wa, sel ? nullptr : b1, sel ? g_xd : g_xs,
               sel ? bx - PRE_TILES : bx);
        return;
    }
    bx -= 2 * PRE_TILES;
    // zero g_agg
    const int base = bx * 16384 + threadIdx.x * 4;
#pragma unroll
    for (int k = 0; k < 16; ++k) {
        const int i = base + k * 1024;
        if (i < NN * DD) *(float4*)&g_agg[i] = make_float4(0.f, 0.f, 0.f, 0.f);
    }
}

// ================= fused edge kernel v5: dst-sorted 64-edge tiles, 2 CTAs/SM,
// square warp tiles, cross-tile index prefetch, hoisted swizzle, segment scatter ===
#define ESTR 68
#define OSTR 132
__global__ __launch_bounds__(256, 2)
void k_edge(const float* __restrict__ Wr,   // [16][128]
            const float* __restrict__ w2,   // [128][128]
            const float* __restrict__ b2,
            int numTiles) {
    extern __shared__ float sm[];
    float* sW2   = sm;                        // 128*128
    float* sWr   = sW2 + DD * DD;             // 16*128
    float* sHidT = sWr + RR * DD;             // 128*ESTR (transposed, swizzled); reused as sOut
    float* sRbfT = sHidT + 128 * ESTR;        // 16*ESTR
    int*   sDst  = (int*)(sRbfT + RR * ESTR); // 64

    const int tid = threadIdx.x;
    const int w    = tid >> 5;
    const int lane = tid & 31;
    const int ly   = lane >> 2;
    const int lx   = lane & 3;
    const int r0 = (w & 1) * 32 + ly * 4;
    const int c0 = (w >> 1) * 32 + lx * 8;
    const int sw0 = (c0 >> 3) & 7;

    {
        const float4* w4 = (const float4*)w2;
#pragma unroll
        for (int i = 0; i < 16; ++i)
            ((float4*)sW2)[tid + i * 256] = w4[tid + i * 256];
        const float4* wr4 = (const float4*)Wr;
#pragma unroll
        for (int i = 0; i < 2; ++i)
            ((float4*)sWr)[tid + i * 256] = wr4[tid + i * 256];
    }
    float bias2[8];
#pragma unroll
    for (int j = 0; j < 8; ++j) bias2[j] = b2[c0 + j];

    // prefetch first tile's per-thread src/dst indices
    int psrc[4], pdst[4];
    int tile = blockIdx.x;
    if (tile < numTiles) {
#pragma unroll
        for (int i = 0; i < 4; ++i) {
            psrc[i] = g_ssrc[tile * 64 + r0 + i];
            pdst[i] = g_sdst[tile * 64 + r0 + i];
        }
    }

    for (; tile < numTiles; tile += gridDim.x) {
        const int e0 = tile * 64;
        __syncthreads();  // protect smem from previous tile's readers

        // gather Xs[src]+Xd[dst] using PREFETCHED indices — issues immediately,
        // overlapping staging + phase 1 (dst sorted -> Xd hits L1)
        float xsv[4][8];
#pragma unroll
        for (int i = 0; i < 4; ++i) {
            const float4 a0 = *(const float4*)&g_xs[(size_t)psrc[i] * DD + c0];
            const float4 a1 = *(const float4*)&g_xs[(size_t)psrc[i] * DD + c0 + 4];
            const float4 b0 = *(const float4*)&g_xd[(size_t)pdst[i] * DD + c0];
            const float4 b1 = *(const float4*)&g_xd[(size_t)pdst[i] * DD + c0 + 4];
            xsv[i][0] = a0.x + b0.x; xsv[i][1] = a0.y + b0.y;
            xsv[i][2] = a0.z + b0.z; xsv[i][3] = a0.w + b0.w;
            xsv[i][4] = a1.x + b1.x; xsv[i][5] = a1.y + b1.y;
            xsv[i][6] = a1.z + b1.z; xsv[i][7] = a1.w + b1.w;
        }

        // stage dst (for segment reduce) and rbf (transposed)
        if (tid < 64) sDst[tid] = g_sdst[e0 + tid];
        {
            const int row = tid & 63, c4 = (tid >> 6) * 4;
            const float4 v = *(const float4*)&g_rbf[(size_t)(e0 + row) * RR + c4];
            sRbfT[(c4 + 0) * ESTR + row] = v.x;
            sRbfT[(c4 + 1) * ESTR + row] = v.y;
            sRbfT[(c4 + 2) * ESTR + row] = v.z;
            sRbfT[(c4 + 3) * ESTR + row] = v.w;
        }
        __syncthreads();

        // phase 1: K=16 rbf GEMM (covers the gather latency)
        unsigned long long acc[4][4];
#pragma unroll
        for (int i = 0; i < 4; ++i)
#pragma unroll
            for (int p = 0; p < 4; ++p) acc[i][p] = 0ull;
#pragma unroll
        for (int kk = 0; kk < 16; ++kk) {
            const float4 av = *(const float4*)&sRbfT[kk * ESTR + r0];
            const ulonglong2 B0 = *(const ulonglong2*)&sWr[kk * DD + c0];
            const ulonglong2 B1 = *(const ulonglong2*)&sWr[kk * DD + c0 + 4];
            const float a[4] = { av.x, av.y, av.z, av.w };
#pragma unroll
            for (int i = 0; i < 4; ++i) {
                const unsigned long long aa = pk2(a[i], a[i]);
                ffma2(acc[i][0], aa, B0.x);
                ffma2(acc[i][1], aa, B0.y);
                ffma2(acc[i][2], aa, B1.x);
                ffma2(acc[i][3], aa, B1.y);
            }
        }

        // epilogue 1: silu(acc + xsv) -> sHidT (transposed, XOR-swizzled rows)
        {
            float o[4][8];
#pragma unroll
            for (int i = 0; i < 4; ++i) {
                float x, y;
                up2(acc[i][0], x, y); o[i][0] = silu_f(x + xsv[i][0]); o[i][1] = silu_f(y + xsv[i][1]);
                up2(acc[i][1], x, y); o[i][2] = silu_f(x + xsv[i][2]); o[i][3] = silu_f(y + xsv[i][3]);
                up2(acc[i][2], x, y); o[i][4] = silu_f(x + xsv[i][4]); o[i][5] = silu_f(y + xsv[i][5]);
                up2(acc[i][3], x, y); o[i][6] = silu_f(x + xsv[i][6]); o[i][7] = silu_f(y + xsv[i][7]);
#pragma unroll
                for (int p = 0; p < 4; ++p) acc[i][p] = 0ull;
            }
            const int rs0 = r0 ^ (sw0 << 3);
#pragma unroll
            for (int jj = 0; jj < 8; ++jj) {
                *(float4*)&sHidT[(c0 + jj) * ESTR + rs0] =
                    make_float4(o[0][jj], o[1][jj], o[2][jj], o[3][jj]);
            }
        }
        __syncthreads();

        // prefetch NEXT tile's indices — fully hidden under GEMM2
        {
            const int nt = tile + gridDim.x;
            if (nt < numTiles) {
#pragma unroll
                for (int i = 0; i < 4; ++i) {
                    psrc[i] = g_ssrc[nt * 64 + r0 + i];
                    pdst[i] = g_sdst[nt * 64 + r0 + i];
                }
            }
        }

        // phase 2: K=128 GEMM2, swizzle hoisted per 8-kk block
#pragma unroll 2
        for (int kb = 0; kb < 16; ++kb) {
            const int rs = r0 ^ ((kb & 7) << 3);
            const float* hbase = &sHidT[kb * 8 * ESTR + rs];
            const float* wbase = &sW2[kb * 8 * DD + c0];
#pragma unroll
            for (int kq = 0; kq < 8; ++kq) {
                const float4 av = *(const float4*)&hbase[kq * ESTR];
                const ulonglong2 B0 = *(const ulonglong2*)&wbase[kq * DD];
                const ulonglong2 B1 = *(const ulonglong2*)&wbase[kq * DD + 4];
                const float a[4] = { av.x, av.y, av.z, av.w };
#pragma unroll
                for (int i = 0; i < 4; ++i) {
                    const unsigned long long aa = pk2(a[i], a[i]);
                    ffma2(acc[i][0], aa, B0.x);
                    ffma2(acc[i][1], aa, B0.y);
                    ffma2(acc[i][2], aa, B1.x);
                    ffma2(acc[i][3], aa, B1.y);
                }
            }
        }
        __syncthreads();  // all GEMM2 reads of sHidT complete before overwrite

        // epilogue 2a: write messages (+bias) to smem tile (reuse sHidT region)
        float* sOut = sHidT;  // 64 rows x OSTR
#pragma unroll
        for (int i = 0; i < 4; ++i) {
            float x0, y0, x1, y1;
            up2(acc[i][0], x0, y0); up2(acc[i][1], x1, y1);
            *(float4*)&sOut[(r0 + i) * OSTR + c0] =
                make_float4(x0 + bias2[0], y0 + bias2[1], x1 + bias2[2], y1 + bias2[3]);
            up2(acc[i][2], x0, y0); up2(acc[i][3], x1, y1);
            *(float4*)&sOut[(r0 + i) * OSTR + c0 + 4] =
                make_float4(x0 + bias2[4], y0 + bias2[5], x1 + bias2[6], y1 + bias2[7]);
        }
        __syncthreads();

        // epilogue 2b: segment-sum over sorted dst, one red per (segment, col)
        {
            const int col  = tid & 127;
            const int rbeg = (tid >> 7) * 32;
            float a2 = 0.0f;
            int prev = sDst[rbeg];
            for (int r = rbeg; r < rbeg + 32; ++r) {
                const int d = sDst[r];
                if (d != prev) {
                    red_add_f(&g_agg[(size_t)prev * DD + col], a2);
                    a2 = 0.0f; prev = d;
                }
                a2 += sOut[r * OSTR + col];
            }
            red_add_f(&g_agg[(size_t)prev * DD + col], a2);
        }
    }
}

// ================= node update MLP + residual + FUSED LayerNorm -> g_h =================
#define NHSTR 132
__global__ __launch_bounds__(512, 1)
void k_node(const float* __restrict__ w1, const float* __restrict__ b1,
            const float* __restrict__ w2, const float* __restrict__ b2,
            const float* __restrict__ lng, const float* __restrict__ lnb,
            int numTiles) {
    extern __shared__ float sm[];
    float* sW1  = sm;                           // 256*128
    float* sHid = sW1 + 256 * DD;               // 128*NHSTR
    float* sA0  = sHid + 128 * NHSTR;           // 128*16
    float* sA1  = sA0 + 128 * 16;               // 128*16

    const int tid = threadIdx.x;
    const int c0 = (tid & 15) * 8;
    const int r0 = (tid >> 4) * 4;
    const int gr = tid >> 2;
    const int gq = (tid & 3) * 4;
    const int wN = tid >> 5, lane = tid & 31;

    for (int i = tid; i < 256 * DD; i += 512) sW1[i] = w1[i];
    float bias1[8], bias2[8];
#pragma unroll
    for (int j = 0; j < 8; ++j) { bias1[j] = b1[c0 + j]; bias2[j] = b2[c0 + j]; }
    const float4 gg4 = *(const float4*)&lng[lane * 4];
    const float4 bb4 = *(const float4*)&lnb[lane * 4];

    float* bufs[2] = { sA0, sA1 };

    for (int tile = blockIdx.x; tile < numTiles; tile += gridDim.x) {
        const int n0 = tile * 128;
        int gn = n0 + gr; if (gn >= NN) gn = NN - 1;
        unsigned long long acc[4][4];
#pragma unroll
        for (int i = 0; i < 4; ++i)
#pragma unroll
            for (int p = 0; p < 4; ++p) acc[i][p] = 0ull;
        __syncthreads();

        {
            float4 v = *(const float4*)&g_h[(size_t)gn * DD + gq];
            *(float4*)&bufs[0][gr * 16 + gq] = v;
        }
        __syncthreads();

        for (int kc = 0; kc < 16; ++kc) {
            float4 nv;
            if (kc < 15) {
                const int k = (kc + 1) * 16 + gq;
                if (k < 128) nv = *(const float4*)&g_h[(size_t)gn * DD + k];
                else         nv = *(const float4*)&g_agg[(size_t)gn * DD + (k - 128)];
            }
            const float* A = bufs[kc & 1];
            const int kbase = kc * 16;
#pragma unroll
            for (int kk = 0; kk < 16; ++kk) {
                const float* wrow = &sW1[(kbase + kk) * DD + c0];
                const ulonglong2 B0 = *(const ulonglong2*)wrow;
                const ulonglong2 B1 = *(const ulonglong2*)(wrow + 4);
#pragma unroll
                for (int i = 0; i < 4; ++i) {
                    const float a = A[(r0 + i) * 16 + kk];
                    const unsigned long long aa = pk2(a, a);
                    ffma2(acc[i][0], aa, B0.x);
                    ffma2(acc[i][1], aa, B0.y);
                    ffma2(acc[i][2], aa, B1.x);
                    ffma2(acc[i][3], aa, B1.y);
                }
            }
            if (kc < 15) *(float4*)&bufs[(kc + 1) & 1][gr * 16 + gq] = nv;
            __syncthreads();
        }

        {
            float4 w2v = *(const float4*)&w2[tid * 4];
#pragma unroll
            for (int i = 0; i < 4; ++i) {
                float* hrow = &sHid[(r0 + i) * NHSTR + c0];
                float o[8];
#pragma unroll
                for (int p = 0; p < 4; ++p) {
                    float x, y; up2(acc[i][p], x, y);
                    o[2 * p]     = silu_f(x + bias1[2 * p]);
                    o[2 * p + 1] = silu_f(y + bias1[2 * p + 1]);
                    acc[i][p] = 0ull;
                }
                *(float4*)&hrow[0] = make_float4(o[0], o[1], o[2], o[3]);
                *(float4*)&hrow[4] = make_float4(o[4], o[5], o[6], o[7]);
            }
            *(float4*)&bufs[0][tid * 4] = w2v;
        }
        __syncthreads();

        for (int kc = 0; kc < 8; ++kc) {
            float4 nv;
            if (kc < 7) nv = *(const float4*)&w2[(size_t)(kc + 1) * 16 * DD + tid * 4];
            const float* Bc = bufs[kc & 1];
            const int kbase = kc * 16;
#pragma unroll
            for (int kk = 0; kk < 16; ++kk) {
                const float* wrow = &Bc[kk * DD + c0];
                const ulonglong2 B0 = *(const ulonglong2*)wrow;
                const ulonglong2 B1 = *(const ulonglong2*)(wrow + 4);
#pragma unroll
                for (int i = 0; i < 4; ++i) {
                    const float a = sHid[(r0 + i) * NHSTR + kbase + kk];
                    const unsigned long long aa = pk2(a, a);
                    ffma2(acc[i][0], aa, B0.x);
                    ffma2(acc[i][1], aa, B0.y);
                    ffma2(acc[i][2], aa, B1.x);
                    ffma2(acc[i][3], aa, B1.y);
                }
            }
            if (kc < 7) *(float4*)&bufs[(kc + 1) & 1][tid * 4] = nv;
            __syncthreads();
        }
        __syncthreads();  // all GEMM2 reads of sHid done before overwrite

        // epilogue: bias + residual -> sHid rows (full 128-col rows per tile)
#pragma unroll
        for (int i = 0; i < 4; ++i) {
            const int n = n0 + r0 + i;
            const int nc = (n < NN) ? n : (NN - 1);
            const float4 h0 = *(const float4*)&g_h[(size_t)nc * DD + c0];
            const float4 h1 = *(const float4*)&g_h[(size_t)nc * DD + c0 + 4];
            float o[8];
#pragma unroll
            for (int p = 0; p < 4; ++p) {
                float x, y; up2(acc[i][p], x, y);
                o[2 * p]     = x + bias2[2 * p];
                o[2 * p + 1] = y + bias2[2 * p + 1];
            }
            *(float4*)&sHid[(r0 + i) * NHSTR + c0] =
                make_float4(o[0] + h0.x, o[1] + h0.y, o[2] + h0.z, o[3] + h0.w);
            *(float4*)&sHid[(r0 + i) * NHSTR + c0 + 4] =
                make_float4(o[4] + h1.x, o[5] + h1.y, o[6] + h1.z, o[7] + h1.w);
        }
        __syncthreads();

        // fused LayerNorm: warp per row (16 warps x 8 rows)
#pragma unroll
        for (int j = 0; j < 8; ++j) {
            const int row = wN * 8 + j;
            const int n = n0 + row;
            if (n < NN) {
                const float4 v = *(const float4*)&sHid[row * NHSTR + lane * 4];
                float s = v.x + v.y + v.z + v.w;
#pragma unroll
                for (int o = 16; o; o >>= 1) s += __shfl_xor_sync(0xFFFFFFFFu, s, o);
                const float mu = s * (1.0f / 128.0f);
                const float d0 = v.x - mu, d1 = v.y - mu, d2 = v.z - mu, d3 = v.w - mu;
                float q = d0 * d0 + d1 * d1 + d2 * d2 + d3 * d3;
#pragma unroll
                for (int o = 16; o; o >>= 1) q += __shfl_xor_sync(0xFFFFFFFFu, q, o);
                const float inv = rsqrtf(q * (1.0f / 128.0f) + 1e-5f);
                float4 o4;
                o4.x = d0 * inv * gg4.x + bb4.x;
                o4.y = d1 * inv * gg4.y + bb4.y;
                o4.z = d2 * inv * gg4.z + bb4.z;
                o4.w = d3 * inv * gg4.w + bb4.w;
                *(float4*)&g_h[(size_t)n * DD + lane * 4] = o4;
            }
        }
    }
}

// ---------------- output MLP ----------------
__global__ void k_out(const float* __restrict__ w1, const float* __restrict__ b1,
                      const float* __restrict__ w2, const float* __restrict__ b2,
                      float* __restrict__ out) {
    extern __shared__ float sm[];
    float* sW1  = sm;
    float* sW2  = sW1 + DD * DD;
    float* sX   = sW2 + DD * 3;
    float* sHid = sX + DD;
    const int j = threadIdx.x;  // 128
    for (int i = j; i < DD * DD; i += DD) sW1[i] = w1[i];
    for (int i = j; i < DD * 3; i += DD) sW2[i] = w2[i];
    const float bb1 = b1[j];
    __syncthreads();
    const int n0 = blockIdx.x * 16;
    for (int m = 0; m < 16; ++m) {
        const int n = n0 + m;
        sX[j] = g_h[(size_t)n * DD + j];
        __syncthreads();
        float acc = bb1;
#pragma unroll 8
        for (int k = 0; k < DD; ++k) acc += sX[k] * sW1[k * DD + j];
        sHid[j] = silu_f(acc);
        __syncthreads();
        if (j < 3) {
            float o = b2[j];
            for (int k = 0; k < DD; ++k) o += sHid[k] * sW2[k * 3 + j];
            out[(size_t)n * 3 + j] = o;
        }
        __syncthreads();
    }
}

// ---------------- launch ----------------
extern "C" void kernel_launch(void* const* d_in, const int* in_sizes, int n_in,
                              void* d_out, int out_size) {
    const float* x_t      = (const float*)d_in[0];
    const int*   ei       = (const int*)d_in[1];
    const int*   tp       = (const int*)d_in[2];
    const float* time_w1  = (const float*)d_in[3];
    const float* time_b1  = (const float*)d_in[4];
    const float* time_w2  = (const float*)d_in[5];
    const float* time_b2  = (const float*)d_in[6];
    const float* nodein_w1= (const float*)d_in[7];
    const float* nodein_b1= (const float*)d_in[8];
    const float* nodein_w2= (const float*)d_in[9];
    const float* nodein_b2= (const float*)d_in[10];
    const float* phim_w1  = (const float*)d_in[11];
    const float* phim_b1  = (const float*)d_in[12];
    const float* phim_w2  = (const float*)d_in[13];
    const float* phim_b2  = (const float*)d_in[14];
    const float* phih_w1  = (const float*)d_in[15];
    const float* phih_b1  = (const float*)d_in[16];
    const float* phih_w2  = (const float*)d_in[17];
    const float* phih_b2  = (const float*)d_in[18];
    const float* ln_g     = (const float*)d_in[19];
    const float* ln_b     = (const float*)d_in[20];
    const float* out_w1   = (const float*)d_in[21];
    const float* out_b1   = (const float*)d_in[22];
    const float* out_w2   = (const float*)d_in[23];
    const float* out_b2   = (const float*)d_in[24];
    float* out = (float*)d_out;

    const int SMEM_EDGE = (DD * DD + RR * DD + 128 * ESTR + RR * ESTR) * 4 + 128 * 4;
    const int SMEM_PRE  = (DD * DD + 128 * ATSTR) * 4;
    const int SMEM_NIN  = (DD * DD + 128 * ATSTR + 3 * DD + DD) * 4;
    const int SMEM_NODE = (256 * DD + 128 * NHSTR + 2 * 128 * 16) * 4;
    const int SMEM_OUT  = (DD * DD + DD * 3 + DD + DD) * 4;

    cudaFuncSetAttribute(k_edge,     cudaFuncAttributeMaxDynamicSharedMemorySize, SMEM_EDGE);
    cudaFuncSetAttribute(k_prep,     cudaFuncAttributeMaxDynamicSharedMemorySize, SMEM_PRE);
    cudaFuncSetAttribute(k_scan_nin, cudaFuncAttributeMaxDynamicSharedMemorySize, SMEM_NIN);
    cudaFuncSetAttribute(k_node,     cudaFuncAttributeMaxDynamicSharedMemorySize, SMEM_NODE);
    cudaFuncSetAttribute(k_out,      cudaFuncAttributeMaxDynamicSharedMemorySize, SMEM_OUT);

    const int edgeTiles = EE / 64;           // 10000
    const int nodeTiles = (NN + 127) / 128;  // 157
    const int SCAT = EE / 256;               // 2500

    // launch 0: time MLP + dst histogram
    k_time_hist<<<1 + SCAT, 256>>>(ei, tp, time_w1, time_b1, time_w2, time_b2,
                                   nodein_w1, nodein_b1);
    // launch 1: exclusive scan + node-input MLP
    k_scan_nin<<<1 + PRE_TILES, 256, SMEM_NIN>>>(x_t, nodein_w1, nodein_w2, nodein_b2);

    for (int l = 0; l < LL; ++l) {
        const float* W1l = phim_w1 + (size_t)l * 272 * DD;
        const int scat = (l == 0) ? SCAT : 0;   // sort + rbf once; xs/xd/agg-zero per layer
        k_prep<<<scat + 2 * PRE_TILES + 157, 256, SMEM_PRE>>>(
            W1l, W1l + 128 * DD, phim_b1 + (size_t)l * DD, ei, x_t, scat);
        // launch 3 (l==0) -> ncu capture target
        k_edge<<<296, 256, SMEM_EDGE>>>(W1l + 256 * DD,
                                        phim_w2 + (size_t)l * DD * DD,
                                        phim_b2 + (size_t)l * DD,
                                        edgeTiles);
        k_node<<<148, 512, SMEM_NODE>>>(phih_w1 + (size_t)l * 256 * DD,
                                        phih_b1 + (size_t)l * DD,
                                        phih_w2 + (size_t)l * DD * DD,
                                        phih_b2 + (size_t)l * DD,
                                        ln_g + (size_t)l * DD, ln_b + (size_t)l * DD,
                                        nodeTiles);
    }

    k_out<<<NN / 16, 128, SMEM_OUT>>>(out_w1, out_b1, out_w2, out_b2, out);
}

// round 15
// speedup vs baseline: 5.7588x; 1.3688x over previous
#include <cuda_runtime.h>
#include <cuda_bf16.h>
#include <cstdint>

#define NN 20000
#define EE 640000
#define DD 128
#define RR 16
#define LL 3

// ---------------- device scratch ----------------
__device__ float g_h   [(size_t)NN * DD];
__device__ float g_agg [(size_t)NN * DD];
__device__ float g_rbf [(size_t)EE * RR];   // in SORTED edge order
__device__ float g_xs  [(size_t)NN * DD];
__device__ float g_xd  [(size_t)NN * DD];
__device__ float g_base[DD];
__device__ int   g_hist[NN + 1];            // zero-initialized at load
__device__ int   g_woff[NN];
__device__ int   g_ssrc[EE];
__device__ int   g_sdst[EE];
// per-layer W2^T bf16 hi/lo in swizzled [n][k] layout (32KB each)
__device__ uint4 g_w2hi[2048];
__device__ uint4 g_w2lo[2048];

__device__ __forceinline__ float silu_f(float x) {
    return x / (1.0f + __expf(-x));
}

// sm_103a packed fp32 FMA helpers
__device__ __forceinline__ unsigned long long pk2(float lo, float hi) {
    unsigned long long r;
    asm("mov.b64 %0, {%1, %2};" : "=l"(r) : "f"(lo), "f"(hi));
    return r;
}
__device__ __forceinline__ void up2(unsigned long long v, float& lo, float& hi) {
    asm("mov.b64 {%0, %1}, %2;" : "=f"(lo), "=f"(hi) : "l"(v));
}
__device__ __forceinline__ void ffma2(unsigned long long& d, unsigned long long a, unsigned long long b) {
    asm("fma.rn.f32x2 %0, %1, %2, %0;" : "+l"(d) : "l"(a), "l"(b));
}
__device__ __forceinline__ void red_add_v2(float* p, float a, float b) {
    asm volatile("red.global.add.v2.f32 [%0], {%1, %2};" :: "l"(p), "f"(a), "f"(b) : "memory");
}

// ---------------- mma.sync / ldmatrix helpers (plain sm_103 features) ----------------
__device__ __forceinline__ uint32_t smem_u32(const void* p) {
    uint32_t a;
    asm("{ .reg .u64 t; cvta.to.shared.u64 t, %1; cvt.u32.u64 %0, t; }" : "=r"(a) : "l"(p));
    return a;
}
__device__ __forceinline__ void ldsm4(uint32_t* r, uint32_t addr) {
    asm volatile("ldmatrix.sync.aligned.m8n8.x4.shared.b16 {%0,%1,%2,%3}, [%4];"
                 : "=r"(r[0]), "=r"(r[1]), "=r"(r[2]), "=r"(r[3]) : "r"(addr));
}
__device__ __forceinline__ void ldsm2(uint32_t* r, uint32_t addr) {
    asm volatile("ldmatrix.sync.aligned.m8n8.x2.shared.b16 {%0,%1}, [%2];"
                 : "=r"(r[0]), "=r"(r[1]) : "r"(addr));
}
__device__ __forceinline__ void mma16816(float* c, const uint32_t* a, const uint32_t* b) {
    asm volatile("mma.sync.aligned.m16n8k16.row.col.f32.bf16.bf16.f32 "
                 "{%0,%1,%2,%3}, {%4,%5,%6,%7}, {%8,%9}, {%0,%1,%2,%3};"
                 : "+f"(c[0]), "+f"(c[1]), "+f"(c[2]), "+f"(c[3])
                 : "r"(a[0]), "r"(a[1]), "r"(a[2]), "r"(a[3]), "r"(b[0]), "r"(b[1]));
}

// ---------------- launch 0: time MLP (block 0) + dst histogram ----------------
__global__ void k_time_hist(const int* __restrict__ ei, const int* __restrict__ tptr,
                            const float* __restrict__ tw1, const float* __restrict__ tb1,
                            const float* __restrict__ tw2, const float* __restrict__ tb2,
                            const float* __restrict__ nw1, const float* __restrict__ nb1) {
    if (blockIdx.x > 0) {
        const int e = (blockIdx.x - 1) * 256 + threadIdx.x;
        atomicAdd(&g_hist[ei[EE + e]], 1);
        return;
    }
    __shared__ float sE[DD], sH[DD], sTe[DD];
    const int j = threadIdx.x;
    const bool act = (j < DD);
    int iv = *tptr;
    float t = (iv >= 0 && iv < 1000000) ? (float)iv : __int_as_float(iv);
    if (act) {
        int i = (j < 64) ? j : (j - 64);
        float f = __expf(-logf(10000.0f) * (float)i / 63.0f);
        float a = t * f;
        sE[j] = (j < 64) ? sinf(a) : cosf(a);
    }
    __syncthreads();
    if (act) {
        float acc = tb1[j];
        for (int k = 0; k < DD; ++k) acc += sE[k] * tw1[k * DD + j];
        sH[j] = silu_f(acc);
    }
    __syncthreads();
    if (act) {
        float acc2 = tb2[j];
        for (int k = 0; k < DD; ++k) acc2 += sH[k] * tw2[k * DD + j];
        sTe[j] = acc2;
    }
    __syncthreads();
    if (act) {
        float accb = nb1[j];
        for (int k = 0; k < DD; ++k) accb += sTe[k] * nw1[(3 + k) * DD + j];
        g_base[j] = accb;
    }
}

// ================= fp32 fast-GEMM core =================
#define ATSTR 132

__device__ __forceinline__ void do_pre(const float* __restrict__ W,
                                       const float* __restrict__ bias,
                                       float* __restrict__ out, int tileIdx) {
    extern __shared__ float sm[];
    float* sW  = sm;
    float* sAT = sW + DD * DD;

    const int tid = threadIdx.x;
    const int tx = tid & 15, ty = tid >> 4;
    const int c0 = tx * 8, r0 = ty * 8;
    const int n0 = tileIdx * 128;

    {
        const float4* w4 = (const float4*)W;
#pragma unroll
        for (int i = 0; i < 16; ++i)
            ((float4*)sW)[tid + i * 256] = w4[tid + i * 256];
    }
#pragma unroll
    for (int i = 0; i < 16; ++i) {
        const int idx = tid + i * 256;
        const int nl = idx >> 5;
        const int q = (idx & 31) * 4;
        int n = n0 + nl; if (n >= NN) n = NN - 1;
        const float4 v = *(const float4*)&g_h[(size_t)n * DD + q];
        const float vv[4] = { v.x, v.y, v.z, v.w };
#pragma unroll
        for (int m = 0; m < 4; ++m) {
            const int k = q + m;
            sAT[k * ATSTR + (nl ^ (((k >> 3) & 7) << 3))] = vv[m];
        }
    }
    __syncthreads();

    unsigned long long acc[8][4];
#pragma unroll
    for (int i = 0; i < 8; ++i)
#pragma unroll
        for (int p = 0; p < 4; ++p) acc[i][p] = 0ull;

    for (int kk = 0; kk < 128; ++kk) {
        const int rs = r0 ^ (((kk >> 3) & 7) << 3);
        const float4 a0 = *(const float4*)&sAT[kk * ATSTR + rs];
        const float4 a1 = *(const float4*)&sAT[kk * ATSTR + rs + 4];
        const ulonglong2 B0 = *(const ulonglong2*)&sW[kk * DD + c0];
        const ulonglong2 B1 = *(const ulonglong2*)&sW[kk * DD + c0 + 4];
        const float a[8] = { a0.x, a0.y, a0.z, a0.w, a1.x, a1.y, a1.z, a1.w };
#pragma unroll
        for (int i = 0; i < 8; ++i) {
            const unsigned long long aa = pk2(a[i], a[i]);
            ffma2(acc[i][0], aa, B0.x);
            ffma2(acc[i][1], aa, B0.y);
            ffma2(acc[i][2], aa, B1.x);
            ffma2(acc[i][3], aa, B1.y);
        }
    }

    float bv[8];
#pragma unroll
    for (int j = 0; j < 8; ++j) bv[j] = bias ? bias[c0 + j] : 0.0f;
#pragma unroll
    for (int i = 0; i < 8; ++i) {
        const int n = n0 + r0 + i;
        if (n < NN) {
            float o[8];
#pragma unroll
            for (int p = 0; p < 4; ++p) {
                float x, y; up2(acc[i][p], x, y);
                o[2 * p] = x + bv[2 * p]; o[2 * p + 1] = y + bv[2 * p + 1];
            }
            *(float4*)&out[(size_t)n * DD + c0]     = make_float4(o[0], o[1], o[2], o[3]);
            *(float4*)&out[(size_t)n * DD + c0 + 4] = make_float4(o[4], o[5], o[6], o[7]);
        }
    }
}

// ---------------- launch 1: scan (block 0) + node-input MLP ----------------
__global__ __launch_bounds__(256, 1)
void k_scan_nin(const float* __restrict__ xt,
                const float* __restrict__ w1,
                const float* __restrict__ w2,
                const float* __restrict__ b2) {
    extern __shared__ float sm[];
    if (blockIdx.x == 0) {
        int* ip = (int*)sm;
        const int t = threadIdx.x;
        const int per = 79;
        const int start = t * per;
        int sum = 0;
        for (int i = 0; i < per; ++i) {
            const int idx = start + i;
            if (idx < NN) sum += g_hist[idx];
        }
        ip[t] = sum;
        __syncthreads();
        if (t == 0) {
            int run = 0;
            for (int i = 0; i < 256; ++i) { int v = ip[i]; ip[i] = run; run += v; }
        }
        __syncthreads();
        int run = ip[t];
        for (int i = 0; i < per; ++i) {
            const int idx = start + i;
            if (idx < NN) { int v = g_hist[idx]; g_woff[idx] = run; run += v; }
        }
        return;
    }
    float* sW    = sm;
    float* sAT   = sW + DD * DD;
    float* sW1x  = sAT + 128 * ATSTR;
    float* sBase = sW1x + 3 * DD;

    const int tid = threadIdx.x;
    const int tx = tid & 15, ty = tid >> 4;
    const int c0 = tx * 8, r0 = ty * 8;
    const int n0 = (blockIdx.x - 1) * 128;

    {
        const float4* w4 = (const float4*)w2;
#pragma unroll
        for (int i = 0; i < 16; ++i)
            ((float4*)sW)[tid + i * 256] = w4[tid + i * 256];
    }
    if (tid < 128) {
        sW1x[tid]       = w1[tid];
        sW1x[128 + tid] = w1[128 + tid];
        sW1x[256 + tid] = w1[256 + tid];
        sBase[tid]      = g_base[tid];
    }
    __syncthreads();

#pragma unroll
    for (int i = 0; i < 16; ++i) {
        const int idx = tid + i * 256;
        const int nl = idx >> 5;
        const int q = (idx & 31) * 4;
        int n = n0 + nl; if (n >= NN) n = NN - 1;
        const float x0 = xt[n * 3 + 0], x1 = xt[n * 3 + 1], x2 = xt[n * 3 + 2];
#pragma unroll
        for (int m = 0; m < 4; ++m) {
            const int k = q + m;
            const float v = silu_f(sBase[k] + x0 * sW1x[k] + x1 * sW1x[128 + k] + x2 * sW1x[256 + k]);
            sAT[k * ATSTR + (nl ^ (((k >> 3) & 7) << 3))] = v;
        }
    }
    __syncthreads();

    unsigned long long acc[8][4];
#pragma unroll
    for (int i = 0; i < 8; ++i)
#pragma unroll
        for (int p = 0; p < 4; ++p) acc[i][p] = 0ull;

    for (int kk = 0; kk < 128; ++kk) {
        const int rs = r0 ^ (((kk >> 3) & 7) << 3);
        const float4 a0 = *(const float4*)&sAT[kk * ATSTR + rs];
        const float4 a1 = *(const float4*)&sAT[kk * ATSTR + rs + 4];
        const ulonglong2 B0 = *(const ulonglong2*)&sW[kk * DD + c0];
        const ulonglong2 B1 = *(const ulonglong2*)&sW[kk * DD + c0 + 4];
        const float a[8] = { a0.x, a0.y, a0.z, a0.w, a1.x, a1.y, a1.z, a1.w };
#pragma unroll
        for (int i = 0; i < 8; ++i) {
            const unsigned long long aa = pk2(a[i], a[i]);
            ffma2(acc[i][0], aa, B0.x);
            ffma2(acc[i][1], aa, B0.y);
            ffma2(acc[i][2], aa, B1.x);
            ffma2(acc[i][3], aa, B1.y);
        }
    }

    float bv[8];
#pragma unroll
    for (int j = 0; j < 8; ++j) bv[j] = b2[c0 + j];
#pragma unroll
    for (int i = 0; i < 8; ++i) {
        const int n = n0 + r0 + i;
        if (n < NN) {
            float o[8];
#pragma unroll
            for (int p = 0; p < 4; ++p) {
                float x, y; up2(acc[i][p], x, y);
                o[2 * p] = x + bv[2 * p]; o[2 * p + 1] = y + bv[2 * p + 1];
            }
            *(float4*)&g_h[(size_t)n * DD + c0]     = make_float4(o[0], o[1], o[2], o[3]);
            *(float4*)&g_h[(size_t)n * DD + c0 + 4] = make_float4(o[4], o[5], o[6], o[7]);
        }
    }
}

// ================= per-layer prologue =================
#define PRE_TILES 157
__global__ __launch_bounds__(256, 1)
void k_prep(const float* __restrict__ Wa, const float* __restrict__ Wb,
            const float* __restrict__ b1, const float* __restrict__ w2,
            const int* __restrict__ ei, const float* __restrict__ xt,
            int scatBlocks) {
    int bx = blockIdx.x;
    if (bx < scatBlocks) {
        const int e = bx * 256 + threadIdx.x;
        if (e <= NN) g_hist[e] = 0;
        const int s = ei[e], d = ei[EE + e];
        const int pos = atomicAdd(&g_woff[d], 1);
        g_ssrc[pos] = s;
        g_sdst[pos] = d;
        const float dx = xt[s * 3 + 0] - xt[d * 3 + 0];
        const float dy = xt[s * 3 + 1] - xt[d * 3 + 1];
        const float r = sqrtf(dx * dx + dy * dy + 1e-8f);
        const float step = 1.41421356237309515f / 15.0f;
        const float gamma = 1.0f / (2.0f * step * step);
#pragma unroll
        for (int c = 0; c < RR; ++c) {
            float u = r - (float)c * step;
            g_rbf[(size_t)pos * RR + c] = __expf(-gamma * u * u);
        }
        return;
    }
    bx -= scatBlocks;
    if (bx < 2 * PRE_TILES) {
        const int sel = (bx >= PRE_TILES);
        do_pre(sel ? Wb : Wa, sel ? nullptr : b1, sel ? g_xd : g_xs,
               sel ? bx - PRE_TILES : bx);
        return;
    }
    bx -= 2 * PRE_TILES;
    if (bx < 157) {
        const int base = bx * 16384 + threadIdx.x * 4;
#pragma unroll
        for (int k = 0; k < 16; ++k) {
            const int i = base + k * 1024;
            if (i < NN * DD) *(float4*)&g_agg[i] = make_float4(0.f, 0.f, 0.f, 0.f);
        }
        return;
    }
    bx -= 157;
    // W2^T -> bf16 hi/lo in swizzled [n][k] layout (8 blocks x 2048 elems)
    char* w2hiB = (char*)g_w2hi;
    char* w2loB = (char*)g_w2lo;
    const int idx0 = bx * 2048 + threadIdx.x * 8;
#pragma unroll
    for (int t = 0; t < 8; ++t) {
        const int idx = idx0 + t;
        const int n = idx >> 7, k = idx & 127;
        const float val = w2[k * 128 + n];          // B[n][k] = W2[k][n]
        const __nv_bfloat16 bh = __float2bfloat16(val);
        const float hf = __bfloat162float(bh);
        const __nv_bfloat16 bl = __float2bfloat16(val - hf);
        const uint32_t off = (uint32_t)(n * 256 + (((k >> 3) ^ (n & 7)) << 4) + ((k & 7) * 2));
        *(__nv_bfloat16*)(w2hiB + off) = bh;
        *(__nv_bfloat16*)(w2loB + off) = bl;
    }
}

// ================= fused edge kernel v7: mma.sync bf16-split GEMM2 =================
// tile = 64 edges; phase1 fp32 -> A hi/lo bf16 swizzled smem; B (W2^T) hi/lo resident;
// 8 warps x (2m x 4n) m16n8k16 blocks x 8 kb x 3 passes; red.v2 scatter from fragments.
#define SMO_BHI  0
#define SMO_BLO  32768
#define SMO_AHI  65536
#define SMO_ALO  81920
#define SMO_WR   98304                       // fp32 16x128 = 8192B
#define SMO_RBFT (SMO_WR + 8192)             // fp32 16x68 = 4352B
#define SMO_B2   (SMO_RBFT + 4352)           // 512B
#define SMO_DST  (SMO_B2 + 512)              // 256B
#define SMEM_EDGE (SMO_DST + 256)

__global__ __launch_bounds__(256, 2)
void k_edge(const float* __restrict__ Wr,   // [16][128] fp32
            const float* __restrict__ b2,
            int numTiles) {
    extern __shared__ char smc[];
    float* sWr   = (float*)(smc + SMO_WR);
    float* sRbfT = (float*)(smc + SMO_RBFT);
    float* sB2   = (float*)(smc + SMO_B2);
    int*   sDst  = (int*)(smc + SMO_DST);

    const int tid = threadIdx.x;
    const int w = tid >> 5, lane = tid & 31;
    const int wm = w & 1, wn = w >> 1;
    const int ly = lane >> 2, lx = lane & 3;
    const int r0 = wm * 32 + ly * 4;           // phase-1 rows (4)
    const int c0 = wn * 32 + lx * 8;           // phase-1 cols (8)

    // resident weights: W2^T hi/lo (swizzled), Wr, b2
    {
        uint4* bh = (uint4*)(smc + SMO_BHI);
        uint4* bl = (uint4*)(smc + SMO_BLO);
#pragma unroll
        for (int i = 0; i < 8; ++i) {
            bh[tid + i * 256] = g_w2hi[tid + i * 256];
            bl[tid + i * 256] = g_w2lo[tid + i * 256];
        }
        const float4* wr4 = (const float4*)Wr;
#pragma unroll
        for (int i = 0; i < 2; ++i)
            ((float4*)sWr)[tid + i * 256] = wr4[tid + i * 256];
        if (tid < 128) sB2[tid] = b2[tid];
    }

    // ldmatrix lane addressing (rowA&7 == rowB&7 == lane&7 since bases are x8)
    const int lr = lane & 7;
    const int pA = lane >> 4;                  // k-chunk parity for A x4
    const int pB = (lane >> 3) & 1;            // k-chunk parity for B x2
    uint32_t baseAhi[2], baseAlo[2], baseBhi[4], baseBlo[4];
    {
        const uint32_t sb = smem_u32(smc);
#pragma unroll
        for (int mb = 0; mb < 2; ++mb) {
            const int rowA = wm * 32 + mb * 16 + lr + ((lane >> 3) & 1) * 8;
            baseAhi[mb] = sb + SMO_AHI + rowA * 256;
            baseAlo[mb] = sb + SMO_ALO + rowA * 256;
        }
#pragma unroll
        for (int nb = 0; nb < 4; ++nb) {
            const int rowB = wn * 32 + nb * 8 + lr;
            baseBhi[nb] = sb + SMO_BHI + rowB * 256;
            baseBlo[nb] = sb + SMO_BLO + rowB * 256;
        }
    }
    __syncthreads();

    // prefetch first tile's per-thread src/dst indices (for gather)
    int psrc[4], pdst[4];
    int tile = blockIdx.x;
    if (tile < numTiles) {
#pragma unroll
        for (int i = 0; i < 4; ++i) {
            psrc[i] = g_ssrc[tile * 64 + r0 + i];
            pdst[i] = g_sdst[tile * 64 + r0 + i];
        }
    }

    for (; tile < numTiles; tile += gridDim.x) {
        const int e0 = tile * 64;
        __syncthreads();  // protect smem from previous tile's readers

        // gather Xs[src]+Xd[dst] (prefetched indices; dst sorted -> L1 hits)
        float xsv[4][8];
#pragma unroll
        for (int i = 0; i < 4; ++i) {
            const float4 a0 = *(const float4*)&g_xs[(size_t)psrc[i] * DD + c0];
            const float4 a1 = *(const float4*)&g_xs[(size_t)psrc[i] * DD + c0 + 4];
            const float4 b0 = *(const float4*)&g_xd[(size_t)pdst[i] * DD + c0];
            const float4 b1 = *(const float4*)&g_xd[(size_t)pdst[i] * DD + c0 + 4];
            xsv[i][0] = a0.x + b0.x; xsv[i][1] = a0.y + b0.y;
            xsv[i][2] = a0.z + b0.z; xsv[i][3] = a0.w + b0.w;
            xsv[i][4] = a1.x + b1.x; xsv[i][5] = a1.y + b1.y;
            xsv[i][6] = a1.z + b1.z; xsv[i][7] = a1.w + b1.w;
        }

        // stage dst + rbf (transposed)
        if (tid < 64) sDst[tid] = g_sdst[e0 + tid];
        {
            const int row = tid & 63, c4 = (tid >> 6) * 4;
            const float4 v = *(const float4*)&g_rbf[(size_t)(e0 + row) * RR + c4];
            sRbfT[(c4 + 0) * 68 + row] = v.x;
            sRbfT[(c4 + 1) * 68 + row] = v.y;
            sRbfT[(c4 + 2) * 68 + row] = v.z;
            sRbfT[(c4 + 3) * 68 + row] = v.w;
        }
        __syncthreads();

        // phase 1: K=16 rbf GEMM (fp32, covers gather latency)
        unsigned long long acc1[4][4];
#pragma unroll
        for (int i = 0; i < 4; ++i)
#pragma unroll
            for (int p = 0; p < 4; ++p) acc1[i][p] = 0ull;
#pragma unroll
        for (int kk = 0; kk < 16; ++kk) {
            const float4 av = *(const float4*)&sRbfT[kk * 68 + r0];
            const ulonglong2 B0 = *(const ulonglong2*)&sWr[kk * DD + c0];
            const ulonglong2 B1 = *(const ulonglong2*)&sWr[kk * DD + c0 + 4];
            const float a[4] = { av.x, av.y, av.z, av.w };
#pragma unroll
            for (int i = 0; i < 4; ++i) {
                const unsigned long long aa = pk2(a[i], a[i]);
                ffma2(acc1[i][0], aa, B0.x);
                ffma2(acc1[i][1], aa, B0.y);
                ffma2(acc1[i][2], aa, B1.x);
                ffma2(acc1[i][3], aa, B1.y);
            }
        }

        // epilogue 1: silu -> bf16 hi/lo A tiles (swizzled 16B-chunk layout)
#pragma unroll
        for (int i = 0; i < 4; ++i) {
            float o[8];
            float x, y;
            up2(acc1[i][0], x, y); o[0] = silu_f(x + xsv[i][0]); o[1] = silu_f(y + xsv[i][1]);
            up2(acc1[i][1], x, y); o[2] = silu_f(x + xsv[i][2]); o[3] = silu_f(y + xsv[i][3]);
            up2(acc1[i][2], x, y); o[4] = silu_f(x + xsv[i][4]); o[5] = silu_f(y + xsv[i][5]);
            up2(acc1[i][3], x, y); o[6] = silu_f(x + xsv[i][6]); o[7] = silu_f(y + xsv[i][7]);
            uint32_t hh[4], ll[4];
#pragma unroll
            for (int p = 0; p < 4; ++p) {
                const float xv = o[2 * p], yv = o[2 * p + 1];
                const float xh = __bfloat162float(__float2bfloat16(xv));
                const float yh = __bfloat162float(__float2bfloat16(yv));
                asm("cvt.rn.bf16x2.f32 %0, %1, %2;" : "=r"(hh[p]) : "f"(yh), "f"(xh));
                asm("cvt.rn.bf16x2.f32 %0, %1, %2;" : "=r"(ll[p]) : "f"(yv - yh), "f"(xv - xh));
            }
            const int rr = r0 + i;
            const uint32_t off = (uint32_t)(rr * 256 + (((c0 >> 3) ^ (rr & 7)) << 4));
            *(uint4*)(smc + SMO_AHI + off) = make_uint4(hh[0], hh[1], hh[2], hh[3]);
            *(uint4*)(smc + SMO_ALO + off) = make_uint4(ll[0], ll[1], ll[2], ll[3]);
        }
        __syncthreads();

        // prefetch NEXT tile's indices (hidden under mma loop)
        {
            const int nt = tile + gridDim.x;
            if (nt < numTiles) {
#pragma unroll
                for (int i = 0; i < 4; ++i) {
                    psrc[i] = g_ssrc[nt * 64 + r0 + i];
                    pdst[i] = g_sdst[nt * 64 + r0 + i];
                }
            }
        }

        // phase 2: tensor-core GEMM2, bf16-split (hi*hi + hi*lo + lo*hi)
        float acc[2][4][4];
#pragma unroll
        for (int mb = 0; mb < 2; ++mb)
#pragma unroll
            for (int nb = 0; nb < 4; ++nb)
#pragma unroll
                for (int q = 0; q < 4; ++q) acc[mb][nb][q] = 0.0f;

#pragma unroll
        for (int kb = 0; kb < 8; ++kb) {
            const uint32_t swA = (uint32_t)(((kb * 2 + pA) ^ lr) << 4);
            const uint32_t swB = (uint32_t)(((kb * 2 + pB) ^ lr) << 4);
            uint32_t ah[2][4], al[2][4];
            ldsm4(ah[0], baseAhi[0] + swA);
            ldsm4(ah[1], baseAhi[1] + swA);
            ldsm4(al[0], baseAlo[0] + swA);
            ldsm4(al[1], baseAlo[1] + swA);
#pragma unroll
            for (int nb = 0; nb < 4; ++nb) {
                uint32_t bh[2], bl[2];
                ldsm2(bh, baseBhi[nb] + swB);
                ldsm2(bl, baseBlo[nb] + swB);
                mma16816(acc[0][nb], ah[0], bh);
                mma16816(acc[1][nb], ah[1], bh);
                mma16816(acc[0][nb], ah[0], bl);
                mma16816(acc[1][nb], ah[1], bl);
                mma16816(acc[0][nb], al[0], bh);
                mma16816(acc[1][nb], al[1], bh);
            }
        }

        // epilogue 2: bias + red.v2 scatter straight from fragments
#pragma unroll
        for (int nb = 0; nb < 4; ++nb) {
            const int cd = wn * 32 + nb * 8 + (lane & 3) * 2;
            const float bb0 = sB2[cd], bb1 = sB2[cd + 1];
#pragma unroll
            for (int mb = 0; mb < 2; ++mb) {
                const int rd = wm * 32 + mb * 16 + (lane >> 2);
                const int d0 = sDst[rd], d1 = sDst[rd + 8];
                red_add_v2(&g_agg[(size_t)d0 * DD + cd],
                           acc[mb][nb][0] + bb0, acc[mb][nb][1] + bb1);
                red_add_v2(&g_agg[(size_t)d1 * DD + cd],
                           acc[mb][nb][2] + bb0, acc[mb][nb][3] + bb1);
            }
        }
    }
}

// ================= node update MLP + residual + fused LayerNorm -> g_h =================
#define NHSTR 132
__global__ __launch_bounds__(512, 1)
void k_node(const float* __restrict__ w1, const float* __restrict__ b1,
            const float* __restrict__ w2, const float* __restrict__ b2,
            const float* __restrict__ lng, const float* __restrict__ lnb,
            int numTiles) {
    extern __shared__ float sm[];
    float* sW1  = sm;
    float* sHid = sW1 + 256 * DD;
    float* sA0  = sHid + 128 * NHSTR;
    float* sA1  = sA0 + 128 * 16;

    const int tid = threadIdx.x;
    const int c0 = (tid & 15) * 8;
    const int r0 = (tid >> 4) * 4;
    const int gr = tid >> 2;
    const int gq = (tid & 3) * 4;
    const int wN = tid >> 5, lane = tid & 31;

    for (int i = tid; i < 256 * DD; i += 512) sW1[i] = w1[i];
    float bias1[8], bias2[8];
#pragma unroll
    for (int j = 0; j < 8; ++j) { bias1[j] = b1[c0 + j]; bias2[j] = b2[c0 + j]; }
    const float4 gg4 = *(const float4*)&lng[lane * 4];
    const float4 bb4 = *(const float4*)&lnb[lane * 4];

    float* bufs[2] = { sA0, sA1 };

    for (int tile = blockIdx.x; tile < numTiles; tile += gridDim.x) {
        const int n0 = tile * 128;
        int gn = n0 + gr; if (gn >= NN) gn = NN - 1;
        unsigned long long acc[4][4];
#pragma unroll
        for (int i = 0; i < 4; ++i)
#pragma unroll
            for (int p = 0; p < 4; ++p) acc[i][p] = 0ull;
        __syncthreads();

        {
            float4 v = *(const float4*)&g_h[(size_t)gn * DD + gq];
            *(float4*)&bufs[0][gr * 16 + gq] = v;
        }
        __syncthreads();

        for (int kc = 0; kc < 16; ++kc) {
            float4 nv;
            if (kc < 15) {
                const int k = (kc + 1) * 16 + gq;
                if (k < 128) nv = *(const float4*)&g_h[(size_t)gn * DD + k];
                else         nv = *(const float4*)&g_agg[(size_t)gn * DD + (k - 128)];
            }
            const float* A = bufs[kc & 1];
            const int kbase = kc * 16;
#pragma unroll
            for (int kk = 0; kk < 16; ++kk) {
                const float* wrow = &sW1[(kbase + kk) * DD + c0];
                const ulonglong2 B0 = *(const ulonglong2*)wrow;
                const ulonglong2 B1 = *(const ulonglong2*)(wrow + 4);
#pragma unroll
                for (int i = 0; i < 4; ++i) {
                    const float a = A[(r0 + i) * 16 + kk];
                    const unsigned long long aa = pk2(a, a);
                    ffma2(acc[i][0], aa, B0.x);
                    ffma2(acc[i][1], aa, B0.y);
                    ffma2(acc[i][2], aa, B1.x);
                    ffma2(acc[i][3], aa, B1.y);
                }
            }
            if (kc < 15) *(float4*)&bufs[(kc + 1) & 1][gr * 16 + gq] = nv;
            __syncthreads();
        }

        {
            float4 w2v = *(const float4*)&w2[tid * 4];
#pragma unroll
            for (int i = 0; i < 4; ++i) {
                float* hrow = &sHid[(r0 + i) * NHSTR + c0];
                float o[8];
#pragma unroll
                for (int p = 0; p < 4; ++p) {
                    float x, y; up2(acc[i][p], x, y);
                    o[2 * p]     = silu_f(x + bias1[2 * p]);
                    o[2 * p + 1] = silu_f(y + bias1[2 * p + 1]);
                    acc[i][p] = 0ull;
                }
                *(float4*)&hrow[0] = make_float4(o[0], o[1], o[2], o[3]);
                *(float4*)&hrow[4] = make_float4(o[4], o[5], o[6], o[7]);
            }
            *(float4*)&bufs[0][tid * 4] = w2v;
        }
        __syncthreads();

        for (int kc = 0; kc < 8; ++kc) {
            float4 nv;
            if (kc < 7) nv = *(const float4*)&w2[(size_t)(kc + 1) * 16 * DD + tid * 4];
            const float* Bc = bufs[kc & 1];
            const int kbase = kc * 16;
#pragma unroll
            for (int kk = 0; kk < 16; ++kk) {
                const float* wrow = &Bc[kk * DD + c0];
                const ulonglong2 B0 = *(const ulonglong2*)wrow;
                const ulonglong2 B1 = *(const ulonglong2*)(wrow + 4);
#pragma unroll
                for (int i = 0; i < 4; ++i) {
                    const float a = sHid[(r0 + i) * NHSTR + kbase + kk];
                    const unsigned long long aa = pk2(a, a);
                    ffma2(acc[i][0], aa, B0.x);
                    ffma2(acc[i][1], aa, B0.y);
                    ffma2(acc[i][2], aa, B1.x);
                    ffma2(acc[i][3], aa, B1.y);
                }
            }
            if (kc < 7) *(float4*)&bufs[(kc + 1) & 1][tid * 4] = nv;
            __syncthreads();
        }
        __syncthreads();

#pragma unroll
        for (int i = 0; i < 4; ++i) {
            const int n = n0 + r0 + i;
            const int nc = (n < NN) ? n : (NN - 1);
            const float4 h0 = *(const float4*)&g_h[(size_t)nc * DD + c0];
            const float4 h1 = *(const float4*)&g_h[(size_t)nc * DD + c0 + 4];
            float o[8];
#pragma unroll
            for (int p = 0; p < 4; ++p) {
                float x, y; up2(acc[i][p], x, y);
                o[2 * p]     = x + bias2[2 * p];
                o[2 * p + 1] = y + bias2[2 * p + 1];
            }
            *(float4*)&sHid[(r0 + i) * NHSTR + c0] =
                make_float4(o[0] + h0.x, o[1] + h0.y, o[2] + h0.z, o[3] + h0.w);
            *(float4*)&sHid[(r0 + i) * NHSTR + c0 + 4] =
                make_float4(o[4] + h1.x, o[5] + h1.y, o[6] + h1.z, o[7] + h1.w);
        }
        __syncthreads();

#pragma unroll
        for (int j = 0; j < 8; ++j) {
            const int row = wN * 8 + j;
            const int n = n0 + row;
            if (n < NN) {
                const float4 v = *(const float4*)&sHid[row * NHSTR + lane * 4];
                float s = v.x + v.y + v.z + v.w;
#pragma unroll
                for (int o = 16; o; o >>= 1) s += __shfl_xor_sync(0xFFFFFFFFu, s, o);
                const float mu = s * (1.0f / 128.0f);
                const float d0 = v.x - mu, d1 = v.y - mu, d2 = v.z - mu, d3 = v.w - mu;
                float q = d0 * d0 + d1 * d1 + d2 * d2 + d3 * d3;
#pragma unroll
                for (int o = 16; o; o >>= 1) q += __shfl_xor_sync(0xFFFFFFFFu, q, o);
                const float inv = rsqrtf(q * (1.0f / 128.0f) + 1e-5f);
                float4 o4;
                o4.x = d0 * inv * gg4.x + bb4.x;
                o4.y = d1 * inv * gg4.y + bb4.y;
                o4.z = d2 * inv * gg4.z + bb4.z;
                o4.w = d3 * inv * gg4.w + bb4.w;
                *(float4*)&g_h[(size_t)n * DD + lane * 4] = o4;
            }
        }
    }
}

// ---------------- output MLP ----------------
__global__ void k_out(const float* __restrict__ w1, const float* __restrict__ b1,
                      const float* __restrict__ w2, const float* __restrict__ b2,
                      float* __restrict__ out) {
    extern __shared__ float sm[];
    float* sW1  = sm;
    float* sW2  = sW1 + DD * DD;
    float* sX   = sW2 + DD * 3;
    float* sHid = sX + DD;
    const int j = threadIdx.x;
    for (int i = j; i < DD * DD; i += DD) sW1[i] = w1[i];
    for (int i = j; i < DD * 3; i += DD) sW2[i] = w2[i];
    const float bb1 = b1[j];
    __syncthreads();
    const int n0 = blockIdx.x * 16;
    for (int m = 0; m < 16; ++m) {
        const int n = n0 + m;
        sX[j] = g_h[(size_t)n * DD + j];
        __syncthreads();
        float acc = bb1;
#pragma unroll 8
        for (int k = 0; k < DD; ++k) acc += sX[k] * sW1[k * DD + j];
        sHid[j] = silu_f(acc);
        __syncthreads();
        if (j < 3) {
            float o = b2[j];
            for (int k = 0; k < DD; ++k) o += sHid[k] * sW2[k * 3 + j];
            out[(size_t)n * 3 + j] = o;
        }
        __syncthreads();
    }
}

// ---------------- launch ----------------
extern "C" void kernel_launch(void* const* d_in, const int* in_sizes, int n_in,
                              void* d_out, int out_size) {
    const float* x_t      = (const float*)d_in[0];
    const int*   ei       = (const int*)d_in[1];
    const int*   tp       = (const int*)d_in[2];
    const float* time_w1  = (const float*)d_in[3];
    const float* time_b1  = (const float*)d_in[4];
    const float* time_w2  = (const float*)d_in[5];
    const float* time_b2  = (const float*)d_in[6];
    const float* nodein_w1= (const float*)d_in[7];
    const float* nodein_b1= (const float*)d_in[8];
    const float* nodein_w2= (const float*)d_in[9];
    const float* nodein_b2= (const float*)d_in[10];
    const float* phim_w1  = (const float*)d_in[11];
    const float* phim_b1  = (const float*)d_in[12];
    const float* phim_w2  = (const float*)d_in[13];
    const float* phim_b2  = (const float*)d_in[14];
    const float* phih_w1  = (const float*)d_in[15];
    const float* phih_b1  = (const float*)d_in[16];
    const float* phih_w2  = (const float*)d_in[17];
    const float* phih_b2  = (const float*)d_in[18];
    const float* ln_g     = (const float*)d_in[19];
    const float* ln_b     = (const float*)d_in[20];
    const float* out_w1   = (const float*)d_in[21];
    const float* out_b1   = (const float*)d_in[22];
    const float* out_w2   = (const float*)d_in[23];
    const float* out_b2   = (const float*)d_in[24];
    float* out = (float*)d_out;

    const int SMEM_PRE  = (DD * DD + 128 * ATSTR) * 4;
    const int SMEM_NIN  = (DD * DD + 128 * ATSTR + 3 * DD + DD) * 4;
    const int SMEM_NODE = (256 * DD + 128 * NHSTR + 2 * 128 * 16) * 4;
    const int SMEM_OUT  = (DD * DD + DD * 3 + DD + DD) * 4;

    cudaFuncSetAttribute(k_edge,     cudaFuncAttributeMaxDynamicSharedMemorySize, SMEM_EDGE);
    cudaFuncSetAttribute(k_prep,     cudaFuncAttributeMaxDynamicSharedMemorySize, SMEM_PRE);
    cudaFuncSetAttribute(k_scan_nin, cudaFuncAttributeMaxDynamicSharedMemorySize, SMEM_NIN);
    cudaFuncSetAttribute(k_node,     cudaFuncAttributeMaxDynamicSharedMemorySize, SMEM_NODE);
    cudaFuncSetAttribute(k_out,      cudaFuncAttributeMaxDynamicSharedMemorySize, SMEM_OUT);

    const int edgeTiles = EE / 64;           // 10000
    const int nodeTiles = (NN + 127) / 128;  // 157
    const int SCAT = EE / 256;               // 2500

    k_time_hist<<<1 + SCAT, 256>>>(ei, tp, time_w1, time_b1, time_w2, time_b2,
                                   nodein_w1, nodein_b1);
    k_scan_nin<<<1 + PRE_TILES, 256, SMEM_NIN>>>(x_t, nodein_w1, nodein_w2, nodein_b2);

    for (int l = 0; l < LL; ++l) {
        const float* W1l = phim_w1 + (size_t)l * 272 * DD;
        const int scat = (l == 0) ? SCAT : 0;
        k_prep<<<scat + 2 * PRE_TILES + 157 + 8, 256, SMEM_PRE>>>(
            W1l, W1l + 128 * DD, phim_b1 + (size_t)l * DD,
            phim_w2 + (size_t)l * DD * DD, ei, x_t, scat);
        // launch 3 (l==0) -> ncu capture target
        k_edge<<<296, 256, SMEM_EDGE>>>(W1l + 256 * DD,
                                        phim_b2 + (size_t)l * DD,
                                        edgeTiles);
        k_node<<<148, 512, SMEM_NODE>>>(phih_w1 + (size_t)l * 256 * DD,
                                        phih_b1 + (size_t)l * DD,
                                        phih_w2 + (size_t)l * DD * DD,
                                        phih_b2 + (size_t)l * DD,
                                        ln_g + (size_t)l * DD, ln_b + (size_t)l * DD,
                                        nodeTiles);
    }

    k_out<<<NN / 16, 128, SMEM_OUT>>>(out_w1, out_b1, out_w2, out_b2, out);
}

// round 17
// speedup vs baseline: 7.4605x; 1.2955x over previous
#include <cuda_runtime.h>
#include <cuda_bf16.h>
#include <cstdint>

#define NN 20000
#define EE 640000
#define DD 128
#define RR 16
#define LL 3

// ---------------- device scratch ----------------
__device__ float g_h   [(size_t)NN * DD];
__device__ float g_agg [(size_t)NN * DD];
__device__ float g_rbf [(size_t)EE * RR];   // in SORTED edge order
__device__ float g_xs  [(size_t)NN * DD];
__device__ float g_xd  [(size_t)NN * DD];
__device__ float g_base[DD];
__device__ int   g_hist[NN + 1];            // zero-initialized at load
__device__ int   g_woff[NN];
__device__ int   g_ssrc[EE];
__device__ int   g_sdst[EE];
// per-layer converted weights: bf16 hi/lo, [n][k] swizzled ldmatrix layout
__device__ uint4 g_w2hi[2048];   // phim_w2^T   (edge GEMM2)
__device__ uint4 g_w2lo[2048];
__device__ uint4 g_pahi[2048];   // phim_w1 rows 0..127 ^T  (Xs)
__device__ uint4 g_palo[2048];
__device__ uint4 g_pbhi[2048];   // phim_w1 rows 128..255 ^T (Xd)
__device__ uint4 g_pblo[2048];
__device__ uint4 g_n1hi[4096];   // phih_w1^T (K=256, two 128-halves)
__device__ uint4 g_n1lo[4096];
__device__ uint4 g_n2hi[2048];   // phih_w2^T
__device__ uint4 g_n2lo[2048];

__device__ __forceinline__ float silu_f(float x) {
    return x / (1.0f + __expf(-x));
}

// sm_103a packed fp32 FMA helpers
__device__ __forceinline__ unsigned long long pk2(float lo, float hi) {
    unsigned long long r;
    asm("mov.b64 %0, {%1, %2};" : "=l"(r) : "f"(lo), "f"(hi));
    return r;
}
__device__ __forceinline__ void up2(unsigned long long v, float& lo, float& hi) {
    asm("mov.b64 {%0, %1}, %2;" : "=f"(lo), "=f"(hi) : "l"(v));
}
__device__ __forceinline__ void ffma2(unsigned long long& d, unsigned long long a, unsigned long long b) {
    asm("fma.rn.f32x2 %0, %1, %2, %0;" : "+l"(d) : "l"(a), "l"(b));
}
__device__ __forceinline__ void red_add_v2(float* p, float a, float b) {
    asm volatile("red.global.add.v2.f32 [%0], {%1, %2};" :: "l"(p), "f"(a), "f"(b) : "memory");
}

// ---------------- mma.sync / ldmatrix helpers ----------------
__device__ __forceinline__ uint32_t smem_u32(const void* p) {
    uint32_t a;
    asm("{ .reg .u64 t; cvta.to.shared.u64 t, %1; cvt.u32.u64 %0, t; }" : "=r"(a) : "l"(p));
    return a;
}
__device__ __forceinline__ void ldsm4(uint32_t* r, uint32_t addr) {
    asm volatile("ldmatrix.sync.aligned.m8n8.x4.shared.b16 {%0,%1,%2,%3}, [%4];"
                 : "=r"(r[0]), "=r"(r[1]), "=r"(r[2]), "=r"(r[3]) : "r"(addr));
}
__device__ __forceinline__ void ldsm2(uint32_t* r, uint32_t addr) {
    asm volatile("ldmatrix.sync.aligned.m8n8.x2.shared.b16 {%0,%1}, [%2];"
                 : "=r"(r[0]), "=r"(r[1]) : "r"(addr));
}
__device__ __forceinline__ void mma16816(float* c, const uint32_t* a, const uint32_t* b) {
    asm volatile("mma.sync.aligned.m16n8k16.row.col.f32.bf16.bf16.f32 "
                 "{%0,%1,%2,%3}, {%4,%5,%6,%7}, {%8,%9}, {%0,%1,%2,%3};"
                 : "+f"(c[0]), "+f"(c[1]), "+f"(c[2]), "+f"(c[3])
                 : "r"(a[0]), "r"(a[1]), "r"(a[2]), "r"(a[3]), "r"(b[0]), "r"(b[1]));
}
__device__ __forceinline__ void bf16split(float xv, float yv, uint32_t& hh, uint32_t& ll) {
    const float xh = __bfloat162float(__float2bfloat16(xv));
    const float yh = __bfloat162float(__float2bfloat16(yv));
    asm("cvt.rn.bf16x2.f32 %0, %1, %2;" : "=r"(hh) : "f"(yh), "f"(xh));
    asm("cvt.rn.bf16x2.f32 %0, %1, %2;" : "=r"(ll) : "f"(yv - yh), "f"(xv - xh));
}

// ---------------- launch 0: time MLP (block 0) + dst histogram ----------------
__global__ void k_time_hist(const int* __restrict__ ei, const int* __restrict__ tptr,
                            const float* __restrict__ tw1, const float* __restrict__ tb1,
                            const float* __restrict__ tw2, const float* __restrict__ tb2,
                            const float* __restrict__ nw1, const float* __restrict__ nb1) {
    if (blockIdx.x > 0) {
        const int e = (blockIdx.x - 1) * 256 + threadIdx.x;
        atomicAdd(&g_hist[ei[EE + e]], 1);
        return;
    }
    __shared__ float sE[DD], sH[DD], sTe[DD];
    const int j = threadIdx.x;
    const bool act = (j < DD);
    int iv = *tptr;
    float t = (iv >= 0 && iv < 1000000) ? (float)iv : __int_as_float(iv);
    if (act) {
        int i = (j < 64) ? j : (j - 64);
        float f = __expf(-logf(10000.0f) * (float)i / 63.0f);
        float a = t * f;
        sE[j] = (j < 64) ? sinf(a) : cosf(a);
    }
    __syncthreads();
    if (act) {
        float acc = tb1[j];
        for (int k = 0; k < DD; ++k) acc += sE[k] * tw1[k * DD + j];
        sH[j] = silu_f(acc);
    }
    __syncthreads();
    if (act) {
        float acc2 = tb2[j];
        for (int k = 0; k < DD; ++k) acc2 += sH[k] * tw2[k * DD + j];
        sTe[j] = acc2;
    }
    __syncthreads();
    if (act) {
        float accb = nb1[j];
        for (int k = 0; k < DD; ++k) accb += sTe[k] * nw1[(3 + k) * DD + j];
        g_base[j] = accb;
    }
}

// ---------------- launch 1: scan (block 0) + node-input MLP (fp32) ----------------
#define ATSTR 132
__global__ __launch_bounds__(256, 1)
void k_scan_nin(const float* __restrict__ xt,
                const float* __restrict__ w1,
                const float* __restrict__ w2,
                const float* __restrict__ b2) {
    extern __shared__ float sm[];
    if (blockIdx.x == 0) {
        int* ip = (int*)sm;
        const int t = threadIdx.x;
        const int per = 79;
        const int start = t * per;
        int sum = 0;
        for (int i = 0; i < per; ++i) {
            const int idx = start + i;
            if (idx < NN) sum += g_hist[idx];
        }
        ip[t] = sum;
        __syncthreads();
        if (t == 0) {
            int run = 0;
            for (int i = 0; i < 256; ++i) { int v = ip[i]; ip[i] = run; run += v; }
        }
        __syncthreads();
        int run = ip[t];
        for (int i = 0; i < per; ++i) {
            const int idx = start + i;
            if (idx < NN) { int v = g_hist[idx]; g_woff[idx] = run; run += v; }
        }
        return;
    }
    float* sW    = sm;
    float* sAT   = sW + DD * DD;
    float* sW1x  = sAT + 128 * ATSTR;
    float* sBase = sW1x + 3 * DD;

    const int tid = threadIdx.x;
    const int tx = tid & 15, ty = tid >> 4;
    const int c0 = tx * 8, r0 = ty * 8;
    const int n0 = (blockIdx.x - 1) * 128;

    {
        const float4* w4 = (const float4*)w2;
#pragma unroll
        for (int i = 0; i < 16; ++i)
            ((float4*)sW)[tid + i * 256] = w4[tid + i * 256];
    }
    if (tid < 128) {
        sW1x[tid]       = w1[tid];
        sW1x[128 + tid] = w1[128 + tid];
        sW1x[256 + tid] = w1[256 + tid];
        sBase[tid]      = g_base[tid];
    }
    __syncthreads();

#pragma unroll
    for (int i = 0; i < 16; ++i) {
        const int idx = tid + i * 256;
        const int nl = idx >> 5;
        const int q = (idx & 31) * 4;
        int n = n0 + nl; if (n >= NN) n = NN - 1;
        const float x0 = xt[n * 3 + 0], x1 = xt[n * 3 + 1], x2 = xt[n * 3 + 2];
#pragma unroll
        for (int m = 0; m < 4; ++m) {
            const int k = q + m;
            const float v = silu_f(sBase[k] + x0 * sW1x[k] + x1 * sW1x[128 + k] + x2 * sW1x[256 + k]);
            sAT[k * ATSTR + (nl ^ (((k >> 3) & 7) << 3))] = v;
        }
    }
    __syncthreads();

    unsigned long long acc[8][4];
#pragma unroll
    for (int i = 0; i < 8; ++i)
#pragma unroll
        for (int p = 0; p < 4; ++p) acc[i][p] = 0ull;

    for (int kk = 0; kk < 128; ++kk) {
        const int rs = r0 ^ (((kk >> 3) & 7) << 3);
        const float4 a0 = *(const float4*)&sAT[kk * ATSTR + rs];
        const float4 a1 = *(const float4*)&sAT[kk * ATSTR + rs + 4];
        const ulonglong2 B0 = *(const ulonglong2*)&sW[kk * DD + c0];
        const ulonglong2 B1 = *(const ulonglong2*)&sW[kk * DD + c0 + 4];
        const float a[8] = { a0.x, a0.y, a0.z, a0.w, a1.x, a1.y, a1.z, a1.w };
#pragma unroll
        for (int i = 0; i < 8; ++i) {
            const unsigned long long aa = pk2(a[i], a[i]);
            ffma2(acc[i][0], aa, B0.x);
            ffma2(acc[i][1], aa, B0.y);
            ffma2(acc[i][2], aa, B1.x);
            ffma2(acc[i][3], aa, B1.y);
        }
    }

    float bv[8];
#pragma unroll
    for (int j = 0; j < 8; ++j) bv[j] = b2[c0 + j];
#pragma unroll
    for (int i = 0; i < 8; ++i) {
        const int n = n0 + r0 + i;
        if (n < NN) {
            float o[8];
#pragma unroll
            for (int p = 0; p < 4; ++p) {
                float x, y; up2(acc[i][p], x, y);
                o[2 * p] = x + bv[2 * p]; o[2 * p + 1] = y + bv[2 * p + 1];
            }
            *(float4*)&g_h[(size_t)n * DD + c0]     = make_float4(o[0], o[1], o[2], o[3]);
            *(float4*)&g_h[(size_t)n * DD + c0 + 4] = make_float4(o[4], o[5], o[6], o[7]);
        }
    }
}

// ---------------- weight conversion: fp32 W[k][128] -> bf16 hi/lo [n][k] swizzled ----------------
__device__ __forceinline__ void conv_mat(const float* __restrict__ src, int K,
                                         uint4* dhi, uint4* dlo, int blk) {
    char* hB = (char*)dhi;
    char* lB = (char*)dlo;
    const int idx0 = blk * 2048 + threadIdx.x * 8;
#pragma unroll
    for (int t = 0; t < 8; ++t) {
        const int idx = idx0 + t;
        const int n = (K == 256) ? (idx >> 8) : (idx >> 7);
        const int k = idx & (K - 1);
        const float val = src[k * 128 + n];
        const __nv_bfloat16 bh = __float2bfloat16(val);
        const float hf = __bfloat162float(bh);
        const __nv_bfloat16 bl = __float2bfloat16(val - hf);
        const int kl = k & 127;
        const uint32_t off = (uint32_t)((k >> 7) * 32768 + n * 256 +
                                        (((kl >> 3) ^ (n & 7)) << 4) + ((kl & 7) * 2));
        *(__nv_bfloat16*)(hB + off) = bh;
        *(__nv_bfloat16*)(lB + off) = bl;
    }
}

// ================= per-layer prologue: scatter-sort+rbf | zero agg | weight conversions =================
__global__ __launch_bounds__(256, 1)
void k_prep(const float* __restrict__ Wa,   // phim_w1 (layer) base; Wb = +128*128
            const float* __restrict__ n1w,  // phih_w1 (256x128)
            const float* __restrict__ n2w,  // phih_w2
            const float* __restrict__ w2e,  // phim_w2
            const int* __restrict__ ei, const float* __restrict__ xt,
            int scatBlocks) {
    int bx = blockIdx.x;
    if (bx < scatBlocks) {
        const int e = bx * 256 + threadIdx.x;
        if (e <= NN) g_hist[e] = 0;
        const int s = ei[e], d = ei[EE + e];
        const int pos = atomicAdd(&g_woff[d], 1);
        g_ssrc[pos] = s;
        g_sdst[pos] = d;
        const float dx = xt[s * 3 + 0] - xt[d * 3 + 0];
        const float dy = xt[s * 3 + 1] - xt[d * 3 + 1];
        const float r = sqrtf(dx * dx + dy * dy + 1e-8f);
        const float step = 1.41421356237309515f / 15.0f;
        const float gamma = 1.0f / (2.0f * step * step);
#pragma unroll
        for (int c = 0; c < RR; ++c) {
            float u = r - (float)c * step;
            g_rbf[(size_t)pos * RR + c] = __expf(-gamma * u * u);
        }
        return;
    }
    bx -= scatBlocks;
    if (bx < 157) {
        const int base = bx * 16384 + threadIdx.x * 4;
#pragma unroll
        for (int k = 0; k < 16; ++k) {
            const int i = base + k * 1024;
            if (i < NN * DD) *(float4*)&g_agg[i] = make_float4(0.f, 0.f, 0.f, 0.f);
        }
        return;
    }
    bx -= 157;
    if (bx < 8)  { conv_mat(Wa,             128, g_pahi, g_palo, bx); return; }
    bx -= 8;
    if (bx < 8)  { conv_mat(Wa + 128 * 128, 128, g_pbhi, g_pblo, bx); return; }
    bx -= 8;
    if (bx < 8)  { conv_mat(w2e,            128, g_w2hi, g_w2lo, bx); return; }
    bx -= 8;
    if (bx < 16) { conv_mat(n1w,            256, g_n1hi, g_n1lo, bx); return; }
    bx -= 16;
    conv_mat(n2w, 128, g_n2hi, g_n2lo, bx);
}

// ================= k_pre: Xs = h@Wa + b1, Xd = h@Wb via tensor cores =================
// A (h tile) converted once; both B matrices resident. 256 thr, warp = 32rows x 64cols.
#define KP_AHI 0
#define KP_ALO 32768
#define KP_B   65536     // Ba hi, Ba lo(+32768), Bb hi(+65536), Bb lo(+98304)
#define SMEM_KPRE 196608

__global__ __launch_bounds__(256, 1)
void k_pre(const float* __restrict__ b1, int numTiles) {
    extern __shared__ char smc[];
    const uint32_t sb = smem_u32(smc);
    const int tid = threadIdx.x;
    const int w = tid >> 5, lane = tid & 31;
    const int wm = w & 3, wn = w >> 2;
    const int lr = lane & 7;
    const int pA = lane >> 4, pB = (lane >> 3) & 1;
    const int tx = tid & 15, ty = tid >> 4;

    {
        uint4* s = (uint4*)smc;
#pragma unroll
        for (int i = 0; i < 8; ++i) {
            s[(KP_B >> 4)           + tid + i * 256] = g_pahi[tid + i * 256];
            s[((KP_B + 32768) >> 4) + tid + i * 256] = g_palo[tid + i * 256];
            s[((KP_B + 65536) >> 4) + tid + i * 256] = g_pbhi[tid + i * 256];
            s[((KP_B + 98304) >> 4) + tid + i * 256] = g_pblo[tid + i * 256];
        }
    }
    float bs[8][2];
#pragma unroll
    for (int nb = 0; nb < 8; ++nb) {
        const int c = wn * 64 + nb * 8 + (lane & 3) * 2;
        bs[nb][0] = b1[c]; bs[nb][1] = b1[c + 1];
    }
    uint32_t baseAhi[2], baseAlo[2];
#pragma unroll
    for (int mb = 0; mb < 2; ++mb) {
        const int rowA = wm * 32 + mb * 16 + lr + ((lane >> 3) & 1) * 8;
        baseAhi[mb] = sb + KP_AHI + rowA * 256;
        baseAlo[mb] = sb + KP_ALO + rowA * 256;
    }
    const uint32_t baseB = sb + KP_B + (wn * 64 + lr) * 256;
    __syncthreads();

    for (int tile = blockIdx.x; tile < numTiles; tile += gridDim.x) {
        const int n0 = tile * 128;
        __syncthreads();
        // convert A = h tile -> hi/lo
#pragma unroll
        for (int i = 0; i < 8; ++i) {
            const int r = ty * 8 + i;
            int n = n0 + r; if (n >= NN) n = NN - 1;
            const float4 v0 = *(const float4*)&g_h[(size_t)n * DD + tx * 8];
            const float4 v1 = *(const float4*)&g_h[(size_t)n * DD + tx * 8 + 4];
            const float o[8] = { v0.x, v0.y, v0.z, v0.w, v1.x, v1.y, v1.z, v1.w };
            uint32_t hh[4], ll[4];
#pragma unroll
            for (int p = 0; p < 4; ++p) bf16split(o[2 * p], o[2 * p + 1], hh[p], ll[p]);
            const uint32_t off = (uint32_t)(r * 256 + ((tx ^ (r & 7)) << 4));
            *(uint4*)(smc + KP_AHI + off) = make_uint4(hh[0], hh[1], hh[2], hh[3]);
            *(uint4*)(smc + KP_ALO + off) = make_uint4(ll[0], ll[1], ll[2], ll[3]);
        }
        __syncthreads();

#pragma unroll 1
        for (int sel = 0; sel < 2; ++sel) {
            float acc[2][8][4];
#pragma unroll
            for (int mb = 0; mb < 2; ++mb)
#pragma unroll
                for (int nb = 0; nb < 8; ++nb)
#pragma unroll
                    for (int q = 0; q < 4; ++q) acc[mb][nb][q] = 0.0f;

#pragma unroll
            for (int kb = 0; kb < 8; ++kb) {
                const uint32_t swA = (uint32_t)(((kb * 2 + pA) ^ lr) << 4);
                const uint32_t swB = (uint32_t)(((kb * 2 + pB) ^ lr) << 4);
                uint32_t ah[2][4], al[2][4];
                ldsm4(ah[0], baseAhi[0] + swA);
                ldsm4(ah[1], baseAhi[1] + swA);
                ldsm4(al[0], baseAlo[0] + swA);
                ldsm4(al[1], baseAlo[1] + swA);
#pragma unroll
                for (int nb = 0; nb < 8; ++nb) {
                    uint32_t bh[2], bl[2];
                    const uint32_t bo = baseB + sel * 65536 + nb * 2048 + swB;
                    ldsm2(bh, bo);
                    ldsm2(bl, bo + 32768);
                    mma16816(acc[0][nb], ah[0], bh);
                    mma16816(acc[1][nb], ah[1], bh);
                    mma16816(acc[0][nb], ah[0], bl);
                    mma16816(acc[1][nb], ah[1], bl);
                    mma16816(acc[0][nb], al[0], bh);
                    mma16816(acc[1][nb], al[1], bh);
                }
            }
            float* dst = sel ? g_xd : g_xs;
#pragma unroll
            for (int nb = 0; nb < 8; ++nb) {
                const int c = wn * 64 + nb * 8 + (lane & 3) * 2;
                const float b0v = sel ? 0.0f : bs[nb][0];
                const float b1v = sel ? 0.0f : bs[nb][1];
#pragma unroll
                for (int mb = 0; mb < 2; ++mb) {
                    const int r = wm * 32 + mb * 16 + (lane >> 2);
                    const int na = n0 + r, nbr = na + 8;
                    if (na < NN)
                        *(float2*)&dst[(size_t)na * DD + c] =
                            make_float2(acc[mb][nb][0] + b0v, acc[mb][nb][1] + b1v);
                    if (nbr < NN)
                        *(float2*)&dst[(size_t)nbr * DD + c] =
                            make_float2(acc[mb][nb][2] + b0v, acc[mb][nb][3] + b1v);
                }
            }
        }
    }
}

// ================= fused edge kernel (unchanged from R15) =================
#define SMO_BHI  0
#define SMO_BLO  32768
#define SMO_AHI  65536
#define SMO_ALO  81920
#define SMO_WR   98304
#define SMO_RBFT (SMO_WR + 8192)
#define SMO_B2   (SMO_RBFT + 4352)
#define SMO_DST  (SMO_B2 + 512)
#define SMEM_EDGE (SMO_DST + 256)

__global__ __launch_bounds__(256, 2)
void k_edge(const float* __restrict__ Wr,
            const float* __restrict__ b2,
            int numTiles) {
    extern __shared__ char smc[];
    float* sWr   = (float*)(smc + SMO_WR);
    float* sRbfT = (float*)(smc + SMO_RBFT);
    float* sB2   = (float*)(smc + SMO_B2);
    int*   sDst  = (int*)(smc + SMO_DST);

    const int tid = threadIdx.x;
    const int w = tid >> 5, lane = tid & 31;
    const int wm = w & 1, wn = w >> 1;
    const int ly = lane >> 2, lx = lane & 3;
    const int r0 = wm * 32 + ly * 4;
    const int c0 = wn * 32 + lx * 8;

    {
        uint4* bh = (uint4*)(smc + SMO_BHI);
        uint4* bl = (uint4*)(smc + SMO_BLO);
#pragma unroll
        for (int i = 0; i < 8; ++i) {
            bh[tid + i * 256] = g_w2hi[tid + i * 256];
            bl[tid + i * 256] = g_w2lo[tid + i * 256];
        }
        const float4* wr4 = (const float4*)Wr;
#pragma unroll
        for (int i = 0; i < 2; ++i)
            ((float4*)sWr)[tid + i * 256] = wr4[tid + i * 256];
        if (tid < 128) sB2[tid] = b2[tid];
    }

    const int lr = lane & 7;
    const int pA = lane >> 4;
    const int pB = (lane >> 3) & 1;
    uint32_t baseAhi[2], baseAlo[2], baseBhi[4], baseBlo[4];
    {
        const uint32_t sb = smem_u32(smc);
#pragma unroll
        for (int mb = 0; mb < 2; ++mb) {
            const int rowA = wm * 32 + mb * 16 + lr + ((lane >> 3) & 1) * 8;
            baseAhi[mb] = sb + SMO_AHI + rowA * 256;
            baseAlo[mb] = sb + SMO_ALO + rowA * 256;
        }
#pragma unroll
        for (int nb = 0; nb < 4; ++nb) {
            const int rowB = wn * 32 + nb * 8 + lr;
            baseBhi[nb] = sb + SMO_BHI + rowB * 256;
            baseBlo[nb] = sb + SMO_BLO + rowB * 256;
        }
    }
    __syncthreads();

    int psrc[4], pdst[4];
    int tile = blockIdx.x;
    if (tile < numTiles) {
#pragma unroll
        for (int i = 0; i < 4; ++i) {
            psrc[i] = g_ssrc[tile * 64 + r0 + i];
            pdst[i] = g_sdst[tile * 64 + r0 + i];
        }
    }

    for (; tile < numTiles; tile += gridDim.x) {
        const int e0 = tile * 64;
        __syncthreads();

        float xsv[4][8];
#pragma unroll
        for (int i = 0; i < 4; ++i) {
            const float4 a0 = *(const float4*)&g_xs[(size_t)psrc[i] * DD + c0];
            const float4 a1 = *(const float4*)&g_xs[(size_t)psrc[i] * DD + c0 + 4];
            const float4 b0 = *(const float4*)&g_xd[(size_t)pdst[i] * DD + c0];
            const float4 b1 = *(const float4*)&g_xd[(size_t)pdst[i] * DD + c0 + 4];
            xsv[i][0] = a0.x + b0.x; xsv[i][1] = a0.y + b0.y;
            xsv[i][2] = a0.z + b0.z; xsv[i][3] = a0.w + b0.w;
            xsv[i][4] = a1.x + b1.x; xsv[i][5] = a1.y + b1.y;
            xsv[i][6] = a1.z + b1.z; xsv[i][7] = a1.w + b1.w;
        }

        if (tid < 64) sDst[tid] = g_sdst[e0 + tid];
        {
            const int row = tid & 63, c4 = (tid >> 6) * 4;
            const float4 v = *(const float4*)&g_rbf[(size_t)(e0 + row) * RR + c4];
            sRbfT[(c4 + 0) * 68 + row] = v.x;
            sRbfT[(c4 + 1) * 68 + row] = v.y;
            sRbfT[(c4 + 2) * 68 + row] = v.z;
            sRbfT[(c4 + 3) * 68 + row] = v.w;
        }
        __syncthreads();

        unsigned long long acc1[4][4];
#pragma unroll
        for (int i = 0; i < 4; ++i)
#pragma unroll
            for (int p = 0; p < 4; ++p) acc1[i][p] = 0ull;
#pragma unroll
        for (int kk = 0; kk < 16; ++kk) {
            const float4 av = *(const float4*)&sRbfT[kk * 68 + r0];
            const ulonglong2 B0 = *(const ulonglong2*)&sWr[kk * DD + c0];
            const ulonglong2 B1 = *(const ulonglong2*)&sWr[kk * DD + c0 + 4];
            const float a[4] = { av.x, av.y, av.z, av.w };
#pragma unroll
            for (int i = 0; i < 4; ++i) {
                const unsigned long long aa = pk2(a[i], a[i]);
                ffma2(acc1[i][0], aa, B0.x);
                ffma2(acc1[i][1], aa, B0.y);
                ffma2(acc1[i][2], aa, B1.x);
                ffma2(acc1[i][3], aa, B1.y);
            }
        }

#pragma unroll
        for (int i = 0; i < 4; ++i) {
            float o[8];
            float x, y;
            up2(acc1[i][0], x, y); o[0] = silu_f(x + xsv[i][0]); o[1] = silu_f(y + xsv[i][1]);
            up2(acc1[i][1], x, y); o[2] = silu_f(x + xsv[i][2]); o[3] = silu_f(y + xsv[i][3]);
            up2(acc1[i][2], x, y); o[4] = silu_f(x + xsv[i][4]); o[5] = silu_f(y + xsv[i][5]);
            up2(acc1[i][3], x, y); o[6] = silu_f(x + xsv[i][6]); o[7] = silu_f(y + xsv[i][7]);
            uint32_t hh[4], ll[4];
#pragma unroll
            for (int p = 0; p < 4; ++p) bf16split(o[2 * p], o[2 * p + 1], hh[p], ll[p]);
            const int rr = r0 + i;
            const uint32_t off = (uint32_t)(rr * 256 + (((c0 >> 3) ^ (rr & 7)) << 4));
            *(uint4*)(smc + SMO_AHI + off) = make_uint4(hh[0], hh[1], hh[2], hh[3]);
            *(uint4*)(smc + SMO_ALO + off) = make_uint4(ll[0], ll[1], ll[2], ll[3]);
        }
        __syncthreads();

        {
            const int nt = tile + gridDim.x;
            if (nt < numTiles) {
#pragma unroll
                for (int i = 0; i < 4; ++i) {
                    psrc[i] = g_ssrc[nt * 64 + r0 + i];
                    pdst[i] = g_sdst[nt * 64 + r0 + i];
                }
            }
        }

        float acc[2][4][4];
#pragma unroll
        for (int mb = 0; mb < 2; ++mb)
#pragma unroll
            for (int nb = 0; nb < 4; ++nb)
#pragma unroll
                for (int q = 0; q < 4; ++q) acc[mb][nb][q] = 0.0f;

#pragma unroll
        for (int kb = 0; kb < 8; ++kb) {
            const uint32_t swA = (uint32_t)(((kb * 2 + pA) ^ lr) << 4);
            const uint32_t swB = (uint32_t)(((kb * 2 + pB) ^ lr) << 4);
            uint32_t ah[2][4], al[2][4];
            ldsm4(ah[0], baseAhi[0] + swA);
            ldsm4(ah[1], baseAhi[1] + swA);
            ldsm4(al[0], baseAlo[0] + swA);
            ldsm4(al[1], baseAlo[1] + swA);
#pragma unroll
            for (int nb = 0; nb < 4; ++nb) {
                uint32_t bh[2], bl[2];
                ldsm2(bh, baseBhi[nb] + swB);
                ldsm2(bl, baseBlo[nb] + swB);
                mma16816(acc[0][nb], ah[0], bh);
                mma16816(acc[1][nb], ah[1], bh);
                mma16816(acc[0][nb], ah[0], bl);
                mma16816(acc[1][nb], ah[1], bl);
                mma16816(acc[0][nb], al[0], bh);
                mma16816(acc[1][nb], al[1], bh);
            }
        }

#pragma unroll
        for (int nb = 0; nb < 4; ++nb) {
            const int cd = wn * 32 + nb * 8 + (lane & 3) * 2;
            const float bb0 = sB2[cd], bb1 = sB2[cd + 1];
#pragma unroll
            for (int mb = 0; mb < 2; ++mb) {
                const int rd = wm * 32 + mb * 16 + (lane >> 2);
                const int d0 = sDst[rd], d1 = sDst[rd + 8];
                red_add_v2(&g_agg[(size_t)d0 * DD + cd],
                           acc[mb][nb][0] + bb0, acc[mb][nb][1] + bb1);
                red_add_v2(&g_agg[(size_t)d1 * DD + cd],
                           acc[mb][nb][2] + bb0, acc[mb][nb][3] + bb1);
            }
        }
    }
}

// ================= k_node: tensor-core node MLP + residual + fused LN -> g_h =================
#define KN_AHI 0
#define KN_ALO 32768
#define KN_BHI 65536
#define KN_BLO 98304
#define SMEM_KNODE 131072

__global__ __launch_bounds__(256, 1)
void k_node(const float* __restrict__ b1, const float* __restrict__ b2,
            const float* __restrict__ lng, const float* __restrict__ lnb,
            int numTiles) {
    extern __shared__ char smc[];
    const uint32_t sb = smem_u32(smc);
    const int tid = threadIdx.x;
    const int w = tid >> 5, lane = tid & 31;
    const int wm = w & 3, wn = w >> 2;
    const int lr = lane & 7;
    const int pA = lane >> 4, pB = (lane >> 3) & 1;
    const int tx = tid & 15, ty = tid >> 4;

    float b1s[8][2], b2s[8][2];
#pragma unroll
    for (int nb = 0; nb < 8; ++nb) {
        const int c = wn * 64 + nb * 8 + (lane & 3) * 2;
        b1s[nb][0] = b1[c]; b1s[nb][1] = b1[c + 1];
        b2s[nb][0] = b2[c]; b2s[nb][1] = b2[c + 1];
    }
    const float4 gg4 = *(const float4*)&lng[lane * 4];
    const float4 bb4 = *(const float4*)&lnb[lane * 4];

    uint32_t baseAhi[2], baseAlo[2];
#pragma unroll
    for (int mb = 0; mb < 2; ++mb) {
        const int rowA = wm * 32 + mb * 16 + lr + ((lane >> 3) & 1) * 8;
        baseAhi[mb] = sb + KN_AHI + rowA * 256;
        baseAlo[mb] = sb + KN_ALO + rowA * 256;
    }
    const uint32_t baseB = sb + KN_BHI + (wn * 64 + lr) * 256;  // lo = +32768

    float* fbuf = (float*)smc;  // aliases A region (post-GEMM2)

    for (int tile = blockIdx.x; tile < numTiles; tile += gridDim.x) {
        const int n0 = tile * 128;
        float acc[2][8][4];
#pragma unroll
        for (int mb = 0; mb < 2; ++mb)
#pragma unroll
            for (int nb = 0; nb < 8; ++nb)
#pragma unroll
                for (int q = 0; q < 4; ++q) acc[mb][nb][q] = 0.0f;

#pragma unroll 1
        for (int stage = 0; stage < 2; ++stage) {
            __syncthreads();  // prev readers done (tile top / stage switch)
            // load B = W1^T half
            {
                uint4* bh = (uint4*)(smc + KN_BHI);
                uint4* bl = (uint4*)(smc + KN_BLO);
                const uint4* sh = g_n1hi + stage * 2048;
                const uint4* sl = g_n1lo + stage * 2048;
#pragma unroll
                for (int i = 0; i < 8; ++i) {
                    bh[tid + i * 256] = sh[tid + i * 256];
                    bl[tid + i * 256] = sl[tid + i * 256];
                }
            }
            // convert A = (stage ? agg : h) tile
            const float* src = stage ? g_agg : g_h;
#pragma unroll
            for (int i = 0; i < 8; ++i) {
                const int r = ty * 8 + i;
                int n = n0 + r; if (n >= NN) n = NN - 1;
                const float4 v0 = *(const float4*)&src[(size_t)n * DD + tx * 8];
                const float4 v1 = *(const float4*)&src[(size_t)n * DD + tx * 8 + 4];
                const float o[8] = { v0.x, v0.y, v0.z, v0.w, v1.x, v1.y, v1.z, v1.w };
                uint32_t hh[4], ll[4];
#pragma unroll
                for (int p = 0; p < 4; ++p) bf16split(o[2 * p], o[2 * p + 1], hh[p], ll[p]);
                const uint32_t off = (uint32_t)(r * 256 + ((tx ^ (r & 7)) << 4));
                *(uint4*)(smc + KN_AHI + off) = make_uint4(hh[0], hh[1], hh[2], hh[3]);
                *(uint4*)(smc + KN_ALO + off) = make_uint4(ll[0], ll[1], ll[2], ll[3]);
            }
            __syncthreads();
#pragma unroll
            for (int kb = 0; kb < 8; ++kb) {
                const uint32_t swA = (uint32_t)(((kb * 2 + pA) ^ lr) << 4);
                const uint32_t swB = (uint32_t)(((kb * 2 + pB) ^ lr) << 4);
                uint32_t ah[2][4], al[2][4];
                ldsm4(ah[0], baseAhi[0] + swA);
                ldsm4(ah[1], baseAhi[1] + swA);
                ldsm4(al[0], baseAlo[0] + swA);
                ldsm4(al[1], baseAlo[1] + swA);
#pragma unroll
                for (int nb = 0; nb < 8; ++nb) {
                    uint32_t bh[2], bl[2];
                    const uint32_t bo = baseB + nb * 2048 + swB;
                    ldsm2(bh, bo);
                    ldsm2(bl, bo + 32768);
                    mma16816(acc[0][nb], ah[0], bh);
                    mma16816(acc[1][nb], ah[1], bh);
                    mma16816(acc[0][nb], ah[0], bl);
                    mma16816(acc[1][nb], ah[1], bl);
                    mma16816(acc[0][nb], al[0], bh);
                    mma16816(acc[1][nb], al[1], bh);
                }
            }
        }
        __syncthreads();  // GEMM1 reads done before A overwrite

        // epilogue 1: hid = silu(acc + b1) -> A hi/lo (from fragments), zero acc
#pragma unroll
        for (int nb = 0; nb < 8; ++nb) {
            const int cc = wn * 8 + nb;              // (c>>3)
            const int cb = (lane & 3) * 4;           // (c&7)*2 bytes
#pragma unroll
            for (int mb = 0; mb < 2; ++mb) {
                const int r = wm * 32 + mb * 16 + (lane >> 2);
                const int r2 = r + 8;
                uint32_t hh, ll;
                bf16split(silu_f(acc[mb][nb][0] + b1s[nb][0]),
                          silu_f(acc[mb][nb][1] + b1s[nb][1]), hh, ll);
                const uint32_t o1 = (uint32_t)(r * 256 + (((cc) ^ (r & 7)) << 4) + cb);
                *(uint32_t*)(smc + KN_AHI + o1) = hh;
                *(uint32_t*)(smc + KN_ALO + o1) = ll;
                bf16split(silu_f(acc[mb][nb][2] + b1s[nb][0]),
                          silu_f(acc[mb][nb][3] + b1s[nb][1]), hh, ll);
                const uint32_t o2 = (uint32_t)(r2 * 256 + (((cc) ^ (r2 & 7)) << 4) + cb);
                *(uint32_t*)(smc + KN_AHI + o2) = hh;
                *(uint32_t*)(smc + KN_ALO + o2) = ll;
#pragma unroll
                for (int q = 0; q < 4; ++q) acc[mb][nb][q] = 0.0f;
            }
        }
        // load B = W2^T
        {
            uint4* bh = (uint4*)(smc + KN_BHI);
            uint4* bl = (uint4*)(smc + KN_BLO);
#pragma unroll
            for (int i = 0; i < 8; ++i) {
                bh[tid + i * 256] = g_n2hi[tid + i * 256];
                bl[tid + i * 256] = g_n2lo[tid + i * 256];
            }
        }
        __syncthreads();
#pragma unroll
        for (int kb = 0; kb < 8; ++kb) {
            const uint32_t swA = (uint32_t)(((kb * 2 + pA) ^ lr) << 4);
            const uint32_t swB = (uint32_t)(((kb * 2 + pB) ^ lr) << 4);
            uint32_t ah[2][4], al[2][4];
            ldsm4(ah[0], baseAhi[0] + swA);
            ldsm4(ah[1], baseAhi[1] + swA);
            ldsm4(al[0], baseAlo[0] + swA);
            ldsm4(al[1], baseAlo[1] + swA);
#pragma unroll
            for (int nb = 0; nb < 8; ++nb) {
                uint32_t bh[2], bl[2];
                const uint32_t bo = baseB + nb * 2048 + swB;
                ldsm2(bh, bo);
                ldsm2(bl, bo + 32768);
                mma16816(acc[0][nb], ah[0], bh);
                mma16816(acc[1][nb], ah[1], bh);
                mma16816(acc[0][nb], ah[0], bl);
                mma16816(acc[1][nb], ah[1], bl);
                mma16816(acc[0][nb], al[0], bh);
                mma16816(acc[1][nb], al[1], bh);
            }
        }
        __syncthreads();  // GEMM2 reads done before fbuf overwrite

        // epilogue 2: out = acc + b2 + residual(h) -> fbuf (fp32, stride 128)
#pragma unroll
        for (int nb = 0; nb < 8; ++nb) {
            const int c = wn * 64 + nb * 8 + (lane & 3) * 2;
#pragma unroll
            for (int mb = 0; mb < 2; ++mb) {
                const int r = wm * 32 + mb * 16 + (lane >> 2);
                const int r2 = r + 8;
                int na = n0 + r;  if (na >= NN) na = NN - 1;
                int nb2 = n0 + r2; if (nb2 >= NN) nb2 = NN - 1;
                const float2 h0 = *(const float2*)&g_h[(size_t)na * DD + c];
                const float2 h1 = *(const float2*)&g_h[(size_t)nb2 * DD + c];
                *(float2*)&fbuf[r * 128 + c] =
                    make_float2(acc[mb][nb][0] + b2s[nb][0] + h0.x,
                                acc[mb][nb][1] + b2s[nb][1] + h0.y);
                *(float2*)&fbuf[r2 * 128 + c] =
                    make_float2(acc[mb][nb][2] + b2s[nb][0] + h1.x,
                                acc[mb][nb][3] + b2s[nb][1] + h1.y);
            }
        }
        __syncthreads();

        // fused LayerNorm: 8 warps x 16 rows
#pragma unroll 1
        for (int j = 0; j < 16; ++j) {
            const int row = w * 16 + j;
            const int n = n0 + row;
            if (n < NN) {
                const float4 v = *(const float4*)&fbuf[row * 128 + lane * 4];
                float s = v.x + v.y + v.z + v.w;
#pragma unroll
                for (int o = 16; o; o >>= 1) s += __shfl_xor_sync(0xFFFFFFFFu, s, o);
                const float mu = s * (1.0f / 128.0f);
                const float d0 = v.x - mu, d1 = v.y - mu, d2 = v.z - mu, d3 = v.w - mu;
                float q = d0 * d0 + d1 * d1 + d2 * d2 + d3 * d3;
#pragma unroll
                for (int o = 16; o; o >>= 1) q += __shfl_xor_sync(0xFFFFFFFFu, q, o);
                const float inv = rsqrtf(q * (1.0f / 128.0f) + 1e-5f);
                float4 o4;
                o4.x = d0 * inv * gg4.x + bb4.x;
                o4.y = d1 * inv * gg4.y + bb4.y;
                o4.z = d2 * inv * gg4.z + bb4.z;
                o4.w = d3 * inv * gg4.w + bb4.w;
                *(float4*)&g_h[(size_t)n * DD + lane * 4] = o4;
            }
        }
    }
}

// ---------------- output MLP ----------------
__global__ void k_out(const float* __restrict__ w1, const float* __restrict__ b1,
                      const float* __restrict__ w2, const float* __restrict__ b2,
                      float* __restrict__ out) {
    extern __shared__ float sm[];
    float* sW1  = sm;
    float* sW2  = sW1 + DD * DD;
    float* sX   = sW2 + DD * 3;
    float* sHid = sX + DD;
    const int j = threadIdx.x;
    for (int i = j; i < DD * DD; i += DD) sW1[i] = w1[i];
    for (int i = j; i < DD * 3; i += DD) sW2[i] = w2[i];
    const float bb1 = b1[j];
    __syncthreads();
    const int n0 = blockIdx.x * 16;
    for (int m = 0; m < 16; ++m) {
        const int n = n0 + m;
        sX[j] = g_h[(size_t)n * DD + j];
        __syncthreads();
        float acc = bb1;
#pragma unroll 8
        for (int k = 0; k < DD; ++k) acc += sX[k] * sW1[k * DD + j];
        sHid[j] = silu_f(acc);
        __syncthreads();
        if (j < 3) {
            float o = b2[j];
            for (int k = 0; k < DD; ++k) o += sHid[k] * sW2[k * 3 + j];
            out[(size_t)n * 3 + j] = o;
        }
        __syncthreads();
    }
}

// ---------------- launch ----------------
extern "C" void kernel_launch(void* const* d_in, const int* in_sizes, int n_in,
                              void* d_out, int out_size) {
    const float* x_t      = (const float*)d_in[0];
    const int*   ei       = (const int*)d_in[1];
    const int*   tp       = (const int*)d_in[2];
    const float* time_w1  = (const float*)d_in[3];
    const float* time_b1  = (const float*)d_in[4];
    const float* time_w2  = (const float*)d_in[5];
    const float* time_b2  = (const float*)d_in[6];
    const float* nodein_w1= (const float*)d_in[7];
    const float* nodein_b1= (const float*)d_in[8];
    const float* nodein_w2= (const float*)d_in[9];
    const float* nodein_b2= (const float*)d_in[10];
    const float* phim_w1  = (const float*)d_in[11];
    const float* phim_b1  = (const float*)d_in[12];
    const float* phim_w2  = (const float*)d_in[13];
    const float* phim_b2  = (const float*)d_in[14];
    const float* phih_w1  = (const float*)d_in[15];
    const float* phih_b1  = (const float*)d_in[16];
    const float* phih_w2  = (const float*)d_in[17];
    const float* phih_b2  = (const float*)d_in[18];
    const float* ln_g     = (const float*)d_in[19];
    const float* ln_b     = (const float*)d_in[20];
    const float* out_w1   = (const float*)d_in[21];
    const float* out_b1   = (const float*)d_in[22];
    const float* out_w2   = (const float*)d_in[23];
    const float* out_b2   = (const float*)d_in[24];
    float* out = (float*)d_out;

    const int SMEM_NIN  = (DD * DD + 128 * ATSTR + 3 * DD + DD) * 4;
    const int SMEM_OUT  = (DD * DD + DD * 3 + DD + DD) * 4;

    cudaFuncSetAttribute(k_edge,     cudaFuncAttributeMaxDynamicSharedMemorySize, SMEM_EDGE);
    cudaFuncSetAttribute(k_pre,      cudaFuncAttributeMaxDynamicSharedMemorySize, SMEM_KPRE);
    cudaFuncSetAttribute(k_node,     cudaFuncAttributeMaxDynamicSharedMemorySize, SMEM_KNODE);
    cudaFuncSetAttribute(k_scan_nin, cudaFuncAttributeMaxDynamicSharedMemorySize, SMEM_NIN);
    cudaFuncSetAttribute(k_out,      cudaFuncAttributeMaxDynamicSharedMemorySize, SMEM_OUT);

    const int edgeTiles = EE / 64;           // 10000
    const int nodeTiles = (NN + 127) / 128;  // 157
    const int SCAT = EE / 256;               // 2500
    const int PRE_TILES = 157;

    k_time_hist<<<1 + SCAT, 256>>>(ei, tp, time_w1, time_b1, time_w2, time_b2,
                                   nodein_w1, nodein_b1);
    k_scan_nin<<<1 + PRE_TILES, 256, SMEM_NIN>>>(x_t, nodein_w1, nodein_w2, nodein_b2);

    for (int l = 0; l < LL; ++l) {
        const float* W1l = phim_w1 + (size_t)l * 272 * DD;
        const int scat = (l == 0) ? SCAT : 0;
        k_prep<<<scat + 157 + 48, 256>>>(W1l,
                                         phih_w1 + (size_t)l * 256 * DD,
                                         phih_w2 + (size_t)l * DD * DD,
                                         phim_w2 + (size_t)l * DD * DD,
                                         ei, x_t, scat);
        k_pre<<<nodeTiles, 256, SMEM_KPRE>>>(phim_b1 + (size_t)l * DD, nodeTiles);
        k_edge<<<296, 256, SMEM_EDGE>>>(W1l + 256 * DD,
                                        phim_b2 + (size_t)l * DD,
                                        edgeTiles);
        k_node<<<nodeTiles, 256, SMEM_KNODE>>>(phih_b1 + (size_t)l * DD,
                                               phih_b2 + (size_t)l * DD,
                                               ln_g + (size_t)l * DD,
                                               ln_b + (size_t)l * DD,
                                               nodeTiles);
    }

    k_out<<<NN / 16, 128, SMEM_OUT>>>(out_w1, out_b1, out_w2, out_b2, out);
}